// round 13
// baseline (speedup 1.0000x reference)
#include <cuda_runtime.h>
#include <math.h>
#include <stdint.h>

#define BB     32
#define NENT   1024
#define LQL    128
#define DFEAT  2112
#define CTX    512
#define CMD    512
#define TT     4
#define MROWS  (BB*NENT)
#define NEGV   (-1e30f)

// ---- mma.sync GEMM tiling ----
#define BMm 128
#define BNm 128
#define BKm 32
#define STAGES 3
#define SROW 36
#define STAGE_F (2 * BMm * SROW)
#define TILE_F  (BMm * SROW)
#define SMEM_DYN (STAGES * STAGE_F * 4)
#define TSST 132

// ---- scratch ----
__device__ float g_imgr   [(size_t)MROWS*DFEAT];
__device__ float g_invnorm[MROWS];
__device__ float g_xloc   [(size_t)MROWS*CTX];
__device__ float g_xctx0  [(size_t)MROWS*CTX];
__device__ float g_xctx1  [(size_t)MROWS*CTX];
__device__ float g_projloc[(size_t)MROWS*CTX];
__device__ float g_pp     [(size_t)MROWS*CTX];
__device__ float g_q      [(size_t)MROWS*CTX];
__device__ float g_k      [(size_t)MROWS*CTX];
__device__ float g_vT     [(size_t)MROWS*CTX];   // [B][CTX][NENT]
__device__ float g_msg    [(size_t)MROWS*CTX];
__device__ float g_qL     [(size_t)MROWS*CTX];
__device__ float g_kL     [(size_t)MROWS*CTX];
__device__ float g_vL     [(size_t)MROWS*CTX];
__device__ float g_score  [(size_t)BB*NENT*NENT];
__device__ float g_qbase  [BB*CMD];
__device__ float g_qcmd   [BB*CMD];
__device__ float g_cmd    [BB*CMD];
__device__ float g_pkg    [BB*CTX];
__device__ float g_pvg    [BB*CTX];
__device__ float g_msgm   [BB*CTX];
__device__ float g_xcm    [BB*CTX];
__device__ float g_SvL    [BB*CTX];
__device__ float g_Spl    [BB*CTX];
__device__ float g_vmask  [BB*CTX];
__device__ float g_wT_ikb[(size_t)CTX*DFEAT];
__device__ float g_wT_pxl[(size_t)CTX*CTX];
__device__ float g_wT_pxc[(size_t)CTX*CTX];
__device__ float g_wT_qry[(size_t)CTX*3*CTX];
__device__ float g_wT_key[(size_t)CTX*3*CTX];
__device__ float g_wT_val[(size_t)CTX*3*CTX];
__device__ float g_wT_mu [(size_t)CTX*2*CTX];
__device__ float g_wT_ck [(size_t)CTX*2*CTX];
__device__ float g_wT_qin [(size_t)CMD*CMD];
__device__ float g_wT_qin2[(size_t)TT*CMD*CMD];
__device__ float g_wT_pk  [(size_t)CMD*CTX];
__device__ float g_wT_pv  [(size_t)CMD*CTX];

__device__ __forceinline__ float rna_tf32(float f) {
    uint32_t r; asm("cvt.rna.tf32.f32 %0, %1;" : "=r"(r) : "f"(f));
    return __uint_as_float(r);
}
__device__ __forceinline__ uint32_t smem_u32(const void* p) {
    uint32_t a;
    asm("{ .reg .u64 t; cvta.to.shared.u64 t, %1; cvt.u32.u64 %0, t; }" : "=r"(a) : "l"(p));
    return a;
}
__device__ __forceinline__ void cp_async16(uint32_t saddr, const void* gptr) {
    asm volatile("cp.async.cg.shared.global [%0], [%1], 16;" :: "r"(saddr), "l"(gptr));
}
#define CP_COMMIT() asm volatile("cp.async.commit_group;" ::: "memory")
#define CP_WAIT1()  asm volatile("cp.async.wait_group 1;" ::: "memory")

__device__ __forceinline__ void ldsm_x4(uint32_t addr, uint32_t& r0, uint32_t& r1,
                                        uint32_t& r2, uint32_t& r3)
{
    asm volatile("ldmatrix.sync.aligned.m8n8.x4.shared.b16 {%0,%1,%2,%3}, [%4];"
                 : "=r"(r0), "=r"(r1), "=r"(r2), "=r"(r3) : "r"(addr));
}

__device__ __forceinline__ void mma_m16n8k8(float* d,
    uint32_t a0, uint32_t a1, uint32_t a2, uint32_t a3,
    uint32_t b0, uint32_t b1)
{
    asm volatile(
        "mma.sync.aligned.m16n8k8.row.col.f32.tf32.tf32.f32 "
        "{%0,%1,%2,%3}, {%4,%5,%6,%7}, {%8,%9}, {%0,%1,%2,%3};"
        : "+f"(d[0]), "+f"(d[1]), "+f"(d[2]), "+f"(d[3])
        : "r"(a0), "r"(a1), "r"(a2), "r"(a3), "r"(b0), "r"(b1));
}

// ---------------- tensor-core GEMM via mma.sync (tf32) ----------------
// MASK 0: none
//      1 (score, z=batch): skip tile if m0>=en || n0>=en
//      2 (message, z=batch): skip tile if m0>=en; truncate K at ceil(en/BKm)
//      3 (row-masked, z=1, batch=m0>>10): skip tile if (m0&1023)>=en
// TRANSC: write C transposed per batch: C is [B][CTX][NENT]; batch = m0>>10.
template<int NSRC, int EPI, bool RND, bool ADD, int MASK, bool TRANSC>
__global__ __launch_bounds__(256, 2)
void gemm_mma(const float* __restrict__ A0, const float* __restrict__ A1,
              const float* __restrict__ A2, const float* __restrict__ Bt,
              const float* __restrict__ bias, const float* __restrict__ extra,
              const float* __restrict__ addC, const int* __restrict__ ennum,
              float* __restrict__ C,
              int K, int lda, int ldb, int ldc,
              size_t sA, size_t sB, size_t sC, float alpha)
{
    extern __shared__ float smem[];
    const uint32_t sbase = smem_u32(smem);

    const int tid = threadIdx.x;
    const int z = blockIdx.z;
    const int m0 = blockIdx.y * BMm;
    const int n0 = blockIdx.x * BNm;

    int Keff = K;
    if (MASK == 1 || MASK == 2) {
        const int en = ennum[z];
        if (m0 >= en) return;
        if (MASK == 1 && n0 >= en) return;
        if (MASK == 2) { const int kc = ((en + BKm - 1) / BKm) * BKm; Keff = kc < K ? kc : K; }
    } else if (MASK == 3) {
        const int en = ennum[m0 >> 10];
        if ((m0 & 1023) >= en) return;
    }

    const float* Abase = A0 + (size_t)z * sA;
    const float* Bbase = Bt + (size_t)z * sB;
    float* Cbase = C + (size_t)z * sC;

    const int wid = tid >> 5, lane = tid & 31;
    const int wm = (wid & 3) * 32;
    const int wn = (wid >> 2) * 64;
    const int gr = lane >> 2;
    const int gc = lane & 3;

    const int lr = lane & 7, lg = lane >> 3;
    const int arow  = wm + lr + (lg & 1) * 8;
    const int akoff = (lg >> 1) * 4;
    const int brow  = wn + lr + (lg >> 1) * 8;
    const int bkoff = (lg & 1) * 4;

    const int prow0 = tid >> 3;
    const int pkq   = (tid & 7) * 4;

    float acc[2][8][4] = {};
    const int NCC = Keff / BKm;

    auto loadChunk = [&](int c, int st) {
        const int k0 = c * BKm;
        const float* Ap; int al, ak;
        if (NSRC == 1) { Ap = Abase; al = lda; ak = k0; }
        else {
            const int src = k0 >> 9;
            Ap = (src == 0) ? A0 : ((src == 1) ? A1 : A2);
            al = CTX; ak = k0 & (CTX - 1);
        }
        const uint32_t sa = sbase + (uint32_t)(st * STAGE_F) * 4;
        const uint32_t sb = sa + (uint32_t)TILE_F * 4;
        #pragma unroll
        for (int t = 0; t < 4; ++t) {
            const int row = prow0 + t * 32;
            cp_async16(sa + (uint32_t)(row * SROW + pkq) * 4,
                       Ap + (size_t)(m0 + row) * al + ak + pkq);
            cp_async16(sb + (uint32_t)(row * SROW + pkq) * 4,
                       Bbase + (size_t)(n0 + row) * ldb + k0 + pkq);
        }
        CP_COMMIT();
    };

    auto compute = [&](int st) {
        const uint32_t SAu = sbase + (uint32_t)(st * STAGE_F) * 4;
        const uint32_t SBu = SAu + (uint32_t)TILE_F * 4;
        #pragma unroll
        for (int kk = 0; kk < BKm; kk += 8) {
            uint32_t b[8][2];
            #pragma unroll
            for (int ntp = 0; ntp < 4; ++ntp) {
                const uint32_t addr = SBu +
                    (uint32_t)(((brow + ntp * 16) * SROW) + kk + bkoff) * 4;
                ldsm_x4(addr, b[2*ntp][0], b[2*ntp][1], b[2*ntp+1][0], b[2*ntp+1][1]);
            }
            #pragma unroll
            for (int mt = 0; mt < 2; ++mt) {
                uint32_t a0, a1, a2, a3;
                const uint32_t addr = SAu +
                    (uint32_t)(((arow + mt * 16) * SROW) + kk + akoff) * 4;
                ldsm_x4(addr, a0, a1, a2, a3);
                #pragma unroll
                for (int nt = 0; nt < 8; ++nt)
                    mma_m16n8k8(acc[mt][nt], a0, a1, a2, a3, b[nt][0], b[nt][1]);
            }
        }
    };

    #pragma unroll
    for (int s = 0; s < STAGES - 1; ++s) {
        if (s < NCC) loadChunk(s, s);
        else CP_COMMIT();
    }
    {
        int st = 0;
        for (int c = 0; c < NCC; ++c) {
            CP_WAIT1();
            __syncthreads();
            const int nc = c + STAGES - 1;
            int nst = st + STAGES - 1; if (nst >= STAGES) nst -= STAGES;
            if (nc < NCC) loadChunk(nc, nst);
            else CP_COMMIT();
            compute(st);
            if (++st == STAGES) st = 0;
        }
    }

    if (TRANSC) __syncthreads();

    #pragma unroll
    for (int mt = 0; mt < 2; ++mt) {
        #pragma unroll
        for (int half = 0; half < 2; ++half) {
            const int m = m0 + wm + mt * 16 + gr + half * 8;
            const float rs = (EPI == 1) ? extra[m] : 0.f;
            #pragma unroll
            for (int nt = 0; nt < 8; ++nt) {
                const int n = n0 + wn + nt * 8 + gc * 2;
                float v0 = acc[mt][nt][half * 2 + 0];
                float v1 = acc[mt][nt][half * 2 + 1];
                if (ADD) {
                    const float2 ad = *reinterpret_cast<const float2*>(addC + (size_t)m * ldc + n);
                    v0 += ad.x; v1 += ad.y;
                }
                const float bb0 = bias ? bias[n]     : 0.f;
                const float bb1 = bias ? bias[n + 1] : 0.f;
                if (EPI == 0)      { v0 = v0 * alpha + bb0;  v1 = v1 * alpha + bb1; }
                else if (EPI == 1) { v0 = v0 * rs + bb0;     v1 = v1 * rs + bb1; }
                else if (EPI == 2) {
                    const float* g = extra + (size_t)(m >> 10) * CTX + n;
                    v0 = (v0 + bb0) * g[0];
                    v1 = (v1 + bb1) * g[1];
                } else {
                    const float* g = extra + (size_t)m * ldc + n;
                    v0 = (v0 + bb0) * g[0];
                    v1 = (v1 + bb1) * g[1];
                }
                if (RND) { v0 = rna_tf32(v0); v1 = rna_tf32(v1); }
                if (!TRANSC) {
                    *reinterpret_cast<float2*>(Cbase + (size_t)m * ldc + n) = make_float2(v0, v1);
                } else {
                    const int ml = wm + mt * 16 + gr + half * 8;
                    const int nl = wn + nt * 8 + gc * 2;
                    smem[(size_t)nl * TSST + ml] = v0;
                    smem[(size_t)(nl + 1) * TSST + ml] = v1;
                }
            }
        }
    }

    if (TRANSC) {
        __syncthreads();
        float* outT = C + (size_t)(m0 >> 10) * CTX * NENT;
        const int bofs = m0 & 1023;
        #pragma unroll
        for (int r = 0; r < 16; ++r) {
            const int row = wid * 16 + r;
            const float4 val = *reinterpret_cast<const float4*>(&smem[(size_t)row * TSST + lane * 4]);
            *reinterpret_cast<float4*>(outT + (size_t)(n0 + row) * NENT + bofs + lane * 4) = val;
        }
    }
}

// ---- one-time: column mean of src rows [NT, NENT) per batch ----
__global__ __launch_bounds__(512)
void colmean_masked_kernel(const float* __restrict__ src, const int* __restrict__ ennum,
                           float* __restrict__ out)
{
    const int b = blockIdx.x;
    const int en = ennum[b];
    const int NT = ((en + 127) >> 7) << 7;
    if (NT >= NENT) return;
    const int d = threadIdx.x;
    const float* base = src + (size_t)b * NENT * CTX + d;
    float s = 0.f;
    for (int m = NT; m < NENT; ++m) s += base[(size_t)m * CTX];
    out[b * CTX + d] = s * (1.f / (float)(NENT - NT));
}

// ---- per-iter analytic masked-row v mean ----
// vmask = (SvL + xcm@Wv_xc + ((xcm@pxc + b) .* Spl)@Wv_pp + val_b) .* pvg
__global__ __launch_bounds__(256)
void vmask_kernel(const float* __restrict__ xcm, const float* __restrict__ wPXC,
                  const float* __restrict__ pxc_b, const float* __restrict__ Spl,
                  const float* __restrict__ wVAL, const float* __restrict__ val_b,
                  const float* __restrict__ pvg, const float* __restrict__ SvL,
                  const int* __restrict__ ennum, float* __restrict__ vmask)
{
    const int b = blockIdx.x;
    const int en = ennum[b];
    if (((en + 127) >> 7 << 7) >= NENT) return;
    const int tid = threadIdx.x, wid = tid >> 5, lane = tid & 31;
    __shared__ float xcs[CTX];
    __shared__ float x2[CTX];
    for (int d = tid; d < CTX; d += 256) xcs[d] = xcm[b * CTX + d];
    __syncthreads();
    for (int j = wid; j < CTX; j += 8) {
        const float* w = wPXC + (size_t)j * CTX;
        float acc = 0.f;
        #pragma unroll
        for (int i = 0; i < CTX / 32; ++i)
            acc = fmaf(xcs[lane + 32 * i], w[lane + 32 * i], acc);
        #pragma unroll
        for (int o = 16; o > 0; o >>= 1) acc += __shfl_down_sync(0xFFFFFFFFu, acc, o);
        if (lane == 0) x2[j] = (acc + pxc_b[j]) * Spl[b * CTX + j];
    }
    __syncthreads();
    for (int d = wid; d < CTX; d += 8) {
        const float* w = wVAL + (size_t)d * (3 * CTX) + CTX;   // k = 512..1535
        float acc = 0.f;
        #pragma unroll
        for (int i = 0; i < CTX / 32; ++i) {
            acc = fmaf(xcs[lane + 32 * i], w[lane + 32 * i], acc);
            acc = fmaf(x2[lane + 32 * i],  w[CTX + lane + 32 * i], acc);
        }
        #pragma unroll
        for (int o = 16; o > 0; o >>= 1) acc += __shfl_down_sync(0xFFFFFFFFu, acc, o);
        if (lane == 0)
            vmask[b * CTX + d] = (acc + val_b[d] + SvL[b * CTX + d]) * pvg[b * CTX + d];
    }
}

// ---- per-batch mean over vT rows (live cols < NT) + analytic masked part ----
__global__ void mean_vT_kernel(const float* __restrict__ vT, const int* __restrict__ ennum,
                               const float* __restrict__ vmask, float* __restrict__ msgm)
{
    const int b = blockIdx.y;
    const int en = ennum[b];
    if (en >= NENT) return;
    const int NT = ((en + 127) >> 7) << 7;
    const int wid = threadIdx.x >> 5, lane = threadIdx.x & 31;
    const int d = blockIdx.x * 8 + wid;
    const float* row = vT + (size_t)b * CTX * NENT + (size_t)d * NENT;
    float s = 0.f;
    for (int i = 0; i < NT / 32; ++i) s += row[lane + 32 * i];
    #pragma unroll
    for (int o = 16; o > 0; o >>= 1) s += __shfl_down_sync(0xFFFFFFFFu, s, o);
    if (lane == 0)
        msgm[b * CTX + d] = rna_tf32((s + (float)(NENT - NT) * vmask[b * CTX + d]) * (1.f / NENT));
}

// ---- masked-row x_ctx compute: y = rna([xcm|msgm]@mu + b); xcm <- y ----
__global__ __launch_bounds__(256)
void ctx_compute_kernel(const float* __restrict__ msgm, const float* __restrict__ wMU,
                        const float* __restrict__ mu_b, const int* __restrict__ ennum,
                        float* __restrict__ xcm)
{
    const int b = blockIdx.x;
    if (ennum[b] >= NENT) return;
    const int tid = threadIdx.x;
    const int wid = tid >> 5, lane = tid & 31;
    __shared__ float x[2 * CTX];
    __shared__ float y[CTX];
    for (int d = tid; d < CTX; d += 256) {
        x[d] = xcm[b * CTX + d];
        x[CTX + d] = msgm[b * CTX + d];
    }
    __syncthreads();
    for (int j = wid; j < CTX; j += 8) {
        const float* w = wMU + (size_t)j * (2 * CTX);
        float acc = 0.f;
        #pragma unroll
        for (int i = 0; i < (2 * CTX) / 32; ++i)
            acc = fmaf(x[lane + 32 * i], w[lane + 32 * i], acc);
        #pragma unroll
        for (int o = 16; o > 0; o >>= 1)
            acc += __shfl_down_sync(0xFFFFFFFFu, acc, o);
        if (lane == 0) y[j] = rna_tf32(acc + mu_b[j]);
    }
    __syncthreads();
    for (int d = tid; d < CTX; d += 256) xcm[b * CTX + d] = y[d];
}

// ---- broadcast xcm row into xn masked rows ----
__global__ __launch_bounds__(256)
void bcast_rows_kernel(const float* __restrict__ xcm, const int* __restrict__ ennum,
                       float* __restrict__ xn)
{
    const int b = blockIdx.y;
    const int en = ennum[b];
    const int r0 = blockIdx.x * 128;
    int start = r0 > en ? r0 : en;
    const int end = r0 + 128;
    if (start >= end) return;
    __shared__ float y[CTX];
    const int tid = threadIdx.x;
    for (int d = tid; d < CTX; d += 256) y[d] = xcm[b * CTX + d];
    __syncthreads();
    const int c4 = (tid & 127) * 4;
    const float4 val = *reinterpret_cast<const float4*>(&y[c4]);
    float* base = xn + (size_t)b * NENT * CTX;
    for (int m = start + (tid >> 7); m < end; m += 2)
        *reinterpret_cast<float4*>(base + (size_t)m * CTX + c4) = val;
}

// ---- transpose, optional tf32 round ----
template<bool RND>
__global__ void transpose_kernel(const float* __restrict__ in, float* __restrict__ out,
                                 int R, int C, size_t sIn, size_t sOut)
{
    __shared__ float tile[32][33];
    const int z = blockIdx.z;
    in  += (size_t)z * sIn;
    out += (size_t)z * sOut;
    const int r0 = blockIdx.y * 32, c0 = blockIdx.x * 32;
    #pragma unroll
    for (int i = threadIdx.y; i < 32; i += 8) {
        float x = in[(size_t)(r0 + i) * C + c0 + threadIdx.x];
        tile[i][threadIdx.x] = RND ? rna_tf32(x) : x;
    }
    __syncthreads();
    #pragma unroll
    for (int i = threadIdx.y; i < 32; i += 8)
        out[(size_t)(c0 + i) * R + r0 + threadIdx.x] = tile[threadIdx.x][i];
}

// ---- fused row inv-norm + tf32-rounded copy ----
__global__ void rownorm_round_kernel(const float* __restrict__ img, float* __restrict__ invn,
                                     float* __restrict__ imgr)
{
    const int m = blockIdx.x;
    const float4* r4 = reinterpret_cast<const float4*>(img + (size_t)m * DFEAT);
    float4* o4 = reinterpret_cast<float4*>(imgr + (size_t)m * DFEAT);
    const int tid = threadIdx.x;
    float s = 0.f;
    for (int i = tid; i < DFEAT / 4; i += 256) {
        float4 u = r4[i];
        s = fmaf(u.x, u.x, s); s = fmaf(u.y, u.y, s);
        s = fmaf(u.z, u.z, s); s = fmaf(u.w, u.w, s);
        u.x = rna_tf32(u.x); u.y = rna_tf32(u.y);
        u.z = rna_tf32(u.z); u.w = rna_tf32(u.w);
        o4[i] = u;
    }
    __shared__ float red[256];
    red[tid] = s; __syncthreads();
    for (int o = 128; o > 0; o >>= 1) { if (tid < o) red[tid] += red[tid + o]; __syncthreads(); }
    if (tid == 0) invn[m] = 1.f / fmaxf(sqrtf(red[0]), 1e-12f);
}

__global__ void ctx_init_kernel(const float* __restrict__ initMem, float* __restrict__ xctx,
                                float* __restrict__ xcm)
{
    const size_t i = (size_t)blockIdx.x * blockDim.x + threadIdx.x;
    const float val = rna_tf32(initMem[i & (CTX - 1)]);
    xctx[i] = val;
    if (i < BB * CTX) xcm[i] = val;
}

// ---- fast batch-32 linear ----
template<bool ELU>
__global__ void small_linear_fast(const float* __restrict__ in, const float* __restrict__ wT,
                                  const float* __restrict__ bias, float* __restrict__ out)
{
    const int b = blockIdx.y;
    const int jb = blockIdx.x * 32;
    const int tid = threadIdx.x;
    const int wid = tid >> 5, lane = tid & 31;
    __shared__ float x[CMD];
    for (int d = tid; d < CMD; d += 256) x[d] = in[b * CMD + d];
    __syncthreads();
    #pragma unroll
    for (int jj = 0; jj < 4; ++jj) {
        const int j = jb + wid * 4 + jj;
        const float* w = wT + (size_t)j * CMD;
        float acc = 0.f;
        #pragma unroll
        for (int i = 0; i < CMD / 32; ++i)
            acc = fmaf(x[lane + 32 * i], w[lane + 32 * i], acc);
        #pragma unroll
        for (int o = 16; o > 0; o >>= 1)
            acc += __shfl_down_sync(0xFFFFFFFFu, acc, o);
        if (lane == 0) {
            acc += bias[j];
            if (ELU) acc = (acc > 0.f) ? acc : expm1f(acc);
            out[b * CMD + j] = acc;
        }
    }
}

// ---- fast textual command ----
__global__ __launch_bounds__(1024)
void text_cmd_fast(const float* __restrict__ qcmd, const float* __restrict__ lstm,
                   const float* __restrict__ c2l_w, const float* __restrict__ c2l_b,
                   const int* __restrict__ qlen, float* __restrict__ cmd)
{
    const int b = blockIdx.x;
    const int tid = threadIdx.x;
    const int wid = tid >> 5, lane = tid & 31;
    __shared__ float e[CMD];
    __shared__ float att[LQL];
    __shared__ float red[128];
    __shared__ float smx, ssum;

    if (tid < CMD) e[tid] = qcmd[b * CMD + tid] * c2l_w[tid];
    __syncthreads();

    const int en = qlen[b];
    #pragma unroll
    for (int li = 0; li < 4; ++li) {
        const int l = wid + li * 32;
        const float* L = lstm + ((size_t)b * LQL + l) * CMD;
        float acc = 0.f;
        #pragma unroll
        for (int i = 0; i < CMD / 32; ++i)
            acc = fmaf(L[lane + 32 * i], e[lane + 32 * i], acc);
        #pragma unroll
        for (int o = 16; o > 0; o >>= 1)
            acc += __shfl_down_sync(0xFFFFFFFFu, acc, o);
        if (lane == 0) att[l] = (l >= en) ? NEGV : (acc + c2l_b[0]);
    }
    __syncthreads();

    if (tid < 128) red[tid] = att[tid];
    __syncthreads();
    for (int o = 64; o > 0; o >>= 1) {
        if (tid < o) red[tid] = fmaxf(red[tid], red[tid + o]);
        __syncthreads();
    }
    if (tid == 0) smx = red[0];
    __syncthreads();
    float ev = 0.f;
    if (tid < 128) { ev = expf(att[tid] - smx); red[tid] = ev; }
    __syncthreads();
    for (int o = 64; o > 0; o >>= 1) {
        if (tid < o) red[tid] += red[tid + o];
        __syncthreads();
    }
    if (tid == 0) ssum = red[0];
    __syncthreads();
    if (tid < 128) att[tid] = ev / ssum;
    __syncthreads();

    if (tid < CMD) {
        float acc = 0.f;
        const float* L = lstm + (size_t)b * LQL * CMD + tid;
        #pragma unroll 4
        for (int l = 0; l < LQL; ++l)
            acc = fmaf(att[l], L[(size_t)l * CMD], acc);
        cmd[b * CMD + tid] = acc;
    }
}

// masked row softmax (in place)
__global__ void attn_softmax_kernel(float* __restrict__ score, const int* __restrict__ entity_num)
{
    const int row = blockIdx.x;
    const int b = row >> 10;
    const int n = row & 1023;
    const int en = entity_num[b];
    if (n >= en) return;
    float* s = score + (size_t)row * NENT;
    const int tid = threadIdx.x;

    const int kc = ((en + 15) / 16) * 16;
    const int nblk = (kc + 255) >> 8;

    float v[4];
    float mx = -3.4e38f;
    #pragma unroll
    for (int j = 0; j < 4; j++) {
        const int m = tid + j * 256;
        float x = NEGV;
        if (j < nblk && m < en) x = s[m];
        v[j] = x;
        mx = fmaxf(mx, x);
    }
    __shared__ float red[256];
    red[tid] = mx; __syncthreads();
    for (int o = 128; o > 0; o >>= 1) { if (tid < o) red[tid] = fmaxf(red[tid], red[tid + o]); __syncthreads(); }
    mx = red[0];
    __syncthreads();

    float sum = 0.f;
    #pragma unroll
    for (int j = 0; j < 4; j++) { v[j] = expf(v[j] - mx); sum += v[j]; }
    red[tid] = sum; __syncthreads();
    for (int o = 128; o > 0; o >>= 1) { if (tid < o) red[tid] += red[tid + o]; __syncthreads(); }
    const float inv = 1.f / red[0];

    #pragma unroll
    for (int j = 0; j < 4; j++)
        if (j < nblk) s[tid + j * 256] = rna_tf32(v[j] * inv);
}

// ---------------- launch ----------------
template<typename T> static float* symaddr(T& sym) {
    void* p = nullptr;
    cudaGetSymbolAddress(&p, sym);
    return (float*)p;
}

extern "C" void kernel_launch(void* const* d_in, const int* in_sizes, int n_in,
                              void* d_out, int out_size)
{
    const float* images    = (const float*)d_in[0];
    const float* q_enc     = (const float*)d_in[1];
    const float* lstm      = (const float*)d_in[2];
    const int*   q_length  = (const int*)  d_in[3];
    const int*   ent_num   = (const int*)  d_in[4];
    const float* initKB_w  = (const float*)d_in[5];
    const float* initKB_b  = (const float*)d_in[6];
    const float* initMem   = (const float*)d_in[7];
    const float* qInput_w  = (const float*)d_in[8];
    const float* qInput_b  = (const float*)d_in[9];
    const float* qInput2_w = (const float*)d_in[10];
    const float* qInput2_b = (const float*)d_in[11];
    const float* c2l_w     = (const float*)d_in[12];
    const float* c2l_b     = (const float*)d_in[13];
    const float* pxl_w     = (const float*)d_in[14];
    const float* pxl_b     = (const float*)d_in[15];
    const float* pxc_w     = (const float*)d_in[16];
    const float* pxc_b     = (const float*)d_in[17];
    const float* qry_w     = (const float*)d_in[18];
    const float* qry_b     = (const float*)d_in[19];
    const float* key_w     = (const float*)d_in[20];
    const float* key_b     = (const float*)d_in[21];
    const float* val_w     = (const float*)d_in[22];
    const float* val_b     = (const float*)d_in[23];
    const float* pk_w      = (const float*)d_in[24];
    const float* pk_b      = (const float*)d_in[25];
    const float* pv_w      = (const float*)d_in[26];
    const float* pv_b      = (const float*)d_in[27];
    const float* mu_w      = (const float*)d_in[28];
    const float* mu_b      = (const float*)d_in[29];
    const float* ck_w      = (const float*)d_in[30];
    const float* ck_b      = (const float*)d_in[31];

    float* imgr  = symaddr(g_imgr);
    float* invn  = symaddr(g_invnorm);
    float* xloc  = symaddr(g_xloc);
    float* xctxA = symaddr(g_xctx0);
    float* xctxB = symaddr(g_xctx1);
    float* prjl  = symaddr(g_projloc);
    float* pp    = symaddr(g_pp);
    float* q     = symaddr(g_q);
    float* k     = symaddr(g_k);
    float* vT    = symaddr(g_vT);
    float* msg   = symaddr(g_msg);
    float* qL    = symaddr(g_qL);
    float* kL    = symaddr(g_kL);
    float* vL    = symaddr(g_vL);
    float* score = symaddr(g_score);
    float* qbase = symaddr(g_qbase);
    float* qcmd  = symaddr(g_qcmd);
    float* cmd   = symaddr(g_cmd);
    float* pkg   = symaddr(g_pkg);
    float* pvg   = symaddr(g_pvg);
    float* msgm  = symaddr(g_msgm);
    float* xcm   = symaddr(g_xcm);
    float* SvL   = symaddr(g_SvL);
    float* Spl   = symaddr(g_Spl);
    float* vmask = symaddr(g_vmask);
    float* wIKB  = symaddr(g_wT_ikb);
    float* wPXL  = symaddr(g_wT_pxl);
    float* wPXC  = symaddr(g_wT_pxc);
    float* wQRY  = symaddr(g_wT_qry);
    float* wKEY  = symaddr(g_wT_key);
    float* wVAL  = symaddr(g_wT_val);
    float* wMU   = symaddr(g_wT_mu);
    float* wCK   = symaddr(g_wT_ck);
    float* wQIN  = symaddr(g_wT_qin);
    float* wQIN2 = symaddr(g_wT_qin2);
    float* wPK   = symaddr(g_wT_pk);
    float* wPV   = symaddr(g_wT_pv);

    cudaFuncSetAttribute(gemm_mma<1,0,false,false,0,false>, cudaFuncAttributeMaxDynamicSharedMemorySize, SMEM_DYN);
    cudaFuncSetAttribute(gemm_mma<1,0,false,false,3,false>, cudaFuncAttributeMaxDynamicSharedMemorySize, SMEM_DYN);
    cudaFuncSetAttribute(gemm_mma<1,1,true ,false,0,false>, cudaFuncAttributeMaxDynamicSharedMemorySize, SMEM_DYN);
    cudaFuncSetAttribute(gemm_mma<1,3,true ,false,3,false>, cudaFuncAttributeMaxDynamicSharedMemorySize, SMEM_DYN);
    cudaFuncSetAttribute(gemm_mma<1,0,false,false,1,false>, cudaFuncAttributeMaxDynamicSharedMemorySize, SMEM_DYN);
    cudaFuncSetAttribute(gemm_mma<1,0,true ,false,2,false>, cudaFuncAttributeMaxDynamicSharedMemorySize, SMEM_DYN);
    cudaFuncSetAttribute(gemm_mma<2,0,true ,true ,3,false>, cudaFuncAttributeMaxDynamicSharedMemorySize, SMEM_DYN);
    cudaFuncSetAttribute(gemm_mma<2,2,true ,true ,3,false>, cudaFuncAttributeMaxDynamicSharedMemorySize, SMEM_DYN);
    cudaFuncSetAttribute(gemm_mma<2,2,true ,true ,3,true >, cudaFuncAttributeMaxDynamicSharedMemorySize, SMEM_DYN);
    cudaFuncSetAttribute(gemm_mma<2,0,true ,false,3,false>, cudaFuncAttributeMaxDynamicSharedMemorySize, SMEM_DYN);
    cudaFuncSetAttribute(gemm_mma<2,0,false,false,0,false>, cudaFuncAttributeMaxDynamicSharedMemorySize, SMEM_DYN);

    const float scale = 0.044194173824159216f;   // 1/sqrt(512)
    const dim3 tdim(32, 8);
    const dim3 gridMain(CTX / BNm, MROWS / BMm, 1);
    const dim3 gridScore(NENT / BNm, NENT / BMm, BB);
    const dim3 gridMsg(CTX / BNm, NENT / BMm, BB);
    const dim3 gridSL(CMD / 32, BB);

    // --- order: initKB GEMM at launch index 3 (ncu -s 5) ---
    transpose_kernel<true ><<<dim3(CTX/32, DFEAT/32, 1), tdim>>>(initKB_w, wIKB, DFEAT, CTX, 0, 0); // 0
    rownorm_round_kernel<<<MROWS, 256>>>(images, invn, imgr);                                        // 1
    ctx_init_kernel<<<(MROWS * CTX) / 256, 256>>>(initMem, xctxA, xcm);                              // 2
    // 3: x_loc = normalize(images) @ initKB_w + b   <-- ncu target
    gemm_mma<1,1,true,false,0,false><<<gridMain, 256, SMEM_DYN>>>(
        imgr, nullptr, nullptr, wIKB, initKB_b, invn, nullptr, nullptr, xloc,
        DFEAT, DFEAT, DFEAT, CTX, 0, 0, 0, 1.f);

    // remaining weight transposes
    transpose_kernel<false><<<dim3(CMD/32, CMD/32, 1), tdim>>>(qInput_w, wQIN, CMD, CMD, 0, 0);
    small_linear_fast<true><<<gridSL, 256>>>(q_enc, wQIN, qInput_b, qbase);
    transpose_kernel<true><<<dim3(CTX/32, CTX/32, 1),   tdim>>>(pxl_w, wPXL, CTX,   CTX, 0, 0);
    transpose_kernel<true><<<dim3(CTX/32, CTX/32, 1),   tdim>>>(pxc_w, wPXC, CTX,   CTX, 0, 0);
    transpose_kernel<true><<<dim3(CTX/32, 3*CTX/32, 1), tdim>>>(qry_w, wQRY, 3*CTX, CTX, 0, 0);
    transpose_kernel<true><<<dim3(CTX/32, 3*CTX/32, 1), tdim>>>(key_w, wKEY, 3*CTX, CTX, 0, 0);
    transpose_kernel<true><<<dim3(CTX/32, 3*CTX/32, 1), tdim>>>(val_w, wVAL, 3*CTX, CTX, 0, 0);
    transpose_kernel<true><<<dim3(CTX/32, 2*CTX/32, 1), tdim>>>(mu_w,  wMU,  2*CTX, CTX, 0, 0);
    transpose_kernel<true><<<dim3(CTX/32, 2*CTX/32, 1), tdim>>>(ck_w,  wCK,  2*CTX, CTX, 0, 0);
    transpose_kernel<false><<<dim3(CMD/32, CMD/32, TT), tdim>>>(qInput2_w, wQIN2, CMD, CMD,
                                                                (size_t)CMD*CMD, (size_t)CMD*CMD);
    transpose_kernel<false><<<dim3(CTX/32, CMD/32, 1), tdim>>>(pk_w, wPK, CMD, CTX, 0, 0);
    transpose_kernel<false><<<dim3(CTX/32, CMD/32, 1), tdim>>>(pv_w, wPV, CMD, CTX, 0, 0);

    // ---- iteration-invariant hoists ----
    gemm_mma<1,0,false,false,0,false><<<gridMain, 256, SMEM_DYN>>>(
        xloc, nullptr, nullptr, wPXL, pxl_b, nullptr, nullptr, nullptr, prjl,
        CTX, CTX, CTX, CTX, 0, 0, 0, 1.f);
    gemm_mma<1,0,false,false,3,false><<<gridMain, 256, SMEM_DYN>>>(
        xloc, nullptr, nullptr, wQRY, nullptr, nullptr, nullptr, ent_num, qL,
        CTX, CTX, 3*CTX, CTX, 0, 0, 0, 1.f);
    gemm_mma<1,0,false,false,3,false><<<gridMain, 256, SMEM_DYN>>>(
        xloc, nullptr, nullptr, wKEY, nullptr, nullptr, nullptr, ent_num, kL,
        CTX, CTX, 3*CTX, CTX, 0, 0, 0, 1.f);
    gemm_mma<1,0,false,false,0,false><<<gridMain, 256, SMEM_DYN>>>(
        xloc, nullptr, nullptr, wVAL, nullptr, nullptr, nullptr, nullptr, vL,
        CTX, CTX, 3*CTX, CTX, 0, 0, 0, 1.f);

    // one-time masked-row stats (means over rows >= NT)
    colmean_masked_kernel<<<BB, 512>>>(vL,   ent_num, SvL);
    colmean_masked_kernel<<<BB, 512>>>(prjl, ent_num, Spl);

    float* xc = xctxA;
    float* xn = xctxB;
    for (int t = 0; t < TT; t++) {
        small_linear_fast<false><<<gridSL, 256>>>(qbase, wQIN2 + (size_t)t * CMD * CMD,
                                                  qInput2_b + (size_t)t * CMD, qcmd);
        text_cmd_fast<<<BB, 1024>>>(qcmd, lstm, c2l_w, c2l_b, q_length, cmd);
        small_linear_fast<false><<<gridSL, 256>>>(cmd, wPK, pk_b, pkg);
        small_linear_fast<false><<<gridSL, 256>>>(cmd, wPV, pv_b, pvg);

        // analytic masked-row v mean (uses current xcm; before ctx update)
        vmask_kernel<<<BB, 256>>>(xcm, wPXC, pxc_b, Spl, wVAL, val_b, pvg, SvL,
                                  ent_num, vmask);

        // pp = (x_ctx @ pxc + b) * proj_loc — live tiles only now
        gemm_mma<1,3,true,false,3,false><<<gridMain, 256, SMEM_DYN>>>(
            xc, nullptr, nullptr, wPXC, pxc_b, prjl, nullptr, ent_num, pp,
            CTX, CTX, CTX, CTX, 0, 0, 0, 1.f);

        // q/k: live rows only; v: live rows only, written TRANSPOSED to vT
        gemm_mma<2,0,true,true,3,false><<<gridMain, 256, SMEM_DYN>>>(
            xc, pp, nullptr, wQRY + CTX, qry_b, nullptr, qL, ent_num, q,
            2*CTX, 0, 3*CTX, CTX, 0, 0, 0, 1.f);
        gemm_mma<2,2,true,true,3,false><<<gridMain, 256, SMEM_DYN>>>(
            xc, pp, nullptr, wKEY + CTX, key_b, pkg, kL, ent_num, k,
            2*CTX, 0, 3*CTX, CTX, 0, 0, 0, 1.f);
        gemm_mma<2,2,true,true,3,true><<<gridMain, 256, SMEM_DYN>>>(
            xc, pp, nullptr, wVAL + CTX, val_b, pvg, vL, ent_num, vT,
            2*CTX, 0, 3*CTX, CTX, 0, 0, 0, 1.f);

        // score[b] = scale * q[b] @ k[b]^T — live tiles only
        gemm_mma<1,0,false,false,1,false><<<gridScore, 256, SMEM_DYN>>>(
            q, nullptr, nullptr, k, nullptr, nullptr, nullptr, ent_num, score,
            CTX, CTX, CTX, NENT,
            (size_t)NENT * CTX, (size_t)NENT * CTX, (size_t)NENT * NENT, scale);

        attn_softmax_kernel<<<MROWS, 256>>>(score, ent_num);

        // message live rows; mean = live sum (cols < NT) + analytic masked part
        gemm_mma<1,0,true,false,2,false><<<gridMsg, 256, SMEM_DYN>>>(
            score, nullptr, nullptr, vT, nullptr, nullptr, nullptr, ent_num, msg,
            NENT, NENT, NENT, CTX,
            (size_t)NENT * NENT, (size_t)CTX * NENT, (size_t)NENT * CTX, 1.f);
        mean_vT_kernel<<<dim3(CTX / 8, BB), 256>>>(vT, ent_num, vmask, msgm);

        // x_ctx' live rows via MMA; masked rows via parallel broadcast
        gemm_mma<2,0,true,false,3,false><<<gridMain, 256, SMEM_DYN>>>(
            xc, msg, nullptr, wMU, mu_b, nullptr, nullptr, ent_num, xn,
            2*CTX, 0, 2*CTX, CTX, 0, 0, 0, 1.f);
        ctx_compute_kernel<<<BB, 256>>>(msgm, wMU, mu_b, ent_num, xcm);
        bcast_rows_kernel<<<dim3(NENT / 128, BB), 256>>>(xcm, ent_num, xn);

        float* tmp = xc; xc = xn; xn = tmp;
    }

    // out = [x_loc | x_ctx] @ ck + b
    gemm_mma<2,0,false,false,0,false><<<gridMain, 256, SMEM_DYN>>>(
        xloc, xc, nullptr, wCK, ck_b, nullptr, nullptr, nullptr, (float*)d_out,
        2*CTX, 0, 2*CTX, CTX, 0, 0, 0, 1.f);
}

// round 14
// speedup vs baseline: 1.2331x; 1.2331x over previous
#include <cuda_runtime.h>
#include <math.h>
#include <stdint.h>

#define BB     32
#define NENT   1024
#define LQL    128
#define DFEAT  2112
#define CTX    512
#define CMD    512
#define TT     4
#define MROWS  (BB*NENT)
#define NEGV   (-1e30f)

// ---- mma.sync GEMM tiling ----
#define BMm 128
#define BNm 128
#define BKm 32
#define STAGES 3
#define SROW 36
#define STAGE_F (2 * BMm * SROW)
#define TILE_F  (BMm * SROW)
#define SMEM_DYN (STAGES * STAGE_F * 4)
#define TSST 132

// ---- scratch ----
__device__ float g_imgr   [(size_t)MROWS*DFEAT];
__device__ float g_invnorm[MROWS];
__device__ float g_xloc   [(size_t)MROWS*CTX];
__device__ float g_xctx0  [(size_t)MROWS*CTX];
__device__ float g_xctx1  [(size_t)MROWS*CTX];
__device__ float g_projloc[(size_t)MROWS*CTX];
__device__ float g_pp     [(size_t)MROWS*CTX];
__device__ float g_q      [(size_t)MROWS*CTX];
__device__ float g_k      [(size_t)MROWS*CTX];
__device__ float g_vT     [(size_t)MROWS*CTX];   // [B][CTX][NENT]
__device__ float g_msg    [(size_t)MROWS*CTX];
__device__ float g_qL     [(size_t)MROWS*CTX];
__device__ float g_kL     [(size_t)MROWS*CTX];
__device__ float g_vL     [(size_t)MROWS*CTX];
__device__ float g_score  [(size_t)BB*NENT*NENT];
__device__ float g_qbase  [BB*CMD];
__device__ float g_qcmd   [BB*CMD];
__device__ float g_cmd    [BB*CMD];
__device__ float g_pkg    [BB*CTX];
__device__ float g_pvg    [BB*CTX];
__device__ float g_msgm   [BB*CTX];
__device__ float g_xcm    [BB*CTX];
__device__ float g_SvL    [BB*CTX];
__device__ float g_Spl    [BB*CTX];
__device__ float g_ppm    [BB*CTX];
__device__ float g_vmask  [BB*CTX];
__device__ float g_wT_ikb[(size_t)CTX*DFEAT];
__device__ float g_wT_pxl[(size_t)CTX*CTX];
__device__ float g_wT_pxc[(size_t)CTX*CTX];
__device__ float g_wT_qry[(size_t)CTX*3*CTX];
__device__ float g_wT_key[(size_t)CTX*3*CTX];
__device__ float g_wT_val[(size_t)CTX*3*CTX];
__device__ float g_wT_mu [(size_t)CTX*2*CTX];
__device__ float g_wT_ck [(size_t)CTX*2*CTX];
__device__ float g_wT_qin [(size_t)CMD*CMD];
__device__ float g_wT_qin2[(size_t)TT*CMD*CMD];
__device__ float g_wT_pk  [(size_t)CMD*CTX];
__device__ float g_wT_pv  [(size_t)CMD*CTX];

__device__ __forceinline__ float rna_tf32(float f) {
    uint32_t r; asm("cvt.rna.tf32.f32 %0, %1;" : "=r"(r) : "f"(f));
    return __uint_as_float(r);
}
__device__ __forceinline__ uint32_t smem_u32(const void* p) {
    uint32_t a;
    asm("{ .reg .u64 t; cvta.to.shared.u64 t, %1; cvt.u32.u64 %0, t; }" : "=r"(a) : "l"(p));
    return a;
}
__device__ __forceinline__ void cp_async16(uint32_t saddr, const void* gptr) {
    asm volatile("cp.async.cg.shared.global [%0], [%1], 16;" :: "r"(saddr), "l"(gptr));
}
#define CP_COMMIT() asm volatile("cp.async.commit_group;" ::: "memory")
#define CP_WAIT1()  asm volatile("cp.async.wait_group 1;" ::: "memory")

__device__ __forceinline__ void ldsm_x4(uint32_t addr, uint32_t& r0, uint32_t& r1,
                                        uint32_t& r2, uint32_t& r3)
{
    asm volatile("ldmatrix.sync.aligned.m8n8.x4.shared.b16 {%0,%1,%2,%3}, [%4];"
                 : "=r"(r0), "=r"(r1), "=r"(r2), "=r"(r3) : "r"(addr));
}

__device__ __forceinline__ void mma_m16n8k8(float* d,
    uint32_t a0, uint32_t a1, uint32_t a2, uint32_t a3,
    uint32_t b0, uint32_t b1)
{
    asm volatile(
        "mma.sync.aligned.m16n8k8.row.col.f32.tf32.tf32.f32 "
        "{%0,%1,%2,%3}, {%4,%5,%6,%7}, {%8,%9}, {%0,%1,%2,%3};"
        : "+f"(d[0]), "+f"(d[1]), "+f"(d[2]), "+f"(d[3])
        : "r"(a0), "r"(a1), "r"(a2), "r"(a3), "r"(b0), "r"(b1));
}

// ---------------- tensor-core GEMM via mma.sync (tf32) ----------------
// MASK 0: none
//      1 (score, z=batch): skip tile if m0>=en || n0>=en
//      2 (message, z=batch): skip tile if m0>=en; truncate K at ceil(en/BKm)
//      3 (row-masked, z=1, batch=m0>>10): skip tile if (m0&1023)>=en
// TRANSC: write C transposed per batch: C is [B][CTX][NENT]; batch = m0>>10.
template<int NSRC, int EPI, bool RND, bool ADD, int MASK, bool TRANSC>
__global__ __launch_bounds__(256, 2)
void gemm_mma(const float* __restrict__ A0, const float* __restrict__ A1,
              const float* __restrict__ A2, const float* __restrict__ Bt,
              const float* __restrict__ bias, const float* __restrict__ extra,
              const float* __restrict__ addC, const int* __restrict__ ennum,
              float* __restrict__ C,
              int K, int lda, int ldb, int ldc,
              size_t sA, size_t sB, size_t sC, float alpha)
{
    extern __shared__ float smem[];
    const uint32_t sbase = smem_u32(smem);

    const int tid = threadIdx.x;
    const int z = blockIdx.z;
    const int m0 = blockIdx.y * BMm;
    const int n0 = blockIdx.x * BNm;

    int Keff = K;
    if (MASK == 1 || MASK == 2) {
        const int en = ennum[z];
        if (m0 >= en) return;
        if (MASK == 1 && n0 >= en) return;
        if (MASK == 2) { const int kc = ((en + BKm - 1) / BKm) * BKm; Keff = kc < K ? kc : K; }
    } else if (MASK == 3) {
        const int en = ennum[m0 >> 10];
        if ((m0 & 1023) >= en) return;
    }

    const float* Abase = A0 + (size_t)z * sA;
    const float* Bbase = Bt + (size_t)z * sB;
    float* Cbase = C + (size_t)z * sC;

    const int wid = tid >> 5, lane = tid & 31;
    const int wm = (wid & 3) * 32;
    const int wn = (wid >> 2) * 64;
    const int gr = lane >> 2;
    const int gc = lane & 3;

    const int lr = lane & 7, lg = lane >> 3;
    const int arow  = wm + lr + (lg & 1) * 8;
    const int akoff = (lg >> 1) * 4;
    const int brow  = wn + lr + (lg >> 1) * 8;
    const int bkoff = (lg & 1) * 4;

    const int prow0 = tid >> 3;
    const int pkq   = (tid & 7) * 4;

    float acc[2][8][4] = {};
    const int NCC = Keff / BKm;

    auto loadChunk = [&](int c, int st) {
        const int k0 = c * BKm;
        const float* Ap; int al, ak;
        if (NSRC == 1) { Ap = Abase; al = lda; ak = k0; }
        else {
            const int src = k0 >> 9;
            Ap = (src == 0) ? A0 : ((src == 1) ? A1 : A2);
            al = CTX; ak = k0 & (CTX - 1);
        }
        const uint32_t sa = sbase + (uint32_t)(st * STAGE_F) * 4;
        const uint32_t sb = sa + (uint32_t)TILE_F * 4;
        #pragma unroll
        for (int t = 0; t < 4; ++t) {
            const int row = prow0 + t * 32;
            cp_async16(sa + (uint32_t)(row * SROW + pkq) * 4,
                       Ap + (size_t)(m0 + row) * al + ak + pkq);
            cp_async16(sb + (uint32_t)(row * SROW + pkq) * 4,
                       Bbase + (size_t)(n0 + row) * ldb + k0 + pkq);
        }
        CP_COMMIT();
    };

    auto compute = [&](int st) {
        const uint32_t SAu = sbase + (uint32_t)(st * STAGE_F) * 4;
        const uint32_t SBu = SAu + (uint32_t)TILE_F * 4;
        #pragma unroll
        for (int kk = 0; kk < BKm; kk += 8) {
            uint32_t b[8][2];
            #pragma unroll
            for (int ntp = 0; ntp < 4; ++ntp) {
                const uint32_t addr = SBu +
                    (uint32_t)(((brow + ntp * 16) * SROW) + kk + bkoff) * 4;
                ldsm_x4(addr, b[2*ntp][0], b[2*ntp][1], b[2*ntp+1][0], b[2*ntp+1][1]);
            }
            #pragma unroll
            for (int mt = 0; mt < 2; ++mt) {
                uint32_t a0, a1, a2, a3;
                const uint32_t addr = SAu +
                    (uint32_t)(((arow + mt * 16) * SROW) + kk + akoff) * 4;
                ldsm_x4(addr, a0, a1, a2, a3);
                #pragma unroll
                for (int nt = 0; nt < 8; ++nt)
                    mma_m16n8k8(acc[mt][nt], a0, a1, a2, a3, b[nt][0], b[nt][1]);
            }
        }
    };

    #pragma unroll
    for (int s = 0; s < STAGES - 1; ++s) {
        if (s < NCC) loadChunk(s, s);
        else CP_COMMIT();
    }
    {
        int st = 0;
        for (int c = 0; c < NCC; ++c) {
            CP_WAIT1();
            __syncthreads();
            const int nc = c + STAGES - 1;
            int nst = st + STAGES - 1; if (nst >= STAGES) nst -= STAGES;
            if (nc < NCC) loadChunk(nc, nst);
            else CP_COMMIT();
            compute(st);
            if (++st == STAGES) st = 0;
        }
    }

    if (TRANSC) __syncthreads();

    #pragma unroll
    for (int mt = 0; mt < 2; ++mt) {
        #pragma unroll
        for (int half = 0; half < 2; ++half) {
            const int m = m0 + wm + mt * 16 + gr + half * 8;
            const float rs = (EPI == 1) ? extra[m] : 0.f;
            #pragma unroll
            for (int nt = 0; nt < 8; ++nt) {
                const int n = n0 + wn + nt * 8 + gc * 2;
                float v0 = acc[mt][nt][half * 2 + 0];
                float v1 = acc[mt][nt][half * 2 + 1];
                if (ADD) {
                    const float2 ad = *reinterpret_cast<const float2*>(addC + (size_t)m * ldc + n);
                    v0 += ad.x; v1 += ad.y;
                }
                const float bb0 = bias ? bias[n]     : 0.f;
                const float bb1 = bias ? bias[n + 1] : 0.f;
                if (EPI == 0)      { v0 = v0 * alpha + bb0;  v1 = v1 * alpha + bb1; }
                else if (EPI == 1) { v0 = v0 * rs + bb0;     v1 = v1 * rs + bb1; }
                else if (EPI == 2) {
                    const float* g = extra + (size_t)(m >> 10) * CTX + n;
                    v0 = (v0 + bb0) * g[0];
                    v1 = (v1 + bb1) * g[1];
                } else {
                    const float* g = extra + (size_t)m * ldc + n;
                    v0 = (v0 + bb0) * g[0];
                    v1 = (v1 + bb1) * g[1];
                }
                if (RND) { v0 = rna_tf32(v0); v1 = rna_tf32(v1); }
                if (!TRANSC) {
                    *reinterpret_cast<float2*>(Cbase + (size_t)m * ldc + n) = make_float2(v0, v1);
                } else {
                    const int ml = wm + mt * 16 + gr + half * 8;
                    const int nl = wn + nt * 8 + gc * 2;
                    smem[(size_t)nl * TSST + ml] = v0;
                    smem[(size_t)(nl + 1) * TSST + ml] = v1;
                }
            }
        }
    }

    if (TRANSC) {
        __syncthreads();
        float* outT = C + (size_t)(m0 >> 10) * CTX * NENT;
        const int bofs = m0 & 1023;
        #pragma unroll
        for (int r = 0; r < 16; ++r) {
            const int row = wid * 16 + r;
            const float4 val = *reinterpret_cast<const float4*>(&smem[(size_t)row * TSST + lane * 4]);
            *reinterpret_cast<float4*>(outT + (size_t)(n0 + row) * NENT + bofs + lane * 4) = val;
        }
    }
}

// ---- one-time: column mean of src rows [NT, NENT) per batch (4-acc MLP) ----
__global__ __launch_bounds__(512)
void colmean_masked_kernel(const float* __restrict__ src, const int* __restrict__ ennum,
                           float* __restrict__ out)
{
    const int b = blockIdx.x;
    const int en = ennum[b];
    const int NT = ((en + 127) >> 7) << 7;
    if (NT >= NENT) return;
    const int d = threadIdx.x;
    const float* base = src + (size_t)b * NENT * CTX + d;
    float s0 = 0.f, s1 = 0.f, s2 = 0.f, s3 = 0.f;
    for (int m = NT; m < NENT; m += 4) {          // (NENT-NT) multiple of 128
        s0 += base[(size_t)(m + 0) * CTX];
        s1 += base[(size_t)(m + 1) * CTX];
        s2 += base[(size_t)(m + 2) * CTX];
        s3 += base[(size_t)(m + 3) * CTX];
    }
    out[b * CTX + d] = ((s0 + s1) + (s2 + s3)) * (1.f / (float)(NENT - NT));
}

// ---- wide: ppm[b][j] = (xcm[b]@pxc_row_j + pxc_b[j]) * Spl[b][j] ----
__global__ __launch_bounds__(256)
void ppm_kernel(const float* __restrict__ xcm, const float* __restrict__ wPXC,
                const float* __restrict__ pxc_b, const float* __restrict__ Spl,
                const int* __restrict__ ennum, float* __restrict__ ppm)
{
    const int b = blockIdx.y;
    const int en = ennum[b];
    if (((en + 127) >> 7 << 7) >= NENT) return;
    const int jb = blockIdx.x * 32;
    const int tid = threadIdx.x, wid = tid >> 5, lane = tid & 31;
    __shared__ float x[CTX];
    for (int d = tid; d < CTX; d += 256) x[d] = xcm[b * CTX + d];
    __syncthreads();
    #pragma unroll
    for (int jj = 0; jj < 4; ++jj) {
        const int j = jb + wid * 4 + jj;
        const float* w = wPXC + (size_t)j * CTX;
        float acc = 0.f;
        #pragma unroll
        for (int i = 0; i < CTX / 32; ++i)
            acc = fmaf(x[lane + 32 * i], w[lane + 32 * i], acc);
        #pragma unroll
        for (int o = 16; o > 0; o >>= 1) acc += __shfl_down_sync(0xFFFFFFFFu, acc, o);
        if (lane == 0) ppm[b * CTX + j] = (acc + pxc_b[j]) * Spl[b * CTX + j];
    }
}

// ---- wide: vmask[b][d] = ([xcm|ppm]@wVAL_row_d[CTX..3CTX) + val_b + SvL) * pvg ----
__global__ __launch_bounds__(256)
void vmask_wide_kernel(const float* __restrict__ xcm, const float* __restrict__ ppm,
                       const float* __restrict__ wVAL, const float* __restrict__ val_b,
                       const float* __restrict__ pvg, const float* __restrict__ SvL,
                       const int* __restrict__ ennum, float* __restrict__ vmask)
{
    const int b = blockIdx.y;
    const int en = ennum[b];
    if (((en + 127) >> 7 << 7) >= NENT) return;
    const int jb = blockIdx.x * 32;
    const int tid = threadIdx.x, wid = tid >> 5, lane = tid & 31;
    __shared__ float x[2 * CTX];
    for (int d = tid; d < CTX; d += 256) {
        x[d] = xcm[b * CTX + d];
        x[CTX + d] = ppm[b * CTX + d];
    }
    __syncthreads();
    #pragma unroll
    for (int jj = 0; jj < 4; ++jj) {
        const int d = jb + wid * 4 + jj;
        const float* w = wVAL + (size_t)d * (3 * CTX) + CTX;
        float acc = 0.f;
        #pragma unroll
        for (int i = 0; i < (2 * CTX) / 32; ++i)
            acc = fmaf(x[lane + 32 * i], w[lane + 32 * i], acc);
        #pragma unroll
        for (int o = 16; o > 0; o >>= 1) acc += __shfl_down_sync(0xFFFFFFFFu, acc, o);
        if (lane == 0)
            vmask[b * CTX + d] = (acc + val_b[d] + SvL[b * CTX + d]) * pvg[b * CTX + d];
    }
}

// ---- per-batch mean over vT rows: unrolled predicated sum + analytic tail ----
__global__ void mean_vT_kernel(const float* __restrict__ vT, const int* __restrict__ ennum,
                               const float* __restrict__ vmask, float* __restrict__ msgm)
{
    const int b = blockIdx.y;
    const int en = ennum[b];
    if (en >= NENT) return;
    const int NT = ((en + 127) >> 7) << 7;
    const int wid = threadIdx.x >> 5, lane = threadIdx.x & 31;
    const int d = blockIdx.x * 8 + wid;
    const float* row = vT + (size_t)b * CTX * NENT + (size_t)d * NENT;
    float s = 0.f;
    #pragma unroll
    for (int i = 0; i < NENT / 32; ++i) {
        float x = row[lane + 32 * i];
        if (lane + 32 * i >= NT) x = 0.f;        // stale cols excluded in-register
        s += x;
    }
    #pragma unroll
    for (int o = 16; o > 0; o >>= 1) s += __shfl_down_sync(0xFFFFFFFFu, s, o);
    if (lane == 0)
        msgm[b * CTX + d] = rna_tf32((s + (float)(NENT - NT) * vmask[b * CTX + d]) * (1.f / NENT));
}

// ---- masked-row x_ctx compute ----
__global__ __launch_bounds__(256)
void ctx_compute_kernel(const float* __restrict__ msgm, const float* __restrict__ wMU,
                        const float* __restrict__ mu_b, const int* __restrict__ ennum,
                        float* __restrict__ xcm)
{
    const int b = blockIdx.x;
    if (ennum[b] >= NENT) return;
    const int tid = threadIdx.x;
    const int wid = tid >> 5, lane = tid & 31;
    __shared__ float x[2 * CTX];
    __shared__ float y[CTX];
    for (int d = tid; d < CTX; d += 256) {
        x[d] = xcm[b * CTX + d];
        x[CTX + d] = msgm[b * CTX + d];
    }
    __syncthreads();
    for (int j = wid; j < CTX; j += 8) {
        const float* w = wMU + (size_t)j * (2 * CTX);
        float acc = 0.f;
        #pragma unroll
        for (int i = 0; i < (2 * CTX) / 32; ++i)
            acc = fmaf(x[lane + 32 * i], w[lane + 32 * i], acc);
        #pragma unroll
        for (int o = 16; o > 0; o >>= 1)
            acc += __shfl_down_sync(0xFFFFFFFFu, acc, o);
        if (lane == 0) y[j] = rna_tf32(acc + mu_b[j]);
    }
    __syncthreads();
    for (int d = tid; d < CTX; d += 256) xcm[b * CTX + d] = y[d];
}

// ---- broadcast xcm row into xn masked rows ----
__global__ __launch_bounds__(256)
void bcast_rows_kernel(const float* __restrict__ xcm, const int* __restrict__ ennum,
                       float* __restrict__ xn)
{
    const int b = blockIdx.y;
    const int en = ennum[b];
    const int r0 = blockIdx.x * 128;
    int start = r0 > en ? r0 : en;
    const int end = r0 + 128;
    if (start >= end) return;
    __shared__ float y[CTX];
    const int tid = threadIdx.x;
    for (int d = tid; d < CTX; d += 256) y[d] = xcm[b * CTX + d];
    __syncthreads();
    const int c4 = (tid & 127) * 4;
    const float4 val = *reinterpret_cast<const float4*>(&y[c4]);
    float* base = xn + (size_t)b * NENT * CTX;
    for (int m = start + (tid >> 7); m < end; m += 2)
        *reinterpret_cast<float4*>(base + (size_t)m * CTX + c4) = val;
}

// ---- transpose, optional tf32 round ----
template<bool RND>
__global__ void transpose_kernel(const float* __restrict__ in, float* __restrict__ out,
                                 int R, int C, size_t sIn, size_t sOut)
{
    __shared__ float tile[32][33];
    const int z = blockIdx.z;
    in  += (size_t)z * sIn;
    out += (size_t)z * sOut;
    const int r0 = blockIdx.y * 32, c0 = blockIdx.x * 32;
    #pragma unroll
    for (int i = threadIdx.y; i < 32; i += 8) {
        float x = in[(size_t)(r0 + i) * C + c0 + threadIdx.x];
        tile[i][threadIdx.x] = RND ? rna_tf32(x) : x;
    }
    __syncthreads();
    #pragma unroll
    for (int i = threadIdx.y; i < 32; i += 8)
        out[(size_t)(c0 + i) * R + r0 + threadIdx.x] = tile[threadIdx.x][i];
}

// ---- fused row inv-norm + tf32-rounded copy ----
__global__ void rownorm_round_kernel(const float* __restrict__ img, float* __restrict__ invn,
                                     float* __restrict__ imgr)
{
    const int m = blockIdx.x;
    const float4* r4 = reinterpret_cast<const float4*>(img + (size_t)m * DFEAT);
    float4* o4 = reinterpret_cast<float4*>(imgr + (size_t)m * DFEAT);
    const int tid = threadIdx.x;
    float s = 0.f;
    for (int i = tid; i < DFEAT / 4; i += 256) {
        float4 u = r4[i];
        s = fmaf(u.x, u.x, s); s = fmaf(u.y, u.y, s);
        s = fmaf(u.z, u.z, s); s = fmaf(u.w, u.w, s);
        u.x = rna_tf32(u.x); u.y = rna_tf32(u.y);
        u.z = rna_tf32(u.z); u.w = rna_tf32(u.w);
        o4[i] = u;
    }
    __shared__ float red[256];
    red[tid] = s; __syncthreads();
    for (int o = 128; o > 0; o >>= 1) { if (tid < o) red[tid] += red[tid + o]; __syncthreads(); }
    if (tid == 0) invn[m] = 1.f / fmaxf(sqrtf(red[0]), 1e-12f);
}

__global__ void ctx_init_kernel(const float* __restrict__ initMem, float* __restrict__ xctx,
                                float* __restrict__ xcm)
{
    const size_t i = (size_t)blockIdx.x * blockDim.x + threadIdx.x;
    const float val = rna_tf32(initMem[i & (CTX - 1)]);
    xctx[i] = val;
    if (i < BB * CTX) xcm[i] = val;
}

// ---- fast batch-32 linear ----
template<bool ELU>
__global__ void small_linear_fast(const float* __restrict__ in, const float* __restrict__ wT,
                                  const float* __restrict__ bias, float* __restrict__ out)
{
    const int b = blockIdx.y;
    const int jb = blockIdx.x * 32;
    const int tid = threadIdx.x;
    const int wid = tid >> 5, lane = tid & 31;
    __shared__ float x[CMD];
    for (int d = tid; d < CMD; d += 256) x[d] = in[b * CMD + d];
    __syncthreads();
    #pragma unroll
    for (int jj = 0; jj < 4; ++jj) {
        const int j = jb + wid * 4 + jj;
        const float* w = wT + (size_t)j * CMD;
        float acc = 0.f;
        #pragma unroll
        for (int i = 0; i < CMD / 32; ++i)
            acc = fmaf(x[lane + 32 * i], w[lane + 32 * i], acc);
        #pragma unroll
        for (int o = 16; o > 0; o >>= 1)
            acc += __shfl_down_sync(0xFFFFFFFFu, acc, o);
        if (lane == 0) {
            acc += bias[j];
            if (ELU) acc = (acc > 0.f) ? acc : expm1f(acc);
            out[b * CMD + j] = acc;
        }
    }
}

// ---- fast textual command ----
__global__ __launch_bounds__(1024)
void text_cmd_fast(const float* __restrict__ qcmd, const float* __restrict__ lstm,
                   const float* __restrict__ c2l_w, const float* __restrict__ c2l_b,
                   const int* __restrict__ qlen, float* __restrict__ cmd)
{
    const int b = blockIdx.x;
    const int tid = threadIdx.x;
    const int wid = tid >> 5, lane = tid & 31;
    __shared__ float e[CMD];
    __shared__ float att[LQL];
    __shared__ float red[128];
    __shared__ float smx, ssum;

    if (tid < CMD) e[tid] = qcmd[b * CMD + tid] * c2l_w[tid];
    __syncthreads();

    const int en = qlen[b];
    #pragma unroll
    for (int li = 0; li < 4; ++li) {
        const int l = wid + li * 32;
        const float* L = lstm + ((size_t)b * LQL + l) * CMD;
        float acc = 0.f;
        #pragma unroll
        for (int i = 0; i < CMD / 32; ++i)
            acc = fmaf(L[lane + 32 * i], e[lane + 32 * i], acc);
        #pragma unroll
        for (int o = 16; o > 0; o >>= 1)
            acc += __shfl_down_sync(0xFFFFFFFFu, acc, o);
        if (lane == 0) att[l] = (l >= en) ? NEGV : (acc + c2l_b[0]);
    }
    __syncthreads();

    if (tid < 128) red[tid] = att[tid];
    __syncthreads();
    for (int o = 64; o > 0; o >>= 1) {
        if (tid < o) red[tid] = fmaxf(red[tid], red[tid + o]);
        __syncthreads();
    }
    if (tid == 0) smx = red[0];
    __syncthreads();
    float ev = 0.f;
    if (tid < 128) { ev = expf(att[tid] - smx); red[tid] = ev; }
    __syncthreads();
    for (int o = 64; o > 0; o >>= 1) {
        if (tid < o) red[tid] += red[tid + o];
        __syncthreads();
    }
    if (tid == 0) ssum = red[0];
    __syncthreads();
    if (tid < 128) att[tid] = ev / ssum;
    __syncthreads();

    if (tid < CMD) {
        float acc = 0.f;
        const float* L = lstm + (size_t)b * LQL * CMD + tid;
        #pragma unroll 4
        for (int l = 0; l < LQL; ++l)
            acc = fmaf(att[l], L[(size_t)l * CMD], acc);
        cmd[b * CMD + tid] = acc;
    }
}

// masked row softmax (in place)
__global__ void attn_softmax_kernel(float* __restrict__ score, const int* __restrict__ entity_num)
{
    const int row = blockIdx.x;
    const int b = row >> 10;
    const int n = row & 1023;
    const int en = entity_num[b];
    if (n >= en) return;
    float* s = score + (size_t)row * NENT;
    const int tid = threadIdx.x;

    const int kc = ((en + 15) / 16) * 16;
    const int nblk = (kc + 255) >> 8;

    float v[4];
    float mx = -3.4e38f;
    #pragma unroll
    for (int j = 0; j < 4; j++) {
        const int m = tid + j * 256;
        float x = NEGV;
        if (j < nblk && m < en) x = s[m];
        v[j] = x;
        mx = fmaxf(mx, x);
    }
    __shared__ float red[256];
    red[tid] = mx; __syncthreads();
    for (int o = 128; o > 0; o >>= 1) { if (tid < o) red[tid] = fmaxf(red[tid], red[tid + o]); __syncthreads(); }
    mx = red[0];
    __syncthreads();

    float sum = 0.f;
    #pragma unroll
    for (int j = 0; j < 4; j++) { v[j] = expf(v[j] - mx); sum += v[j]; }
    red[tid] = sum; __syncthreads();
    for (int o = 128; o > 0; o >>= 1) { if (tid < o) red[tid] += red[tid + o]; __syncthreads(); }
    const float inv = 1.f / red[0];

    #pragma unroll
    for (int j = 0; j < 4; j++)
        if (j < nblk) s[tid + j * 256] = rna_tf32(v[j] * inv);
}

// ---------------- launch ----------------
template<typename T> static float* symaddr(T& sym) {
    void* p = nullptr;
    cudaGetSymbolAddress(&p, sym);
    return (float*)p;
}

extern "C" void kernel_launch(void* const* d_in, const int* in_sizes, int n_in,
                              void* d_out, int out_size)
{
    const float* images    = (const float*)d_in[0];
    const float* q_enc     = (const float*)d_in[1];
    const float* lstm      = (const float*)d_in[2];
    const int*   q_length  = (const int*)  d_in[3];
    const int*   ent_num   = (const int*)  d_in[4];
    const float* initKB_w  = (const float*)d_in[5];
    const float* initKB_b  = (const float*)d_in[6];
    const float* initMem   = (const float*)d_in[7];
    const float* qInput_w  = (const float*)d_in[8];
    const float* qInput_b  = (const float*)d_in[9];
    const float* qInput2_w = (const float*)d_in[10];
    const float* qInput2_b = (const float*)d_in[11];
    const float* c2l_w     = (const float*)d_in[12];
    const float* c2l_b     = (const float*)d_in[13];
    const float* pxl_w     = (const float*)d_in[14];
    const float* pxl_b     = (const float*)d_in[15];
    const float* pxc_w     = (const float*)d_in[16];
    const float* pxc_b     = (const float*)d_in[17];
    const float* qry_w     = (const float*)d_in[18];
    const float* qry_b     = (const float*)d_in[19];
    const float* key_w     = (const float*)d_in[20];
    const float* key_b     = (const float*)d_in[21];
    const float* val_w     = (const float*)d_in[22];
    const float* val_b     = (const float*)d_in[23];
    const float* pk_w      = (const float*)d_in[24];
    const float* pk_b      = (const float*)d_in[25];
    const float* pv_w      = (const float*)d_in[26];
    const float* pv_b      = (const float*)d_in[27];
    const float* mu_w      = (const float*)d_in[28];
    const float* mu_b      = (const float*)d_in[29];
    const float* ck_w      = (const float*)d_in[30];
    const float* ck_b      = (const float*)d_in[31];

    float* imgr  = symaddr(g_imgr);
    float* invn  = symaddr(g_invnorm);
    float* xloc  = symaddr(g_xloc);
    float* xctxA = symaddr(g_xctx0);
    float* xctxB = symaddr(g_xctx1);
    float* prjl  = symaddr(g_projloc);
    float* pp    = symaddr(g_pp);
    float* q     = symaddr(g_q);
    float* k     = symaddr(g_k);
    float* vT    = symaddr(g_vT);
    float* msg   = symaddr(g_msg);
    float* qL    = symaddr(g_qL);
    float* kL    = symaddr(g_kL);
    float* vL    = symaddr(g_vL);
    float* score = symaddr(g_score);
    float* qbase = symaddr(g_qbase);
    float* qcmd  = symaddr(g_qcmd);
    float* cmd   = symaddr(g_cmd);
    float* pkg   = symaddr(g_pkg);
    float* pvg   = symaddr(g_pvg);
    float* msgm  = symaddr(g_msgm);
    float* xcm   = symaddr(g_xcm);
    float* SvL   = symaddr(g_SvL);
    float* Spl   = symaddr(g_Spl);
    float* ppm   = symaddr(g_ppm);
    float* vmask = symaddr(g_vmask);
    float* wIKB  = symaddr(g_wT_ikb);
    float* wPXL  = symaddr(g_wT_pxl);
    float* wPXC  = symaddr(g_wT_pxc);
    float* wQRY  = symaddr(g_wT_qry);
    float* wKEY  = symaddr(g_wT_key);
    float* wVAL  = symaddr(g_wT_val);
    float* wMU   = symaddr(g_wT_mu);
    float* wCK   = symaddr(g_wT_ck);
    float* wQIN  = symaddr(g_wT_qin);
    float* wQIN2 = symaddr(g_wT_qin2);
    float* wPK   = symaddr(g_wT_pk);
    float* wPV   = symaddr(g_wT_pv);

    cudaFuncSetAttribute(gemm_mma<1,0,false,false,0,false>, cudaFuncAttributeMaxDynamicSharedMemorySize, SMEM_DYN);
    cudaFuncSetAttribute(gemm_mma<1,0,false,false,3,false>, cudaFuncAttributeMaxDynamicSharedMemorySize, SMEM_DYN);
    cudaFuncSetAttribute(gemm_mma<1,1,true ,false,0,false>, cudaFuncAttributeMaxDynamicSharedMemorySize, SMEM_DYN);
    cudaFuncSetAttribute(gemm_mma<1,3,true ,false,3,false>, cudaFuncAttributeMaxDynamicSharedMemorySize, SMEM_DYN);
    cudaFuncSetAttribute(gemm_mma<1,0,false,false,1,false>, cudaFuncAttributeMaxDynamicSharedMemorySize, SMEM_DYN);
    cudaFuncSetAttribute(gemm_mma<1,0,true ,false,2,false>, cudaFuncAttributeMaxDynamicSharedMemorySize, SMEM_DYN);
    cudaFuncSetAttribute(gemm_mma<2,0,true ,true ,3,false>, cudaFuncAttributeMaxDynamicSharedMemorySize, SMEM_DYN);
    cudaFuncSetAttribute(gemm_mma<2,2,true ,true ,3,false>, cudaFuncAttributeMaxDynamicSharedMemorySize, SMEM_DYN);
    cudaFuncSetAttribute(gemm_mma<2,2,true ,true ,3,true >, cudaFuncAttributeMaxDynamicSharedMemorySize, SMEM_DYN);
    cudaFuncSetAttribute(gemm_mma<2,0,true ,false,3,false>, cudaFuncAttributeMaxDynamicSharedMemorySize, SMEM_DYN);
    cudaFuncSetAttribute(gemm_mma<2,0,false,false,0,false>, cudaFuncAttributeMaxDynamicSharedMemorySize, SMEM_DYN);

    const float scale = 0.044194173824159216f;   // 1/sqrt(512)
    const dim3 tdim(32, 8);
    const dim3 gridMain(CTX / BNm, MROWS / BMm, 1);
    const dim3 gridScore(NENT / BNm, NENT / BMm, BB);
    const dim3 gridMsg(CTX / BNm, NENT / BMm, BB);
    const dim3 gridSL(CMD / 32, BB);

    // --- order: initKB GEMM at launch index 3 (ncu -s 5) ---
    transpose_kernel<true ><<<dim3(CTX/32, DFEAT/32, 1), tdim>>>(initKB_w, wIKB, DFEAT, CTX, 0, 0); // 0
    rownorm_round_kernel<<<MROWS, 256>>>(images, invn, imgr);                                        // 1
    ctx_init_kernel<<<(MROWS * CTX) / 256, 256>>>(initMem, xctxA, xcm);                              // 2
    // 3: x_loc = normalize(images) @ initKB_w + b   <-- ncu target
    gemm_mma<1,1,true,false,0,false><<<gridMain, 256, SMEM_DYN>>>(
        imgr, nullptr, nullptr, wIKB, initKB_b, invn, nullptr, nullptr, xloc,
        DFEAT, DFEAT, DFEAT, CTX, 0, 0, 0, 1.f);

    // remaining weight transposes
    transpose_kernel<false><<<dim3(CMD/32, CMD/32, 1), tdim>>>(qInput_w, wQIN, CMD, CMD, 0, 0);
    small_linear_fast<true><<<gridSL, 256>>>(q_enc, wQIN, qInput_b, qbase);
    transpose_kernel<true><<<dim3(CTX/32, CTX/32, 1),   tdim>>>(pxl_w, wPXL, CTX,   CTX, 0, 0);
    transpose_kernel<true><<<dim3(CTX/32, CTX/32, 1),   tdim>>>(pxc_w, wPXC, CTX,   CTX, 0, 0);
    transpose_kernel<true><<<dim3(CTX/32, 3*CTX/32, 1), tdim>>>(qry_w, wQRY, 3*CTX, CTX, 0, 0);
    transpose_kernel<true><<<dim3(CTX/32, 3*CTX/32, 1), tdim>>>(key_w, wKEY, 3*CTX, CTX, 0, 0);
    transpose_kernel<true><<<dim3(CTX/32, 3*CTX/32, 1), tdim>>>(val_w, wVAL, 3*CTX, CTX, 0, 0);
    transpose_kernel<true><<<dim3(CTX/32, 2*CTX/32, 1), tdim>>>(mu_w,  wMU,  2*CTX, CTX, 0, 0);
    transpose_kernel<true><<<dim3(CTX/32, 2*CTX/32, 1), tdim>>>(ck_w,  wCK,  2*CTX, CTX, 0, 0);
    transpose_kernel<false><<<dim3(CMD/32, CMD/32, TT), tdim>>>(qInput2_w, wQIN2, CMD, CMD,
                                                                (size_t)CMD*CMD, (size_t)CMD*CMD);
    transpose_kernel<false><<<dim3(CTX/32, CMD/32, 1), tdim>>>(pk_w, wPK, CMD, CTX, 0, 0);
    transpose_kernel<false><<<dim3(CTX/32, CMD/32, 1), tdim>>>(pv_w, wPV, CMD, CTX, 0, 0);

    // ---- iteration-invariant hoists ----
    gemm_mma<1,0,false,false,0,false><<<gridMain, 256, SMEM_DYN>>>(
        xloc, nullptr, nullptr, wPXL, pxl_b, nullptr, nullptr, nullptr, prjl,
        CTX, CTX, CTX, CTX, 0, 0, 0, 1.f);
    gemm_mma<1,0,false,false,3,false><<<gridMain, 256, SMEM_DYN>>>(
        xloc, nullptr, nullptr, wQRY, nullptr, nullptr, nullptr, ent_num, qL,
        CTX, CTX, 3*CTX, CTX, 0, 0, 0, 1.f);
    gemm_mma<1,0,false,false,3,false><<<gridMain, 256, SMEM_DYN>>>(
        xloc, nullptr, nullptr, wKEY, nullptr, nullptr, nullptr, ent_num, kL,
        CTX, CTX, 3*CTX, CTX, 0, 0, 0, 1.f);
    gemm_mma<1,0,false,false,0,false><<<gridMain, 256, SMEM_DYN>>>(
        xloc, nullptr, nullptr, wVAL, nullptr, nullptr, nullptr, nullptr, vL,
        CTX, CTX, 3*CTX, CTX, 0, 0, 0, 1.f);

    // one-time masked-row stats (means over rows >= NT)
    colmean_masked_kernel<<<BB, 512>>>(vL,   ent_num, SvL);
    colmean_masked_kernel<<<BB, 512>>>(prjl, ent_num, Spl);

    float* xc = xctxA;
    float* xn = xctxB;
    for (int t = 0; t < TT; t++) {
        small_linear_fast<false><<<gridSL, 256>>>(qbase, wQIN2 + (size_t)t * CMD * CMD,
                                                  qInput2_b + (size_t)t * CMD, qcmd);
        text_cmd_fast<<<BB, 1024>>>(qcmd, lstm, c2l_w, c2l_b, q_length, cmd);
        small_linear_fast<false><<<gridSL, 256>>>(cmd, wPK, pk_b, pkg);
        small_linear_fast<false><<<gridSL, 256>>>(cmd, wPV, pv_b, pvg);

        // analytic masked-row v mean (wide kernels; uses pre-update xcm)
        ppm_kernel<<<dim3(CTX/32, BB), 256>>>(xcm, wPXC, pxc_b, Spl, ent_num, ppm);
        vmask_wide_kernel<<<dim3(CTX/32, BB), 256>>>(xcm, ppm, wVAL, val_b, pvg, SvL,
                                                     ent_num, vmask);

        // pp = (x_ctx @ pxc + b) * proj_loc — live tiles only
        gemm_mma<1,3,true,false,3,false><<<gridMain, 256, SMEM_DYN>>>(
            xc, nullptr, nullptr, wPXC, pxc_b, prjl, nullptr, ent_num, pp,
            CTX, CTX, CTX, CTX, 0, 0, 0, 1.f);

        // q/k/v: live rows only; v written TRANSPOSED to vT
        gemm_mma<2,0,true,true,3,false><<<gridMain, 256, SMEM_DYN>>>(
            xc, pp, nullptr, wQRY + CTX, qry_b, nullptr, qL, ent_num, q,
            2*CTX, 0, 3*CTX, CTX, 0, 0, 0, 1.f);
        gemm_mma<2,2,true,true,3,false><<<gridMain, 256, SMEM_DYN>>>(
            xc, pp, nullptr, wKEY + CTX, key_b, pkg, kL, ent_num, k,
            2*CTX, 0, 3*CTX, CTX, 0, 0, 0, 1.f);
        gemm_mma<2,2,true,true,3,true><<<gridMain, 256, SMEM_DYN>>>(
            xc, pp, nullptr, wVAL + CTX, val_b, pvg, vL, ent_num, vT,
            2*CTX, 0, 3*CTX, CTX, 0, 0, 0, 1.f);

        // score[b] = scale * q[b] @ k[b]^T — live tiles only
        gemm_mma<1,0,false,false,1,false><<<gridScore, 256, SMEM_DYN>>>(
            q, nullptr, nullptr, k, nullptr, nullptr, nullptr, ent_num, score,
            CTX, CTX, CTX, NENT,
            (size_t)NENT * CTX, (size_t)NENT * CTX, (size_t)NENT * NENT, scale);

        attn_softmax_kernel<<<MROWS, 256>>>(score, ent_num);

        // message live rows; mean via unrolled live sum + analytic tail
        gemm_mma<1,0,true,false,2,false><<<gridMsg, 256, SMEM_DYN>>>(
            score, nullptr, nullptr, vT, nullptr, nullptr, nullptr, ent_num, msg,
            NENT, NENT, NENT, CTX,
            (size_t)NENT * NENT, (size_t)CTX * NENT, (size_t)NENT * CTX, 1.f);
        mean_vT_kernel<<<dim3(CTX / 8, BB), 256>>>(vT, ent_num, vmask, msgm);

        // x_ctx' live rows via MMA; masked rows via parallel broadcast
        gemm_mma<2,0,true,false,3,false><<<gridMain, 256, SMEM_DYN>>>(
            xc, msg, nullptr, wMU, mu_b, nullptr, nullptr, ent_num, xn,
            2*CTX, 0, 2*CTX, CTX, 0, 0, 0, 1.f);
        ctx_compute_kernel<<<BB, 256>>>(msgm, wMU, mu_b, ent_num, xcm);
        bcast_rows_kernel<<<dim3(NENT / 128, BB), 256>>>(xcm, ent_num, xn);

        float* tmp = xc; xc = xn; xn = tmp;
    }

    // out = [x_loc | x_ctx] @ ck + b
    gemm_mma<2,0,false,false,0,false><<<gridMain, 256, SMEM_DYN>>>(
        xloc, xc, nullptr, wCK, ck_b, nullptr, nullptr, nullptr, (float*)d_out,
        2*CTX, 0, 2*CTX, CTX, 0, 0, 0, 1.f);
}

// round 15
// speedup vs baseline: 1.3330x; 1.0810x over previous
#include <cuda_runtime.h>
#include <math.h>
#include <stdint.h>

#define BB     32
#define NENT   1024
#define LQL    128
#define DFEAT  2112
#define CTX    512
#define CMD    512
#define TT     4
#define MROWS  (BB*NENT)
#define NEGV   (-1e30f)

// ---- mma.sync GEMM tiling ----
#define BMm 128
#define BNm 128
#define BKm 32
#define STAGES 3
#define SROW 36
#define STAGE_F (2 * BMm * SROW)
#define TILE_F  (BMm * SROW)
#define SMEM_DYN (STAGES * STAGE_F * 4)
#define TSST 132

// ---- scratch ----
__device__ float g_imgr   [(size_t)MROWS*DFEAT];
__device__ float g_invnorm[MROWS];
__device__ float g_xloc   [(size_t)MROWS*CTX];
__device__ float g_xctx0  [(size_t)MROWS*CTX];
__device__ float g_xctx1  [(size_t)MROWS*CTX];
__device__ float g_projloc[(size_t)MROWS*CTX];
__device__ float g_pp     [(size_t)MROWS*CTX];
__device__ float g_q      [(size_t)MROWS*CTX];
__device__ float g_k      [(size_t)MROWS*CTX];
__device__ float g_vT     [(size_t)MROWS*CTX];   // [B][CTX][NENT]
__device__ float g_msg    [(size_t)MROWS*CTX];
__device__ float g_qL     [(size_t)MROWS*CTX];
__device__ float g_kL     [(size_t)MROWS*CTX];
__device__ float g_vL     [(size_t)MROWS*CTX];
__device__ float g_score  [(size_t)BB*NENT*NENT];
__device__ float g_qbase  [BB*CMD];
__device__ float g_qcmd   [BB*CMD];
__device__ float g_cmd    [BB*CMD];
__device__ float g_pkg    [BB*CTX];
__device__ float g_pvg    [BB*CTX];
__device__ float g_msgm   [BB*CTX];
__device__ float g_xcm    [BB*CTX];
__device__ float g_SvL    [BB*CTX];
__device__ float g_Spl    [BB*CTX];
__device__ float g_ppm    [BB*CTX];
__device__ float g_vmask  [BB*CTX];
__device__ float g_wT_ikb[(size_t)CTX*DFEAT];
__device__ float g_wT_pxl[(size_t)CTX*CTX];
__device__ float g_wT_pxc[(size_t)CTX*CTX];
__device__ float g_wT_qry[(size_t)CTX*3*CTX];
__device__ float g_wT_key[(size_t)CTX*3*CTX];
__device__ float g_wT_val[(size_t)CTX*3*CTX];
__device__ float g_wT_mu [(size_t)CTX*2*CTX];
__device__ float g_wT_ck [(size_t)CTX*2*CTX];
__device__ float g_wT_qin [(size_t)CMD*CMD];
__device__ float g_wT_qin2[(size_t)TT*CMD*CMD];
__device__ float g_wT_pk  [(size_t)CMD*CTX];
__device__ float g_wT_pv  [(size_t)CMD*CTX];

__device__ __forceinline__ float rna_tf32(float f) {
    uint32_t r; asm("cvt.rna.tf32.f32 %0, %1;" : "=r"(r) : "f"(f));
    return __uint_as_float(r);
}
__device__ __forceinline__ uint32_t smem_u32(const void* p) {
    uint32_t a;
    asm("{ .reg .u64 t; cvta.to.shared.u64 t, %1; cvt.u32.u64 %0, t; }" : "=r"(a) : "l"(p));
    return a;
}
__device__ __forceinline__ void cp_async16(uint32_t saddr, const void* gptr) {
    asm volatile("cp.async.cg.shared.global [%0], [%1], 16;" :: "r"(saddr), "l"(gptr));
}
#define CP_COMMIT() asm volatile("cp.async.commit_group;" ::: "memory")
#define CP_WAIT1()  asm volatile("cp.async.wait_group 1;" ::: "memory")

__device__ __forceinline__ void ldsm_x4(uint32_t addr, uint32_t& r0, uint32_t& r1,
                                        uint32_t& r2, uint32_t& r3)
{
    asm volatile("ldmatrix.sync.aligned.m8n8.x4.shared.b16 {%0,%1,%2,%3}, [%4];"
                 : "=r"(r0), "=r"(r1), "=r"(r2), "=r"(r3) : "r"(addr));
}

__device__ __forceinline__ void mma_m16n8k8(float* d,
    uint32_t a0, uint32_t a1, uint32_t a2, uint32_t a3,
    uint32_t b0, uint32_t b1)
{
    asm volatile(
        "mma.sync.aligned.m16n8k8.row.col.f32.tf32.tf32.f32 "
        "{%0,%1,%2,%3}, {%4,%5,%6,%7}, {%8,%9}, {%0,%1,%2,%3};"
        : "+f"(d[0]), "+f"(d[1]), "+f"(d[2]), "+f"(d[3])
        : "r"(a0), "r"(a1), "r"(a2), "r"(a3), "r"(b0), "r"(b1));
}

// ---------------- tensor-core GEMM via mma.sync (tf32) ----------------
// MASK 0: none
//      1 (score, z=batch): skip tile if m0>=en || n0>=en
//      2 (message, z=batch): skip tile if m0>=en; truncate K at ceil(en/BKm)
//      3 (row-masked, z=1, batch=m0>>10): skip tile if (m0&1023)>=en
// TRANSC: write C transposed per batch: C is [B][CTX][NENT]; batch = m0>>10.
template<int NSRC, int EPI, bool RND, bool ADD, int MASK, bool TRANSC>
__global__ __launch_bounds__(256, 2)
void gemm_mma(const float* __restrict__ A0, const float* __restrict__ A1,
              const float* __restrict__ A2, const float* __restrict__ Bt,
              const float* __restrict__ bias, const float* __restrict__ extra,
              const float* __restrict__ addC, const int* __restrict__ ennum,
              float* __restrict__ C,
              int K, int lda, int ldb, int ldc,
              size_t sA, size_t sB, size_t sC, float alpha)
{
    extern __shared__ float smem[];
    const uint32_t sbase = smem_u32(smem);

    const int tid = threadIdx.x;
    const int z = blockIdx.z;
    const int m0 = blockIdx.y * BMm;
    const int n0 = blockIdx.x * BNm;

    int Keff = K;
    if (MASK == 1 || MASK == 2) {
        const int en = ennum[z];
        if (m0 >= en) return;
        if (MASK == 1 && n0 >= en) return;
        if (MASK == 2) { const int kc = ((en + BKm - 1) / BKm) * BKm; Keff = kc < K ? kc : K; }
    } else if (MASK == 3) {
        const int en = ennum[m0 >> 10];
        if ((m0 & 1023) >= en) return;
    }

    const float* Abase = A0 + (size_t)z * sA;
    const float* Bbase = Bt + (size_t)z * sB;
    float* Cbase = C + (size_t)z * sC;

    const int wid = tid >> 5, lane = tid & 31;
    const int wm = (wid & 3) * 32;
    const int wn = (wid >> 2) * 64;
    const int gr = lane >> 2;
    const int gc = lane & 3;

    const int lr = lane & 7, lg = lane >> 3;
    const int arow  = wm + lr + (lg & 1) * 8;
    const int akoff = (lg >> 1) * 4;
    const int brow  = wn + lr + (lg >> 1) * 8;
    const int bkoff = (lg & 1) * 4;

    const int prow0 = tid >> 3;
    const int pkq   = (tid & 7) * 4;

    float acc[2][8][4] = {};
    const int NCC = Keff / BKm;

    auto loadChunk = [&](int c, int st) {
        const int k0 = c * BKm;
        const float* Ap; int al, ak;
        if (NSRC == 1) { Ap = Abase; al = lda; ak = k0; }
        else {
            const int src = k0 >> 9;
            Ap = (src == 0) ? A0 : ((src == 1) ? A1 : A2);
            al = CTX; ak = k0 & (CTX - 1);
        }
        const uint32_t sa = sbase + (uint32_t)(st * STAGE_F) * 4;
        const uint32_t sb = sa + (uint32_t)TILE_F * 4;
        #pragma unroll
        for (int t = 0; t < 4; ++t) {
            const int row = prow0 + t * 32;
            cp_async16(sa + (uint32_t)(row * SROW + pkq) * 4,
                       Ap + (size_t)(m0 + row) * al + ak + pkq);
            cp_async16(sb + (uint32_t)(row * SROW + pkq) * 4,
                       Bbase + (size_t)(n0 + row) * ldb + k0 + pkq);
        }
        CP_COMMIT();
    };

    auto compute = [&](int st) {
        const uint32_t SAu = sbase + (uint32_t)(st * STAGE_F) * 4;
        const uint32_t SBu = SAu + (uint32_t)TILE_F * 4;
        #pragma unroll
        for (int kk = 0; kk < BKm; kk += 8) {
            uint32_t b[8][2];
            #pragma unroll
            for (int ntp = 0; ntp < 4; ++ntp) {
                const uint32_t addr = SBu +
                    (uint32_t)(((brow + ntp * 16) * SROW) + kk + bkoff) * 4;
                ldsm_x4(addr, b[2*ntp][0], b[2*ntp][1], b[2*ntp+1][0], b[2*ntp+1][1]);
            }
            #pragma unroll
            for (int mt = 0; mt < 2; ++mt) {
                uint32_t a0, a1, a2, a3;
                const uint32_t addr = SAu +
                    (uint32_t)(((arow + mt * 16) * SROW) + kk + akoff) * 4;
                ldsm_x4(addr, a0, a1, a2, a3);
                #pragma unroll
                for (int nt = 0; nt < 8; ++nt)
                    mma_m16n8k8(acc[mt][nt], a0, a1, a2, a3, b[nt][0], b[nt][1]);
            }
        }
    };

    #pragma unroll
    for (int s = 0; s < STAGES - 1; ++s) {
        if (s < NCC) loadChunk(s, s);
        else CP_COMMIT();
    }
    {
        int st = 0;
        for (int c = 0; c < NCC; ++c) {
            CP_WAIT1();
            __syncthreads();
            const int nc = c + STAGES - 1;
            int nst = st + STAGES - 1; if (nst >= STAGES) nst -= STAGES;
            if (nc < NCC) loadChunk(nc, nst);
            else CP_COMMIT();
            compute(st);
            if (++st == STAGES) st = 0;
        }
    }

    if (TRANSC) __syncthreads();

    #pragma unroll
    for (int mt = 0; mt < 2; ++mt) {
        #pragma unroll
        for (int half = 0; half < 2; ++half) {
            const int m = m0 + wm + mt * 16 + gr + half * 8;
            const float rs = (EPI == 1) ? extra[m] : 0.f;
            #pragma unroll
            for (int nt = 0; nt < 8; ++nt) {
                const int n = n0 + wn + nt * 8 + gc * 2;
                float v0 = acc[mt][nt][half * 2 + 0];
                float v1 = acc[mt][nt][half * 2 + 1];
                if (ADD) {
                    const float2 ad = *reinterpret_cast<const float2*>(addC + (size_t)m * ldc + n);
                    v0 += ad.x; v1 += ad.y;
                }
                const float bb0 = bias ? bias[n]     : 0.f;
                const float bb1 = bias ? bias[n + 1] : 0.f;
                if (EPI == 0)      { v0 = v0 * alpha + bb0;  v1 = v1 * alpha + bb1; }
                else if (EPI == 1) { v0 = v0 * rs + bb0;     v1 = v1 * rs + bb1; }
                else if (EPI == 2) {
                    const float* g = extra + (size_t)(m >> 10) * CTX + n;
                    v0 = (v0 + bb0) * g[0];
                    v1 = (v1 + bb1) * g[1];
                } else {
                    const float* g = extra + (size_t)m * ldc + n;
                    v0 = (v0 + bb0) * g[0];
                    v1 = (v1 + bb1) * g[1];
                }
                if (RND) { v0 = rna_tf32(v0); v1 = rna_tf32(v1); }
                if (!TRANSC) {
                    *reinterpret_cast<float2*>(Cbase + (size_t)m * ldc + n) = make_float2(v0, v1);
                } else {
                    const int ml = wm + mt * 16 + gr + half * 8;
                    const int nl = wn + nt * 8 + gc * 2;
                    smem[(size_t)nl * TSST + ml] = v0;
                    smem[(size_t)(nl + 1) * TSST + ml] = v1;
                }
            }
        }
    }

    if (TRANSC) {
        __syncthreads();
        float* outT = C + (size_t)(m0 >> 10) * CTX * NENT;
        const int bofs = m0 & 1023;
        #pragma unroll
        for (int r = 0; r < 16; ++r) {
            const int row = wid * 16 + r;
            const float4 val = *reinterpret_cast<const float4*>(&smem[(size_t)row * TSST + lane * 4]);
            *reinterpret_cast<float4*>(outT + (size_t)(n0 + row) * NENT + bofs + lane * 4) = val;
        }
    }
}

// ---- one-time: column mean of src rows [NT, NENT) per batch (4-acc MLP) ----
__global__ __launch_bounds__(512)
void colmean_masked_kernel(const float* __restrict__ src, const int* __restrict__ ennum,
                           float* __restrict__ out)
{
    const int b = blockIdx.x;
    const int en = ennum[b];
    const int NT = ((en + 127) >> 7) << 7;
    if (NT >= NENT) return;
    const int d = threadIdx.x;
    const float* base = src + (size_t)b * NENT * CTX + d;
    float s0 = 0.f, s1 = 0.f, s2 = 0.f, s3 = 0.f;
    for (int m = NT; m < NENT; m += 4) {
        s0 += base[(size_t)(m + 0) * CTX];
        s1 += base[(size_t)(m + 1) * CTX];
        s2 += base[(size_t)(m + 2) * CTX];
        s3 += base[(size_t)(m + 3) * CTX];
    }
    out[b * CTX + d] = ((s0 + s1) + (s2 + s3)) * (1.f / (float)(NENT - NT));
}

// ---- wide: ppm[b][j] = (xcm[b]@pxc_row_j + pxc_b[j]) * Spl[b][j] ----
__global__ __launch_bounds__(256)
void ppm_kernel(const float* __restrict__ xcm, const float* __restrict__ wPXC,
                const float* __restrict__ pxc_b, const float* __restrict__ Spl,
                const int* __restrict__ ennum, float* __restrict__ ppm)
{
    const int b = blockIdx.y;
    const int en = ennum[b];
    if (((en + 127) >> 7 << 7) >= NENT) return;
    const int jb = blockIdx.x * 32;
    const int tid = threadIdx.x, wid = tid >> 5, lane = tid & 31;
    __shared__ float x[CTX];
    for (int d = tid; d < CTX; d += 256) x[d] = xcm[b * CTX + d];
    __syncthreads();
    #pragma unroll
    for (int jj = 0; jj < 4; ++jj) {
        const int j = jb + wid * 4 + jj;
        const float* w = wPXC + (size_t)j * CTX;
        float acc = 0.f;
        #pragma unroll
        for (int i = 0; i < CTX / 32; ++i)
            acc = fmaf(x[lane + 32 * i], w[lane + 32 * i], acc);
        #pragma unroll
        for (int o = 16; o > 0; o >>= 1) acc += __shfl_down_sync(0xFFFFFFFFu, acc, o);
        if (lane == 0) ppm[b * CTX + j] = (acc + pxc_b[j]) * Spl[b * CTX + j];
    }
}

// ---- wide: vmask[b][d] = ([xcm|ppm]@wVAL_row_d[CTX..3CTX) + val_b + SvL) * pvg ----
__global__ __launch_bounds__(256)
void vmask_wide_kernel(const float* __restrict__ xcm, const float* __restrict__ ppm,
                       const float* __restrict__ wVAL, const float* __restrict__ val_b,
                       const float* __restrict__ pvg, const float* __restrict__ SvL,
                       const int* __restrict__ ennum, float* __restrict__ vmask)
{
    const int b = blockIdx.y;
    const int en = ennum[b];
    if (((en + 127) >> 7 << 7) >= NENT) return;
    const int jb = blockIdx.x * 32;
    const int tid = threadIdx.x, wid = tid >> 5, lane = tid & 31;
    __shared__ float x[2 * CTX];
    for (int d = tid; d < CTX; d += 256) {
        x[d] = xcm[b * CTX + d];
        x[CTX + d] = ppm[b * CTX + d];
    }
    __syncthreads();
    #pragma unroll
    for (int jj = 0; jj < 4; ++jj) {
        const int d = jb + wid * 4 + jj;
        const float* w = wVAL + (size_t)d * (3 * CTX) + CTX;
        float acc = 0.f;
        #pragma unroll
        for (int i = 0; i < (2 * CTX) / 32; ++i)
            acc = fmaf(x[lane + 32 * i], w[lane + 32 * i], acc);
        #pragma unroll
        for (int o = 16; o > 0; o >>= 1) acc += __shfl_down_sync(0xFFFFFFFFu, acc, o);
        if (lane == 0)
            vmask[b * CTX + d] = (acc + val_b[d] + SvL[b * CTX + d]) * pvg[b * CTX + d];
    }
}

// ---- per-batch mean over vT rows: unrolled predicated sum + analytic tail ----
__global__ void mean_vT_kernel(const float* __restrict__ vT, const int* __restrict__ ennum,
                               const float* __restrict__ vmask, float* __restrict__ msgm)
{
    const int b = blockIdx.y;
    const int en = ennum[b];
    if (en >= NENT) return;
    const int NT = ((en + 127) >> 7) << 7;
    const int wid = threadIdx.x >> 5, lane = threadIdx.x & 31;
    const int d = blockIdx.x * 8 + wid;
    const float* row = vT + (size_t)b * CTX * NENT + (size_t)d * NENT;
    float s = 0.f;
    #pragma unroll
    for (int i = 0; i < NENT / 32; ++i) {
        float x = row[lane + 32 * i];
        if (lane + 32 * i >= NT) x = 0.f;
        s += x;
    }
    #pragma unroll
    for (int o = 16; o > 0; o >>= 1) s += __shfl_down_sync(0xFFFFFFFFu, s, o);
    if (lane == 0)
        msgm[b * CTX + d] = rna_tf32((s + (float)(NENT - NT) * vmask[b * CTX + d]) * (1.f / NENT));
}

// ---- masked-row x_ctx compute ----
__global__ __launch_bounds__(256)
void ctx_compute_kernel(const float* __restrict__ msgm, const float* __restrict__ wMU,
                        const float* __restrict__ mu_b, const int* __restrict__ ennum,
                        float* __restrict__ xcm)
{
    const int b = blockIdx.x;
    if (ennum[b] >= NENT) return;
    const int tid = threadIdx.x;
    const int wid = tid >> 5, lane = tid & 31;
    __shared__ float x[2 * CTX];
    __shared__ float y[CTX];
    for (int d = tid; d < CTX; d += 256) {
        x[d] = xcm[b * CTX + d];
        x[CTX + d] = msgm[b * CTX + d];
    }
    __syncthreads();
    for (int j = wid; j < CTX; j += 8) {
        const float* w = wMU + (size_t)j * (2 * CTX);
        float acc = 0.f;
        #pragma unroll
        for (int i = 0; i < (2 * CTX) / 32; ++i)
            acc = fmaf(x[lane + 32 * i], w[lane + 32 * i], acc);
        #pragma unroll
        for (int o = 16; o > 0; o >>= 1)
            acc += __shfl_down_sync(0xFFFFFFFFu, acc, o);
        if (lane == 0) y[j] = rna_tf32(acc + mu_b[j]);
    }
    __syncthreads();
    for (int d = tid; d < CTX; d += 256) xcm[b * CTX + d] = y[d];
}

// ---- broadcast xcm row into xn masked rows ----
__global__ __launch_bounds__(256)
void bcast_rows_kernel(const float* __restrict__ xcm, const int* __restrict__ ennum,
                       float* __restrict__ xn)
{
    const int b = blockIdx.y;
    const int en = ennum[b];
    const int r0 = blockIdx.x * 128;
    int start = r0 > en ? r0 : en;
    const int end = r0 + 128;
    if (start >= end) return;
    __shared__ float y[CTX];
    const int tid = threadIdx.x;
    for (int d = tid; d < CTX; d += 256) y[d] = xcm[b * CTX + d];
    __syncthreads();
    const int c4 = (tid & 127) * 4;
    const float4 val = *reinterpret_cast<const float4*>(&y[c4]);
    float* base = xn + (size_t)b * NENT * CTX;
    for (int m = start + (tid >> 7); m < end; m += 2)
        *reinterpret_cast<float4*>(base + (size_t)m * CTX + c4) = val;
}

// ---- transpose, optional tf32 round ----
template<bool RND>
__global__ void transpose_kernel(const float* __restrict__ in, float* __restrict__ out,
                                 int R, int C, size_t sIn, size_t sOut)
{
    __shared__ float tile[32][33];
    const int z = blockIdx.z;
    in  += (size_t)z * sIn;
    out += (size_t)z * sOut;
    const int r0 = blockIdx.y * 32, c0 = blockIdx.x * 32;
    #pragma unroll
    for (int i = threadIdx.y; i < 32; i += 8) {
        float x = in[(size_t)(r0 + i) * C + c0 + threadIdx.x];
        tile[i][threadIdx.x] = RND ? rna_tf32(x) : x;
    }
    __syncthreads();
    #pragma unroll
    for (int i = threadIdx.y; i < 32; i += 8)
        out[(size_t)(c0 + i) * R + r0 + threadIdx.x] = tile[threadIdx.x][i];
}

// ---- fused row inv-norm + tf32-rounded copy ----
__global__ void rownorm_round_kernel(const float* __restrict__ img, float* __restrict__ invn,
                                     float* __restrict__ imgr)
{
    const int m = blockIdx.x;
    const float4* r4 = reinterpret_cast<const float4*>(img + (size_t)m * DFEAT);
    float4* o4 = reinterpret_cast<float4*>(imgr + (size_t)m * DFEAT);
    const int tid = threadIdx.x;
    float s = 0.f;
    for (int i = tid; i < DFEAT / 4; i += 256) {
        float4 u = r4[i];
        s = fmaf(u.x, u.x, s); s = fmaf(u.y, u.y, s);
        s = fmaf(u.z, u.z, s); s = fmaf(u.w, u.w, s);
        u.x = rna_tf32(u.x); u.y = rna_tf32(u.y);
        u.z = rna_tf32(u.z); u.w = rna_tf32(u.w);
        o4[i] = u;
    }
    __shared__ float red[256];
    red[tid] = s; __syncthreads();
    for (int o = 128; o > 0; o >>= 1) { if (tid < o) red[tid] += red[tid + o]; __syncthreads(); }
    if (tid == 0) invn[m] = 1.f / fmaxf(sqrtf(red[0]), 1e-12f);
}

__global__ void ctx_init_kernel(const float* __restrict__ initMem, float* __restrict__ xctx,
                                float* __restrict__ xcm)
{
    const size_t i = (size_t)blockIdx.x * blockDim.x + threadIdx.x;
    const float val = rna_tf32(initMem[i & (CTX - 1)]);
    xctx[i] = val;
    if (i < BB * CTX) xcm[i] = val;
}

// ---- fast batch-32 linear ----
template<bool ELU>
__global__ void small_linear_fast(const float* __restrict__ in, const float* __restrict__ wT,
                                  const float* __restrict__ bias, float* __restrict__ out)
{
    const int b = blockIdx.y;
    const int jb = blockIdx.x * 32;
    const int tid = threadIdx.x;
    const int wid = tid >> 5, lane = tid & 31;
    __shared__ float x[CMD];
    for (int d = tid; d < CMD; d += 256) x[d] = in[b * CMD + d];
    __syncthreads();
    #pragma unroll
    for (int jj = 0; jj < 4; ++jj) {
        const int j = jb + wid * 4 + jj;
        const float* w = wT + (size_t)j * CMD;
        float acc = 0.f;
        #pragma unroll
        for (int i = 0; i < CMD / 32; ++i)
            acc = fmaf(x[lane + 32 * i], w[lane + 32 * i], acc);
        #pragma unroll
        for (int o = 16; o > 0; o >>= 1)
            acc += __shfl_down_sync(0xFFFFFFFFu, acc, o);
        if (lane == 0) {
            acc += bias[j];
            if (ELU) acc = (acc > 0.f) ? acc : expm1f(acc);
            out[b * CMD + j] = acc;
        }
    }
}

// ---- fast textual command ----
__global__ __launch_bounds__(1024)
void text_cmd_fast(const float* __restrict__ qcmd, const float* __restrict__ lstm,
                   const float* __restrict__ c2l_w, const float* __restrict__ c2l_b,
                   const int* __restrict__ qlen, float* __restrict__ cmd)
{
    const int b = blockIdx.x;
    const int tid = threadIdx.x;
    const int wid = tid >> 5, lane = tid & 31;
    __shared__ float e[CMD];
    __shared__ float att[LQL];
    __shared__ float red[128];
    __shared__ float smx, ssum;

    if (tid < CMD) e[tid] = qcmd[b * CMD + tid] * c2l_w[tid];
    __syncthreads();

    const int en = qlen[b];
    #pragma unroll
    for (int li = 0; li < 4; ++li) {
        const int l = wid + li * 32;
        const float* L = lstm + ((size_t)b * LQL + l) * CMD;
        float acc = 0.f;
        #pragma unroll
        for (int i = 0; i < CMD / 32; ++i)
            acc = fmaf(L[lane + 32 * i], e[lane + 32 * i], acc);
        #pragma unroll
        for (int o = 16; o > 0; o >>= 1)
            acc += __shfl_down_sync(0xFFFFFFFFu, acc, o);
        if (lane == 0) att[l] = (l >= en) ? NEGV : (acc + c2l_b[0]);
    }
    __syncthreads();

    if (tid < 128) red[tid] = att[tid];
    __syncthreads();
    for (int o = 64; o > 0; o >>= 1) {
        if (tid < o) red[tid] = fmaxf(red[tid], red[tid + o]);
        __syncthreads();
    }
    if (tid == 0) smx = red[0];
    __syncthreads();
    float ev = 0.f;
    if (tid < 128) { ev = expf(att[tid] - smx); red[tid] = ev; }
    __syncthreads();
    for (int o = 64; o > 0; o >>= 1) {
        if (tid < o) red[tid] += red[tid + o];
        __syncthreads();
    }
    if (tid == 0) ssum = red[0];
    __syncthreads();
    if (tid < 128) att[tid] = ev / ssum;
    __syncthreads();

    if (tid < CMD) {
        float acc = 0.f;
        const float* L = lstm + (size_t)b * LQL * CMD + tid;
        #pragma unroll 4
        for (int l = 0; l < LQL; ++l)
            acc = fmaf(att[l], L[(size_t)l * CMD], acc);
        cmd[b * CMD + tid] = acc;
    }
}

// masked row softmax (in place)
__global__ void attn_softmax_kernel(float* __restrict__ score, const int* __restrict__ entity_num)
{
    const int row = blockIdx.x;
    const int b = row >> 10;
    const int n = row & 1023;
    const int en = entity_num[b];
    if (n >= en) return;
    float* s = score + (size_t)row * NENT;
    const int tid = threadIdx.x;

    const int kc = ((en + 15) / 16) * 16;
    const int nblk = (kc + 255) >> 8;

    float v[4];
    float mx = -3.4e38f;
    #pragma unroll
    for (int j = 0; j < 4; j++) {
        const int m = tid + j * 256;
        float x = NEGV;
        if (j < nblk && m < en) x = s[m];
        v[j] = x;
        mx = fmaxf(mx, x);
    }
    __shared__ float red[256];
    red[tid] = mx; __syncthreads();
    for (int o = 128; o > 0; o >>= 1) { if (tid < o) red[tid] = fmaxf(red[tid], red[tid + o]); __syncthreads(); }
    mx = red[0];
    __syncthreads();

    float sum = 0.f;
    #pragma unroll
    for (int j = 0; j < 4; j++) { v[j] = expf(v[j] - mx); sum += v[j]; }
    red[tid] = sum; __syncthreads();
    for (int o = 128; o > 0; o >>= 1) { if (tid < o) red[tid] += red[tid + o]; __syncthreads(); }
    const float inv = 1.f / red[0];

    #pragma unroll
    for (int j = 0; j < 4; j++)
        if (j < nblk) s[tid + j * 256] = rna_tf32(v[j] * inv);
}

// ---------------- launch ----------------
template<typename T> static float* symaddr(T& sym) {
    void* p = nullptr;
    cudaGetSymbolAddress(&p, sym);
    return (float*)p;
}

extern "C" void kernel_launch(void* const* d_in, const int* in_sizes, int n_in,
                              void* d_out, int out_size)
{
    const float* images    = (const float*)d_in[0];
    const float* q_enc     = (const float*)d_in[1];
    const float* lstm      = (const float*)d_in[2];
    const int*   q_length  = (const int*)  d_in[3];
    const int*   ent_num   = (const int*)  d_in[4];
    const float* initKB_w  = (const float*)d_in[5];
    const float* initKB_b  = (const float*)d_in[6];
    const float* initMem   = (const float*)d_in[7];
    const float* qInput_w  = (const float*)d_in[8];
    const float* qInput_b  = (const float*)d_in[9];
    const float* qInput2_w = (const float*)d_in[10];
    const float* qInput2_b = (const float*)d_in[11];
    const float* c2l_w     = (const float*)d_in[12];
    const float* c2l_b     = (const float*)d_in[13];
    const float* pxl_w     = (const float*)d_in[14];
    const float* pxl_b     = (const float*)d_in[15];
    const float* pxc_w     = (const float*)d_in[16];
    const float* pxc_b     = (const float*)d_in[17];
    const float* qry_w     = (const float*)d_in[18];
    const float* qry_b     = (const float*)d_in[19];
    const float* key_w     = (const float*)d_in[20];
    const float* key_b     = (const float*)d_in[21];
    const float* val_w     = (const float*)d_in[22];
    const float* val_b     = (const float*)d_in[23];
    const float* pk_w      = (const float*)d_in[24];
    const float* pk_b      = (const float*)d_in[25];
    const float* pv_w      = (const float*)d_in[26];
    const float* pv_b      = (const float*)d_in[27];
    const float* mu_w      = (const float*)d_in[28];
    const float* mu_b      = (const float*)d_in[29];
    const float* ck_w      = (const float*)d_in[30];
    const float* ck_b      = (const float*)d_in[31];

    float* imgr  = symaddr(g_imgr);
    float* invn  = symaddr(g_invnorm);
    float* xloc  = symaddr(g_xloc);
    float* xctxA = symaddr(g_xctx0);
    float* xctxB = symaddr(g_xctx1);
    float* prjl  = symaddr(g_projloc);
    float* pp    = symaddr(g_pp);
    float* q     = symaddr(g_q);
    float* k     = symaddr(g_k);
    float* vT    = symaddr(g_vT);
    float* msg   = symaddr(g_msg);
    float* qL    = symaddr(g_qL);
    float* kL    = symaddr(g_kL);
    float* vL    = symaddr(g_vL);
    float* score = symaddr(g_score);
    float* qbase = symaddr(g_qbase);
    float* qcmd  = symaddr(g_qcmd);
    float* cmd   = symaddr(g_cmd);
    float* pkg   = symaddr(g_pkg);
    float* pvg   = symaddr(g_pvg);
    float* msgm  = symaddr(g_msgm);
    float* xcm   = symaddr(g_xcm);
    float* SvL   = symaddr(g_SvL);
    float* Spl   = symaddr(g_Spl);
    float* ppm   = symaddr(g_ppm);
    float* vmask = symaddr(g_vmask);
    float* wIKB  = symaddr(g_wT_ikb);
    float* wPXL  = symaddr(g_wT_pxl);
    float* wPXC  = symaddr(g_wT_pxc);
    float* wQRY  = symaddr(g_wT_qry);
    float* wKEY  = symaddr(g_wT_key);
    float* wVAL  = symaddr(g_wT_val);
    float* wMU   = symaddr(g_wT_mu);
    float* wCK   = symaddr(g_wT_ck);
    float* wQIN  = symaddr(g_wT_qin);
    float* wQIN2 = symaddr(g_wT_qin2);
    float* wPK   = symaddr(g_wT_pk);
    float* wPV   = symaddr(g_wT_pv);

    cudaFuncSetAttribute(gemm_mma<1,0,false,false,0,false>, cudaFuncAttributeMaxDynamicSharedMemorySize, SMEM_DYN);
    cudaFuncSetAttribute(gemm_mma<1,0,false,false,3,false>, cudaFuncAttributeMaxDynamicSharedMemorySize, SMEM_DYN);
    cudaFuncSetAttribute(gemm_mma<1,1,true ,false,0,false>, cudaFuncAttributeMaxDynamicSharedMemorySize, SMEM_DYN);
    cudaFuncSetAttribute(gemm_mma<1,3,true ,false,3,false>, cudaFuncAttributeMaxDynamicSharedMemorySize, SMEM_DYN);
    cudaFuncSetAttribute(gemm_mma<1,0,false,false,1,false>, cudaFuncAttributeMaxDynamicSharedMemorySize, SMEM_DYN);
    cudaFuncSetAttribute(gemm_mma<1,0,true ,false,2,false>, cudaFuncAttributeMaxDynamicSharedMemorySize, SMEM_DYN);
    cudaFuncSetAttribute(gemm_mma<2,0,true ,true ,3,false>, cudaFuncAttributeMaxDynamicSharedMemorySize, SMEM_DYN);
    cudaFuncSetAttribute(gemm_mma<2,2,true ,true ,3,false>, cudaFuncAttributeMaxDynamicSharedMemorySize, SMEM_DYN);
    cudaFuncSetAttribute(gemm_mma<2,2,true ,true ,3,true >, cudaFuncAttributeMaxDynamicSharedMemorySize, SMEM_DYN);
    cudaFuncSetAttribute(gemm_mma<2,0,true ,false,3,false>, cudaFuncAttributeMaxDynamicSharedMemorySize, SMEM_DYN);
    cudaFuncSetAttribute(gemm_mma<2,0,false,false,0,false>, cudaFuncAttributeMaxDynamicSharedMemorySize, SMEM_DYN);

    // ---- one-time side stream + events (created once; no device memory) ----
    static bool s_init = false;
    static cudaStream_t s1;
    static cudaEvent_t evStart, evW, ev0, evGate, evV, evCtx;
    if (!s_init) {
        cudaStreamCreateWithFlags(&s1, cudaStreamNonBlocking);
        cudaEventCreateWithFlags(&evStart, cudaEventDisableTiming);
        cudaEventCreateWithFlags(&evW,     cudaEventDisableTiming);
        cudaEventCreateWithFlags(&ev0,     cudaEventDisableTiming);
        cudaEventCreateWithFlags(&evGate,  cudaEventDisableTiming);
        cudaEventCreateWithFlags(&evV,     cudaEventDisableTiming);
        cudaEventCreateWithFlags(&evCtx,   cudaEventDisableTiming);
        s_init = true;
    }

    const float scale = 0.044194173824159216f;   // 1/sqrt(512)
    const dim3 tdim(32, 8);
    const dim3 gridMain(CTX / BNm, MROWS / BMm, 1);
    const dim3 gridScore(NENT / BNm, NENT / BMm, BB);
    const dim3 gridMsg(CTX / BNm, NENT / BMm, BB);
    const dim3 gridSL(CMD / 32, BB);

    // ---- fork: side stream does the small weight transposes + qbase ----
    cudaEventRecord(evStart, 0);
    cudaStreamWaitEvent(s1, evStart, 0);
    transpose_kernel<false><<<dim3(CMD/32, CMD/32, 1), tdim, 0, s1>>>(qInput_w, wQIN, CMD, CMD, 0, 0);
    small_linear_fast<true><<<gridSL, 256, 0, s1>>>(q_enc, wQIN, qInput_b, qbase);
    transpose_kernel<true><<<dim3(CTX/32, CTX/32, 1),   tdim, 0, s1>>>(pxl_w, wPXL, CTX,   CTX, 0, 0);
    transpose_kernel<true><<<dim3(CTX/32, CTX/32, 1),   tdim, 0, s1>>>(pxc_w, wPXC, CTX,   CTX, 0, 0);
    transpose_kernel<true><<<dim3(CTX/32, 3*CTX/32, 1), tdim, 0, s1>>>(qry_w, wQRY, 3*CTX, CTX, 0, 0);
    transpose_kernel<true><<<dim3(CTX/32, 3*CTX/32, 1), tdim, 0, s1>>>(key_w, wKEY, 3*CTX, CTX, 0, 0);
    transpose_kernel<true><<<dim3(CTX/32, 3*CTX/32, 1), tdim, 0, s1>>>(val_w, wVAL, 3*CTX, CTX, 0, 0);
    transpose_kernel<true><<<dim3(CTX/32, 2*CTX/32, 1), tdim, 0, s1>>>(mu_w,  wMU,  2*CTX, CTX, 0, 0);
    transpose_kernel<true><<<dim3(CTX/32, 2*CTX/32, 1), tdim, 0, s1>>>(ck_w,  wCK,  2*CTX, CTX, 0, 0);
    transpose_kernel<false><<<dim3(CMD/32, CMD/32, TT), tdim, 0, s1>>>(qInput2_w, wQIN2, CMD, CMD,
                                                                       (size_t)CMD*CMD, (size_t)CMD*CMD);
    transpose_kernel<false><<<dim3(CTX/32, CMD/32, 1), tdim, 0, s1>>>(pk_w, wPK, CMD, CTX, 0, 0);
    transpose_kernel<false><<<dim3(CTX/32, CMD/32, 1), tdim, 0, s1>>>(pv_w, wPV, CMD, CTX, 0, 0);
    cudaEventRecord(evW, s1);

    // ---- main stream: big one-time work overlapping the side stream ----
    transpose_kernel<true><<<dim3(CTX/32, DFEAT/32, 1), tdim>>>(initKB_w, wIKB, DFEAT, CTX, 0, 0);
    rownorm_round_kernel<<<MROWS, 256>>>(images, invn, imgr);
    ctx_init_kernel<<<(MROWS * CTX) / 256, 256>>>(initMem, xctxA, xcm);
    gemm_mma<1,1,true,false,0,false><<<gridMain, 256, SMEM_DYN>>>(
        imgr, nullptr, nullptr, wIKB, initKB_b, invn, nullptr, nullptr, xloc,
        DFEAT, DFEAT, DFEAT, CTX, 0, 0, 0, 1.f);
    cudaStreamWaitEvent(0, evW, 0);

    // ---- iteration-invariant hoists (main) ----
    gemm_mma<1,0,false,false,0,false><<<gridMain, 256, SMEM_DYN>>>(
        xloc, nullptr, nullptr, wPXL, pxl_b, nullptr, nullptr, nullptr, prjl,
        CTX, CTX, CTX, CTX, 0, 0, 0, 1.f);
    gemm_mma<1,0,false,false,3,false><<<gridMain, 256, SMEM_DYN>>>(
        xloc, nullptr, nullptr, wQRY, nullptr, nullptr, nullptr, ent_num, qL,
        CTX, CTX, 3*CTX, CTX, 0, 0, 0, 1.f);
    gemm_mma<1,0,false,false,3,false><<<gridMain, 256, SMEM_DYN>>>(
        xloc, nullptr, nullptr, wKEY, nullptr, nullptr, nullptr, ent_num, kL,
        CTX, CTX, 3*CTX, CTX, 0, 0, 0, 1.f);
    gemm_mma<1,0,false,false,0,false><<<gridMain, 256, SMEM_DYN>>>(
        xloc, nullptr, nullptr, wVAL, nullptr, nullptr, nullptr, nullptr, vL,
        CTX, CTX, 3*CTX, CTX, 0, 0, 0, 1.f);
    colmean_masked_kernel<<<BB, 512>>>(vL,   ent_num, SvL);
    colmean_masked_kernel<<<BB, 512>>>(prjl, ent_num, Spl);
    cudaEventRecord(ev0, 0);
    cudaStreamWaitEvent(s1, ev0, 0);     // s1 per-iter chain needs Spl/SvL

    float* xc = xctxA;
    float* xn = xctxB;
    for (int t = 0; t < TT; t++) {
        // ---- s1: cmd chain + analytic masked-v prep ----
        small_linear_fast<false><<<gridSL, 256, 0, s1>>>(qbase, wQIN2 + (size_t)t * CMD * CMD,
                                                         qInput2_b + (size_t)t * CMD, qcmd);
        text_cmd_fast<<<BB, 1024, 0, s1>>>(qcmd, lstm, c2l_w, c2l_b, q_length, cmd);
        small_linear_fast<false><<<gridSL, 256, 0, s1>>>(cmd, wPK, pk_b, pkg);
        small_linear_fast<false><<<gridSL, 256, 0, s1>>>(cmd, wPV, pv_b, pvg);
        cudaEventRecord(evGate, s1);
        ppm_kernel<<<dim3(CTX/32, BB), 256, 0, s1>>>(xcm, wPXC, pxc_b, Spl, ent_num, ppm);
        vmask_wide_kernel<<<dim3(CTX/32, BB), 256, 0, s1>>>(xcm, ppm, wVAL, val_b, pvg, SvL,
                                                            ent_num, vmask);

        // ---- main: pp, q (no gate deps), then gated k, v ----
        gemm_mma<1,3,true,false,3,false><<<gridMain, 256, SMEM_DYN>>>(
            xc, nullptr, nullptr, wPXC, pxc_b, prjl, nullptr, ent_num, pp,
            CTX, CTX, CTX, CTX, 0, 0, 0, 1.f);
        gemm_mma<2,0,true,true,3,false><<<gridMain, 256, SMEM_DYN>>>(
            xc, pp, nullptr, wQRY + CTX, qry_b, nullptr, qL, ent_num, q,
            2*CTX, 0, 3*CTX, CTX, 0, 0, 0, 1.f);
        cudaStreamWaitEvent(0, evGate, 0);
        gemm_mma<2,2,true,true,3,false><<<gridMain, 256, SMEM_DYN>>>(
            xc, pp, nullptr, wKEY + CTX, key_b, pkg, kL, ent_num, k,
            2*CTX, 0, 3*CTX, CTX, 0, 0, 0, 1.f);
        gemm_mma<2,2,true,true,3,true><<<gridMain, 256, SMEM_DYN>>>(
            xc, pp, nullptr, wVAL + CTX, val_b, pvg, vL, ent_num, vT,
            2*CTX, 0, 3*CTX, CTX, 0, 0, 0, 1.f);
        cudaEventRecord(evV, 0);

        // ---- s1: mean chain overlaps score/softmax/msg on main ----
        cudaStreamWaitEvent(s1, evV, 0);
        mean_vT_kernel<<<dim3(CTX / 8, BB), 256, 0, s1>>>(vT, ent_num, vmask, msgm);
        ctx_compute_kernel<<<BB, 256, 0, s1>>>(msgm, wMU, mu_b, ent_num, xcm);
        cudaEventRecord(evCtx, s1);

        // ---- main: attention + mu; bcast after mu (boundary-tile overwrite) ----
        gemm_mma<1,0,false,false,1,false><<<gridScore, 256, SMEM_DYN>>>(
            q, nullptr, nullptr, k, nullptr, nullptr, nullptr, ent_num, score,
            CTX, CTX, CTX, NENT,
            (size_t)NENT * CTX, (size_t)NENT * CTX, (size_t)NENT * NENT, scale);
        attn_softmax_kernel<<<MROWS, 256>>>(score, ent_num);
        gemm_mma<1,0,true,false,2,false><<<gridMsg, 256, SMEM_DYN>>>(
            score, nullptr, nullptr, vT, nullptr, nullptr, nullptr, ent_num, msg,
            NENT, NENT, NENT, CTX,
            (size_t)NENT * NENT, (size_t)CTX * NENT, (size_t)NENT * CTX, 1.f);
        gemm_mma<2,0,true,false,3,false><<<gridMain, 256, SMEM_DYN>>>(
            xc, msg, nullptr, wMU, mu_b, nullptr, nullptr, ent_num, xn,
            2*CTX, 0, 2*CTX, CTX, 0, 0, 0, 1.f);
        cudaStreamWaitEvent(0, evCtx, 0);
        bcast_rows_kernel<<<dim3(NENT / 128, BB), 256>>>(xcm, ent_num, xn);

        float* tmp = xc; xc = xn; xn = tmp;
    }

    // out = [x_loc | x_ctx] @ ck + b   (main; all s1 work joined via evCtx)
    gemm_mma<2,0,false,false,0,false><<<gridMain, 256, SMEM_DYN>>>(
        xloc, xc, nullptr, wCK, ck_b, nullptr, nullptr, nullptr, (float*)d_out,
        2*CTX, 0, 2*CTX, CTX, 0, 0, 0, 1.f);
}

// round 16
// speedup vs baseline: 1.3712x; 1.0287x over previous
#include <cuda_runtime.h>
#include <math.h>
#include <stdint.h>

#define BB     32
#define NENT   1024
#define LQL    128
#define DFEAT  2112
#define CTX    512
#define CMD    512
#define TT     4
#define MROWS  (BB*NENT)
#define NEGV   (-1e30f)

// ---- mma.sync GEMM tiling ----
#define BMm 128
#define BNm 128
#define BKm 32
#define STAGES 3
#define SROW 36
#define STAGE_F (2 * BMm * SROW)
#define TILE_F  (BMm * SROW)
#define SMEM_DYN (STAGES * STAGE_F * 4)
#define TSST 132

// ---- scratch ----
__device__ float g_imgr   [(size_t)MROWS*DFEAT];
__device__ float g_invnorm[MROWS];
__device__ float g_xloc   [(size_t)MROWS*CTX];
__device__ float g_xctx0  [(size_t)MROWS*CTX];
__device__ float g_xctx1  [(size_t)MROWS*CTX];
__device__ float g_projloc[(size_t)MROWS*CTX];
__device__ float g_pp     [(size_t)MROWS*CTX];
__device__ float g_q      [(size_t)MROWS*CTX];
__device__ float g_k      [(size_t)MROWS*CTX];
__device__ float g_vT     [(size_t)MROWS*CTX];   // [B][CTX][NENT]
__device__ float g_msg    [(size_t)MROWS*CTX];
__device__ float g_qL     [(size_t)MROWS*CTX];
__device__ float g_kL     [(size_t)MROWS*CTX];
__device__ float g_vL     [(size_t)MROWS*CTX];
__device__ float g_score  [(size_t)BB*NENT*NENT];
__device__ float g_qbase  [BB*CMD];
__device__ float g_qcmd   [BB*CMD];
__device__ float g_cmd    [BB*CMD];
__device__ float g_pkg    [TT*BB*CTX];
__device__ float g_pvg    [TT*BB*CTX];
__device__ float g_msgm   [BB*CTX];
__device__ float g_xcm    [BB*CTX];
__device__ float g_SvL    [BB*CTX];
__device__ float g_Spl    [BB*CTX];
__device__ float g_ppm    [BB*CTX];
__device__ float g_vmask  [BB*CTX];
__device__ float g_wT_ikb[(size_t)CTX*DFEAT];
__device__ float g_wT_pxl[(size_t)CTX*CTX];
__device__ float g_wT_pxc[(size_t)CTX*CTX];
__device__ float g_wT_qry[(size_t)CTX*3*CTX];
__device__ float g_wT_key[(size_t)CTX*3*CTX];
__device__ float g_wT_val[(size_t)CTX*3*CTX];
__device__ float g_wT_mu [(size_t)CTX*2*CTX];
__device__ float g_wT_ck [(size_t)CTX*2*CTX];
__device__ float g_wT_qin [(size_t)CMD*CMD];
__device__ float g_wT_qin2[(size_t)TT*CMD*CMD];
__device__ float g_wT_pk  [(size_t)CMD*CTX];
__device__ float g_wT_pv  [(size_t)CMD*CTX];

__device__ __forceinline__ float rna_tf32(float f) {
    uint32_t r; asm("cvt.rna.tf32.f32 %0, %1;" : "=r"(r) : "f"(f));
    return __uint_as_float(r);
}
__device__ __forceinline__ uint32_t smem_u32(const void* p) {
    uint32_t a;
    asm("{ .reg .u64 t; cvta.to.shared.u64 t, %1; cvt.u32.u64 %0, t; }" : "=r"(a) : "l"(p));
    return a;
}
__device__ __forceinline__ void cp_async16(uint32_t saddr, const void* gptr) {
    asm volatile("cp.async.cg.shared.global [%0], [%1], 16;" :: "r"(saddr), "l"(gptr));
}
#define CP_COMMIT() asm volatile("cp.async.commit_group;" ::: "memory")
#define CP_WAIT1()  asm volatile("cp.async.wait_group 1;" ::: "memory")

__device__ __forceinline__ void ldsm_x4(uint32_t addr, uint32_t& r0, uint32_t& r1,
                                        uint32_t& r2, uint32_t& r3)
{
    asm volatile("ldmatrix.sync.aligned.m8n8.x4.shared.b16 {%0,%1,%2,%3}, [%4];"
                 : "=r"(r0), "=r"(r1), "=r"(r2), "=r"(r3) : "r"(addr));
}

__device__ __forceinline__ void mma_m16n8k8(float* d,
    uint32_t a0, uint32_t a1, uint32_t a2, uint32_t a3,
    uint32_t b0, uint32_t b1)
{
    asm volatile(
        "mma.sync.aligned.m16n8k8.row.col.f32.tf32.tf32.f32 "
        "{%0,%1,%2,%3}, {%4,%5,%6,%7}, {%8,%9}, {%0,%1,%2,%3};"
        : "+f"(d[0]), "+f"(d[1]), "+f"(d[2]), "+f"(d[3])
        : "r"(a0), "r"(a1), "r"(a2), "r"(a3), "r"(b0), "r"(b1));
}

// ---------------- tensor-core GEMM via mma.sync (tf32) ----------------
// MASK 0: none
//      1 (score, z=batch): skip tile if m0>=en || n0>=en
//      2 (message, z=batch): skip tile if m0>=en; truncate K at ceil(en/BKm)
//      3 (row-masked, z=1, batch=m0>>10): skip tile if (m0&1023)>=en
// TRANSC: write C transposed per batch: C is [B][CTX][NENT]; batch = m0>>10.
template<int NSRC, int EPI, bool RND, bool ADD, int MASK, bool TRANSC>
__global__ __launch_bounds__(256, 2)
void gemm_mma(const float* __restrict__ A0, const float* __restrict__ A1,
              const float* __restrict__ A2, const float* __restrict__ Bt,
              const float* __restrict__ bias, const float* __restrict__ extra,
              const float* __restrict__ addC, const int* __restrict__ ennum,
              float* __restrict__ C,
              int K, int lda, int ldb, int ldc,
              size_t sA, size_t sB, size_t sC, float alpha)
{
    extern __shared__ float smem[];
    const uint32_t sbase = smem_u32(smem);

    const int tid = threadIdx.x;
    const int z = blockIdx.z;
    const int m0 = blockIdx.y * BMm;
    const int n0 = blockIdx.x * BNm;

    int Keff = K;
    if (MASK == 1 || MASK == 2) {
        const int en = ennum[z];
        if (m0 >= en) return;
        if (MASK == 1 && n0 >= en) return;
        if (MASK == 2) { const int kc = ((en + BKm - 1) / BKm) * BKm; Keff = kc < K ? kc : K; }
    } else if (MASK == 3) {
        const int en = ennum[m0 >> 10];
        if ((m0 & 1023) >= en) return;
    }

    const float* Abase = A0 + (size_t)z * sA;
    const float* Bbase = Bt + (size_t)z * sB;
    float* Cbase = C + (size_t)z * sC;

    const int wid = tid >> 5, lane = tid & 31;
    const int wm = (wid & 3) * 32;
    const int wn = (wid >> 2) * 64;
    const int gr = lane >> 2;
    const int gc = lane & 3;

    const int lr = lane & 7, lg = lane >> 3;
    const int arow  = wm + lr + (lg & 1) * 8;
    const int akoff = (lg >> 1) * 4;
    const int brow  = wn + lr + (lg >> 1) * 8;
    const int bkoff = (lg & 1) * 4;

    const int prow0 = tid >> 3;
    const int pkq   = (tid & 7) * 4;

    float acc[2][8][4] = {};
    const int NCC = Keff / BKm;

    auto loadChunk = [&](int c, int st) {
        const int k0 = c * BKm;
        const float* Ap; int al, ak;
        if (NSRC == 1) { Ap = Abase; al = lda; ak = k0; }
        else {
            const int src = k0 >> 9;
            Ap = (src == 0) ? A0 : ((src == 1) ? A1 : A2);
            al = CTX; ak = k0 & (CTX - 1);
        }
        const uint32_t sa = sbase + (uint32_t)(st * STAGE_F) * 4;
        const uint32_t sb = sa + (uint32_t)TILE_F * 4;
        #pragma unroll
        for (int t = 0; t < 4; ++t) {
            const int row = prow0 + t * 32;
            cp_async16(sa + (uint32_t)(row * SROW + pkq) * 4,
                       Ap + (size_t)(m0 + row) * al + ak + pkq);
            cp_async16(sb + (uint32_t)(row * SROW + pkq) * 4,
                       Bbase + (size_t)(n0 + row) * ldb + k0 + pkq);
        }
        CP_COMMIT();
    };

    auto compute = [&](int st) {
        const uint32_t SAu = sbase + (uint32_t)(st * STAGE_F) * 4;
        const uint32_t SBu = SAu + (uint32_t)TILE_F * 4;
        #pragma unroll
        for (int kk = 0; kk < BKm; kk += 8) {
            uint32_t b[8][2];
            #pragma unroll
            for (int ntp = 0; ntp < 4; ++ntp) {
                const uint32_t addr = SBu +
                    (uint32_t)(((brow + ntp * 16) * SROW) + kk + bkoff) * 4;
                ldsm_x4(addr, b[2*ntp][0], b[2*ntp][1], b[2*ntp+1][0], b[2*ntp+1][1]);
            }
            #pragma unroll
            for (int mt = 0; mt < 2; ++mt) {
                uint32_t a0, a1, a2, a3;
                const uint32_t addr = SAu +
                    (uint32_t)(((arow + mt * 16) * SROW) + kk + akoff) * 4;
                ldsm_x4(addr, a0, a1, a2, a3);
                #pragma unroll
                for (int nt = 0; nt < 8; ++nt)
                    mma_m16n8k8(acc[mt][nt], a0, a1, a2, a3, b[nt][0], b[nt][1]);
            }
        }
    };

    #pragma unroll
    for (int s = 0; s < STAGES - 1; ++s) {
        if (s < NCC) loadChunk(s, s);
        else CP_COMMIT();
    }
    {
        int st = 0;
        for (int c = 0; c < NCC; ++c) {
            CP_WAIT1();
            __syncthreads();
            const int nc = c + STAGES - 1;
            int nst = st + STAGES - 1; if (nst >= STAGES) nst -= STAGES;
            if (nc < NCC) loadChunk(nc, nst);
            else CP_COMMIT();
            compute(st);
            if (++st == STAGES) st = 0;
        }
    }

    if (TRANSC) __syncthreads();

    #pragma unroll
    for (int mt = 0; mt < 2; ++mt) {
        #pragma unroll
        for (int half = 0; half < 2; ++half) {
            const int m = m0 + wm + mt * 16 + gr + half * 8;
            const float rs = (EPI == 1) ? extra[m] : 0.f;
            #pragma unroll
            for (int nt = 0; nt < 8; ++nt) {
                const int n = n0 + wn + nt * 8 + gc * 2;
                float v0 = acc[mt][nt][half * 2 + 0];
                float v1 = acc[mt][nt][half * 2 + 1];
                if (ADD) {
                    const float2 ad = *reinterpret_cast<const float2*>(addC + (size_t)m * ldc + n);
                    v0 += ad.x; v1 += ad.y;
                }
                const float bb0 = bias ? bias[n]     : 0.f;
                const float bb1 = bias ? bias[n + 1] : 0.f;
                if (EPI == 0)      { v0 = v0 * alpha + bb0;  v1 = v1 * alpha + bb1; }
                else if (EPI == 1) { v0 = v0 * rs + bb0;     v1 = v1 * rs + bb1; }
                else if (EPI == 2) {
                    const float* g = extra + (size_t)(m >> 10) * CTX + n;
                    v0 = (v0 + bb0) * g[0];
                    v1 = (v1 + bb1) * g[1];
                } else {
                    const float* g = extra + (size_t)m * ldc + n;
                    v0 = (v0 + bb0) * g[0];
                    v1 = (v1 + bb1) * g[1];
                }
                if (RND) { v0 = rna_tf32(v0); v1 = rna_tf32(v1); }
                if (!TRANSC) {
                    *reinterpret_cast<float2*>(Cbase + (size_t)m * ldc + n) = make_float2(v0, v1);
                } else {
                    const int ml = wm + mt * 16 + gr + half * 8;
                    const int nl = wn + nt * 8 + gc * 2;
                    smem[(size_t)nl * TSST + ml] = v0;
                    smem[(size_t)(nl + 1) * TSST + ml] = v1;
                }
            }
        }
    }

    if (TRANSC) {
        __syncthreads();
        float* outT = C + (size_t)(m0 >> 10) * CTX * NENT;
        const int bofs = m0 & 1023;
        #pragma unroll
        for (int r = 0; r < 16; ++r) {
            const int row = wid * 16 + r;
            const float4 val = *reinterpret_cast<const float4*>(&smem[(size_t)row * TSST + lane * 4]);
            *reinterpret_cast<float4*>(outT + (size_t)(n0 + row) * NENT + bofs + lane * 4) = val;
        }
    }
}

// ---- one-time: column mean of src rows [NT, NENT) per batch (4-acc MLP) ----
__global__ __launch_bounds__(512)
void colmean_masked_kernel(const float* __restrict__ src, const int* __restrict__ ennum,
                           float* __restrict__ out)
{
    const int b = blockIdx.x;
    const int en = ennum[b];
    const int NT = ((en + 127) >> 7) << 7;
    if (NT >= NENT) return;
    const int d = threadIdx.x;
    const float* base = src + (size_t)b * NENT * CTX + d;
    float s0 = 0.f, s1 = 0.f, s2 = 0.f, s3 = 0.f;
    for (int m = NT; m < NENT; m += 4) {
        s0 += base[(size_t)(m + 0) * CTX];
        s1 += base[(size_t)(m + 1) * CTX];
        s2 += base[(size_t)(m + 2) * CTX];
        s3 += base[(size_t)(m + 3) * CTX];
    }
    out[b * CTX + d] = ((s0 + s1) + (s2 + s3)) * (1.f / (float)(NENT - NT));
}

// ---- wide: ppm[b][j] = (xcm[b]@pxc_row_j + pxc_b[j]) * Spl[b][j] ----
__global__ __launch_bounds__(256)
void ppm_kernel(const float* __restrict__ xcm, const float* __restrict__ wPXC,
                const float* __restrict__ pxc_b, const float* __restrict__ Spl,
                const int* __restrict__ ennum, float* __restrict__ ppm)
{
    const int b = blockIdx.y;
    const int en = ennum[b];
    if (((en + 127) >> 7 << 7) >= NENT) return;
    const int jb = blockIdx.x * 32;
    const int tid = threadIdx.x, wid = tid >> 5, lane = tid & 31;
    __shared__ float x[CTX];
    for (int d = tid; d < CTX; d += 256) x[d] = xcm[b * CTX + d];
    __syncthreads();
    #pragma unroll
    for (int jj = 0; jj < 4; ++jj) {
        const int j = jb + wid * 4 + jj;
        const float* w = wPXC + (size_t)j * CTX;
        float acc = 0.f;
        #pragma unroll
        for (int i = 0; i < CTX / 32; ++i)
            acc = fmaf(x[lane + 32 * i], w[lane + 32 * i], acc);
        #pragma unroll
        for (int o = 16; o > 0; o >>= 1) acc += __shfl_down_sync(0xFFFFFFFFu, acc, o);
        if (lane == 0) ppm[b * CTX + j] = (acc + pxc_b[j]) * Spl[b * CTX + j];
    }
}

// ---- wide: vmask[b][d] = ([xcm|ppm]@wVAL_row_d[CTX..3CTX) + val_b + SvL) * pvg ----
__global__ __launch_bounds__(256)
void vmask_wide_kernel(const float* __restrict__ xcm, const float* __restrict__ ppm,
                       const float* __restrict__ wVAL, const float* __restrict__ val_b,
                       const float* __restrict__ pvg, const float* __restrict__ SvL,
                       const int* __restrict__ ennum, float* __restrict__ vmask)
{
    const int b = blockIdx.y;
    const int en = ennum[b];
    if (((en + 127) >> 7 << 7) >= NENT) return;
    const int jb = blockIdx.x * 32;
    const int tid = threadIdx.x, wid = tid >> 5, lane = tid & 31;
    __shared__ float x[2 * CTX];
    for (int d = tid; d < CTX; d += 256) {
        x[d] = xcm[b * CTX + d];
        x[CTX + d] = ppm[b * CTX + d];
    }
    __syncthreads();
    #pragma unroll
    for (int jj = 0; jj < 4; ++jj) {
        const int d = jb + wid * 4 + jj;
        const float* w = wVAL + (size_t)d * (3 * CTX) + CTX;
        float acc = 0.f;
        #pragma unroll
        for (int i = 0; i < (2 * CTX) / 32; ++i)
            acc = fmaf(x[lane + 32 * i], w[lane + 32 * i], acc);
        #pragma unroll
        for (int o = 16; o > 0; o >>= 1) acc += __shfl_down_sync(0xFFFFFFFFu, acc, o);
        if (lane == 0)
            vmask[b * CTX + d] = (acc + val_b[d] + SvL[b * CTX + d]) * pvg[b * CTX + d];
    }
}

// ---- per-batch mean over vT rows: unrolled predicated sum + analytic tail ----
__global__ void mean_vT_kernel(const float* __restrict__ vT, const int* __restrict__ ennum,
                               const float* __restrict__ vmask, float* __restrict__ msgm)
{
    const int b = blockIdx.y;
    const int en = ennum[b];
    if (en >= NENT) return;
    const int NT = ((en + 127) >> 7) << 7;
    const int wid = threadIdx.x >> 5, lane = threadIdx.x & 31;
    const int d = blockIdx.x * 8 + wid;
    const float* row = vT + (size_t)b * CTX * NENT + (size_t)d * NENT;
    float s = 0.f;
    #pragma unroll
    for (int i = 0; i < NENT / 32; ++i) {
        float x = row[lane + 32 * i];
        if (lane + 32 * i >= NT) x = 0.f;
        s += x;
    }
    #pragma unroll
    for (int o = 16; o > 0; o >>= 1) s += __shfl_down_sync(0xFFFFFFFFu, s, o);
    if (lane == 0)
        msgm[b * CTX + d] = rna_tf32((s + (float)(NENT - NT) * vmask[b * CTX + d]) * (1.f / NENT));
}

// ---- masked-row x_ctx compute ----
__global__ __launch_bounds__(256)
void ctx_compute_kernel(const float* __restrict__ msgm, const float* __restrict__ wMU,
                        const float* __restrict__ mu_b, const int* __restrict__ ennum,
                        float* __restrict__ xcm)
{
    const int b = blockIdx.x;
    if (ennum[b] >= NENT) return;
    const int tid = threadIdx.x;
    const int wid = tid >> 5, lane = tid & 31;
    __shared__ float x[2 * CTX];
    __shared__ float y[CTX];
    for (int d = tid; d < CTX; d += 256) {
        x[d] = xcm[b * CTX + d];
        x[CTX + d] = msgm[b * CTX + d];
    }
    __syncthreads();
    for (int j = wid; j < CTX; j += 8) {
        const float* w = wMU + (size_t)j * (2 * CTX);
        float acc = 0.f;
        #pragma unroll
        for (int i = 0; i < (2 * CTX) / 32; ++i)
            acc = fmaf(x[lane + 32 * i], w[lane + 32 * i], acc);
        #pragma unroll
        for (int o = 16; o > 0; o >>= 1)
            acc += __shfl_down_sync(0xFFFFFFFFu, acc, o);
        if (lane == 0) y[j] = rna_tf32(acc + mu_b[j]);
    }
    __syncthreads();
    for (int d = tid; d < CTX; d += 256) xcm[b * CTX + d] = y[d];
}

// ---- broadcast xcm row into xn masked rows ----
__global__ __launch_bounds__(256)
void bcast_rows_kernel(const float* __restrict__ xcm, const int* __restrict__ ennum,
                       float* __restrict__ xn)
{
    const int b = blockIdx.y;
    const int en = ennum[b];
    const int r0 = blockIdx.x * 128;
    int start = r0 > en ? r0 : en;
    const int end = r0 + 128;
    if (start >= end) return;
    __shared__ float y[CTX];
    const int tid = threadIdx.x;
    for (int d = tid; d < CTX; d += 256) y[d] = xcm[b * CTX + d];
    __syncthreads();
    const int c4 = (tid & 127) * 4;
    const float4 val = *reinterpret_cast<const float4*>(&y[c4]);
    float* base = xn + (size_t)b * NENT * CTX;
    for (int m = start + (tid >> 7); m < end; m += 2)
        *reinterpret_cast<float4*>(base + (size_t)m * CTX + c4) = val;
}

// ---- transpose, optional tf32 round ----
template<bool RND>
__global__ void transpose_kernel(const float* __restrict__ in, float* __restrict__ out,
                                 int R, int C, size_t sIn, size_t sOut)
{
    __shared__ float tile[32][33];
    const int z = blockIdx.z;
    in  += (size_t)z * sIn;
    out += (size_t)z * sOut;
    const int r0 = blockIdx.y * 32, c0 = blockIdx.x * 32;
    #pragma unroll
    for (int i = threadIdx.y; i < 32; i += 8) {
        float x = in[(size_t)(r0 + i) * C + c0 + threadIdx.x];
        tile[i][threadIdx.x] = RND ? rna_tf32(x) : x;
    }
    __syncthreads();
    #pragma unroll
    for (int i = threadIdx.y; i < 32; i += 8)
        out[(size_t)(c0 + i) * R + r0 + threadIdx.x] = tile[threadIdx.x][i];
}

// ---- fused row inv-norm + tf32-rounded copy ----
__global__ void rownorm_round_kernel(const float* __restrict__ img, float* __restrict__ invn,
                                     float* __restrict__ imgr)
{
    const int m = blockIdx.x;
    const float4* r4 = reinterpret_cast<const float4*>(img + (size_t)m * DFEAT);
    float4* o4 = reinterpret_cast<float4*>(imgr + (size_t)m * DFEAT);
    const int tid = threadIdx.x;
    float s = 0.f;
    for (int i = tid; i < DFEAT / 4; i += 256) {
        float4 u = r4[i];
        s = fmaf(u.x, u.x, s); s = fmaf(u.y, u.y, s);
        s = fmaf(u.z, u.z, s); s = fmaf(u.w, u.w, s);
        u.x = rna_tf32(u.x); u.y = rna_tf32(u.y);
        u.z = rna_tf32(u.z); u.w = rna_tf32(u.w);
        o4[i] = u;
    }
    __shared__ float red[256];
    red[tid] = s; __syncthreads();
    for (int o = 128; o > 0; o >>= 1) { if (tid < o) red[tid] += red[tid + o]; __syncthreads(); }
    if (tid == 0) invn[m] = 1.f / fmaxf(sqrtf(red[0]), 1e-12f);
}

__global__ void ctx_init_kernel(const float* __restrict__ initMem, float* __restrict__ xctx,
                                float* __restrict__ xcm)
{
    const size_t i = (size_t)blockIdx.x * blockDim.x + threadIdx.x;
    const float val = rna_tf32(initMem[i & (CTX - 1)]);
    xctx[i] = val;
    if (i < BB * CTX) xcm[i] = val;
}

// ---- fast batch-32 linear ----
template<bool ELU>
__global__ void small_linear_fast(const float* __restrict__ in, const float* __restrict__ wT,
                                  const float* __restrict__ bias, float* __restrict__ out)
{
    const int b = blockIdx.y;
    const int jb = blockIdx.x * 32;
    const int tid = threadIdx.x;
    const int wid = tid >> 5, lane = tid & 31;
    __shared__ float x[CMD];
    for (int d = tid; d < CMD; d += 256) x[d] = in[b * CMD + d];
    __syncthreads();
    #pragma unroll
    for (int jj = 0; jj < 4; ++jj) {
        const int j = jb + wid * 4 + jj;
        const float* w = wT + (size_t)j * CMD;
        float acc = 0.f;
        #pragma unroll
        for (int i = 0; i < CMD / 32; ++i)
            acc = fmaf(x[lane + 32 * i], w[lane + 32 * i], acc);
        #pragma unroll
        for (int o = 16; o > 0; o >>= 1)
            acc += __shfl_down_sync(0xFFFFFFFFu, acc, o);
        if (lane == 0) {
            acc += bias[j];
            if (ELU) acc = (acc > 0.f) ? acc : expm1f(acc);
            out[b * CMD + j] = acc;
        }
    }
}

// ---- fast textual command ----
__global__ __launch_bounds__(1024)
void text_cmd_fast(const float* __restrict__ qcmd, const float* __restrict__ lstm,
                   const float* __restrict__ c2l_w, const float* __restrict__ c2l_b,
                   const int* __restrict__ qlen, float* __restrict__ cmd)
{
    const int b = blockIdx.x;
    const int tid = threadIdx.x;
    const int wid = tid >> 5, lane = tid & 31;
    __shared__ float e[CMD];
    __shared__ float att[LQL];
    __shared__ float red[128];
    __shared__ float smx, ssum;

    if (tid < CMD) e[tid] = qcmd[b * CMD + tid] * c2l_w[tid];
    __syncthreads();

    const int en = qlen[b];
    #pragma unroll
    for (int li = 0; li < 4; ++li) {
        const int l = wid + li * 32;
        const float* L = lstm + ((size_t)b * LQL + l) * CMD;
        float acc = 0.f;
        #pragma unroll
        for (int i = 0; i < CMD / 32; ++i)
            acc = fmaf(L[lane + 32 * i], e[lane + 32 * i], acc);
        #pragma unroll
        for (int o = 16; o > 0; o >>= 1)
            acc += __shfl_down_sync(0xFFFFFFFFu, acc, o);
        if (lane == 0) att[l] = (l >= en) ? NEGV : (acc + c2l_b[0]);
    }
    __syncthreads();

    if (tid < 128) red[tid] = att[tid];
    __syncthreads();
    for (int o = 64; o > 0; o >>= 1) {
        if (tid < o) red[tid] = fmaxf(red[tid], red[tid + o]);
        __syncthreads();
    }
    if (tid == 0) smx = red[0];
    __syncthreads();
    float ev = 0.f;
    if (tid < 128) { ev = expf(att[tid] - smx); red[tid] = ev; }
    __syncthreads();
    for (int o = 64; o > 0; o >>= 1) {
        if (tid < o) red[tid] += red[tid + o];
        __syncthreads();
    }
    if (tid == 0) ssum = red[0];
    __syncthreads();
    if (tid < 128) att[tid] = ev / ssum;
    __syncthreads();

    if (tid < CMD) {
        float acc = 0.f;
        const float* L = lstm + (size_t)b * LQL * CMD + tid;
        #pragma unroll 4
        for (int l = 0; l < LQL; ++l)
            acc = fmaf(att[l], L[(size_t)l * CMD], acc);
        cmd[b * CMD + tid] = acc;
    }
}

// masked row softmax (in place)
__global__ void attn_softmax_kernel(float* __restrict__ score, const int* __restrict__ entity_num)
{
    const int row = blockIdx.x;
    const int b = row >> 10;
    const int n = row & 1023;
    const int en = entity_num[b];
    if (n >= en) return;
    float* s = score + (size_t)row * NENT;
    const int tid = threadIdx.x;

    const int kc = ((en + 15) / 16) * 16;
    const int nblk = (kc + 255) >> 8;

    float v[4];
    float mx = -3.4e38f;
    #pragma unroll
    for (int j = 0; j < 4; j++) {
        const int m = tid + j * 256;
        float x = NEGV;
        if (j < nblk && m < en) x = s[m];
        v[j] = x;
        mx = fmaxf(mx, x);
    }
    __shared__ float red[256];
    red[tid] = mx; __syncthreads();
    for (int o = 128; o > 0; o >>= 1) { if (tid < o) red[tid] = fmaxf(red[tid], red[tid + o]); __syncthreads(); }
    mx = red[0];
    __syncthreads();

    float sum = 0.f;
    #pragma unroll
    for (int j = 0; j < 4; j++) { v[j] = expf(v[j] - mx); sum += v[j]; }
    red[tid] = sum; __syncthreads();
    for (int o = 128; o > 0; o >>= 1) { if (tid < o) red[tid] += red[tid + o]; __syncthreads(); }
    const float inv = 1.f / red[0];

    #pragma unroll
    for (int j = 0; j < 4; j++)
        if (j < nblk) s[tid + j * 256] = rna_tf32(v[j] * inv);
}

// ---------------- launch ----------------
template<typename T> static float* symaddr(T& sym) {
    void* p = nullptr;
    cudaGetSymbolAddress(&p, sym);
    return (float*)p;
}

extern "C" void kernel_launch(void* const* d_in, const int* in_sizes, int n_in,
                              void* d_out, int out_size)
{
    const float* images    = (const float*)d_in[0];
    const float* q_enc     = (const float*)d_in[1];
    const float* lstm      = (const float*)d_in[2];
    const int*   q_length  = (const int*)  d_in[3];
    const int*   ent_num   = (const int*)  d_in[4];
    const float* initKB_w  = (const float*)d_in[5];
    const float* initKB_b  = (const float*)d_in[6];
    const float* initMem   = (const float*)d_in[7];
    const float* qInput_w  = (const float*)d_in[8];
    const float* qInput_b  = (const float*)d_in[9];
    const float* qInput2_w = (const float*)d_in[10];
    const float* qInput2_b = (const float*)d_in[11];
    const float* c2l_w     = (const float*)d_in[12];
    const float* c2l_b     = (const float*)d_in[13];
    const float* pxl_w     = (const float*)d_in[14];
    const float* pxl_b     = (const float*)d_in[15];
    const float* pxc_w     = (const float*)d_in[16];
    const float* pxc_b     = (const float*)d_in[17];
    const float* qry_w     = (const float*)d_in[18];
    const float* qry_b     = (const float*)d_in[19];
    const float* key_w     = (const float*)d_in[20];
    const float* key_b     = (const float*)d_in[21];
    const float* val_w     = (const float*)d_in[22];
    const float* val_b     = (const float*)d_in[23];
    const float* pk_w      = (const float*)d_in[24];
    const float* pk_b      = (const float*)d_in[25];
    const float* pv_w      = (const float*)d_in[26];
    const float* pv_b      = (const float*)d_in[27];
    const float* mu_w      = (const float*)d_in[28];
    const float* mu_b      = (const float*)d_in[29];
    const float* ck_w      = (const float*)d_in[30];
    const float* ck_b      = (const float*)d_in[31];

    float* imgr  = symaddr(g_imgr);
    float* invn  = symaddr(g_invnorm);
    float* xloc  = symaddr(g_xloc);
    float* xctxA = symaddr(g_xctx0);
    float* xctxB = symaddr(g_xctx1);
    float* prjl  = symaddr(g_projloc);
    float* pp    = symaddr(g_pp);
    float* q     = symaddr(g_q);
    float* k     = symaddr(g_k);
    float* vT    = symaddr(g_vT);
    float* msg   = symaddr(g_msg);
    float* qL    = symaddr(g_qL);
    float* kL    = symaddr(g_kL);
    float* vL    = symaddr(g_vL);
    float* score = symaddr(g_score);
    float* qbase = symaddr(g_qbase);
    float* qcmd  = symaddr(g_qcmd);
    float* cmd   = symaddr(g_cmd);
    float* pkg   = symaddr(g_pkg);
    float* pvg   = symaddr(g_pvg);
    float* msgm  = symaddr(g_msgm);
    float* xcm   = symaddr(g_xcm);
    float* SvL   = symaddr(g_SvL);
    float* Spl   = symaddr(g_Spl);
    float* ppm   = symaddr(g_ppm);
    float* vmask = symaddr(g_vmask);
    float* wIKB  = symaddr(g_wT_ikb);
    float* wPXL  = symaddr(g_wT_pxl);
    float* wPXC  = symaddr(g_wT_pxc);
    float* wQRY  = symaddr(g_wT_qry);
    float* wKEY  = symaddr(g_wT_key);
    float* wVAL  = symaddr(g_wT_val);
    float* wMU   = symaddr(g_wT_mu);
    float* wCK   = symaddr(g_wT_ck);
    float* wQIN  = symaddr(g_wT_qin);
    float* wQIN2 = symaddr(g_wT_qin2);
    float* wPK   = symaddr(g_wT_pk);
    float* wPV   = symaddr(g_wT_pv);

    cudaFuncSetAttribute(gemm_mma<1,0,false,false,0,false>, cudaFuncAttributeMaxDynamicSharedMemorySize, SMEM_DYN);
    cudaFuncSetAttribute(gemm_mma<1,0,false,false,3,false>, cudaFuncAttributeMaxDynamicSharedMemorySize, SMEM_DYN);
    cudaFuncSetAttribute(gemm_mma<1,1,true ,false,0,false>, cudaFuncAttributeMaxDynamicSharedMemorySize, SMEM_DYN);
    cudaFuncSetAttribute(gemm_mma<1,3,true ,false,3,false>, cudaFuncAttributeMaxDynamicSharedMemorySize, SMEM_DYN);
    cudaFuncSetAttribute(gemm_mma<1,0,false,false,1,false>, cudaFuncAttributeMaxDynamicSharedMemorySize, SMEM_DYN);
    cudaFuncSetAttribute(gemm_mma<1,0,true ,false,2,false>, cudaFuncAttributeMaxDynamicSharedMemorySize, SMEM_DYN);
    cudaFuncSetAttribute(gemm_mma<2,0,true ,true ,3,false>, cudaFuncAttributeMaxDynamicSharedMemorySize, SMEM_DYN);
    cudaFuncSetAttribute(gemm_mma<2,2,true ,true ,3,false>, cudaFuncAttributeMaxDynamicSharedMemorySize, SMEM_DYN);
    cudaFuncSetAttribute(gemm_mma<2,2,true ,true ,3,true >, cudaFuncAttributeMaxDynamicSharedMemorySize, SMEM_DYN);
    cudaFuncSetAttribute(gemm_mma<2,0,true ,false,3,false>, cudaFuncAttributeMaxDynamicSharedMemorySize, SMEM_DYN);
    cudaFuncSetAttribute(gemm_mma<2,0,false,false,0,false>, cudaFuncAttributeMaxDynamicSharedMemorySize, SMEM_DYN);

    // ---- one-time side stream + events ----
    static bool s_init = false;
    static cudaStream_t s1;
    static cudaEvent_t evStart, evW, evCmd, ev0, evPP, evV, evCtx;
    if (!s_init) {
        cudaStreamCreateWithFlags(&s1, cudaStreamNonBlocking);
        cudaEventCreateWithFlags(&evStart, cudaEventDisableTiming);
        cudaEventCreateWithFlags(&evW,     cudaEventDisableTiming);
        cudaEventCreateWithFlags(&evCmd,   cudaEventDisableTiming);
        cudaEventCreateWithFlags(&ev0,     cudaEventDisableTiming);
        cudaEventCreateWithFlags(&evPP,    cudaEventDisableTiming);
        cudaEventCreateWithFlags(&evV,     cudaEventDisableTiming);
        cudaEventCreateWithFlags(&evCtx,   cudaEventDisableTiming);
        s_init = true;
    }

    const float scale = 0.044194173824159216f;   // 1/sqrt(512)
    const dim3 tdim(32, 8);
    const dim3 gridMain(CTX / BNm, MROWS / BMm, 1);
    const dim3 gridScore(NENT / BNm, NENT / BMm, BB);
    const dim3 gridMsg(CTX / BNm, NENT / BMm, BB);
    const dim3 gridSL(CMD / 32, BB);

    // ---- fork: s1 does tf32 weight transposes (evW), then ALL cmd chains ----
    cudaEventRecord(evStart, 0);
    cudaStreamWaitEvent(s1, evStart, 0);
    transpose_kernel<true><<<dim3(CTX/32, CTX/32, 1),   tdim, 0, s1>>>(pxl_w, wPXL, CTX,   CTX, 0, 0);
    transpose_kernel<true><<<dim3(CTX/32, CTX/32, 1),   tdim, 0, s1>>>(pxc_w, wPXC, CTX,   CTX, 0, 0);
    transpose_kernel<true><<<dim3(CTX/32, 3*CTX/32, 1), tdim, 0, s1>>>(qry_w, wQRY, 3*CTX, CTX, 0, 0);
    transpose_kernel<true><<<dim3(CTX/32, 3*CTX/32, 1), tdim, 0, s1>>>(key_w, wKEY, 3*CTX, CTX, 0, 0);
    transpose_kernel<true><<<dim3(CTX/32, 3*CTX/32, 1), tdim, 0, s1>>>(val_w, wVAL, 3*CTX, CTX, 0, 0);
    transpose_kernel<true><<<dim3(CTX/32, 2*CTX/32, 1), tdim, 0, s1>>>(mu_w,  wMU,  2*CTX, CTX, 0, 0);
    transpose_kernel<true><<<dim3(CTX/32, 2*CTX/32, 1), tdim, 0, s1>>>(ck_w,  wCK,  2*CTX, CTX, 0, 0);
    cudaEventRecord(evW, s1);
    // cmd chains for all iterations (inputs are constants)
    transpose_kernel<false><<<dim3(CMD/32, CMD/32, 1), tdim, 0, s1>>>(qInput_w, wQIN, CMD, CMD, 0, 0);
    small_linear_fast<true><<<gridSL, 256, 0, s1>>>(q_enc, wQIN, qInput_b, qbase);
    transpose_kernel<false><<<dim3(CMD/32, CMD/32, TT), tdim, 0, s1>>>(qInput2_w, wQIN2, CMD, CMD,
                                                                       (size_t)CMD*CMD, (size_t)CMD*CMD);
    transpose_kernel<false><<<dim3(CTX/32, CMD/32, 1), tdim, 0, s1>>>(pk_w, wPK, CMD, CTX, 0, 0);
    transpose_kernel<false><<<dim3(CTX/32, CMD/32, 1), tdim, 0, s1>>>(pv_w, wPV, CMD, CTX, 0, 0);
    for (int t = 0; t < TT; t++) {
        small_linear_fast<false><<<gridSL, 256, 0, s1>>>(qbase, wQIN2 + (size_t)t * CMD * CMD,
                                                         qInput2_b + (size_t)t * CMD, qcmd);
        text_cmd_fast<<<BB, 1024, 0, s1>>>(qcmd, lstm, c2l_w, c2l_b, q_length, cmd);
        small_linear_fast<false><<<gridSL, 256, 0, s1>>>(cmd, wPK, pk_b, pkg + (size_t)t * BB * CTX);
        small_linear_fast<false><<<gridSL, 256, 0, s1>>>(cmd, wPV, pv_b, pvg + (size_t)t * BB * CTX);
    }
    cudaEventRecord(evCmd, s1);

    // ---- main: big one-time work overlapping s1 ----
    transpose_kernel<true><<<dim3(CTX/32, DFEAT/32, 1), tdim>>>(initKB_w, wIKB, DFEAT, CTX, 0, 0);
    rownorm_round_kernel<<<MROWS, 256>>>(images, invn, imgr);
    ctx_init_kernel<<<(MROWS * CTX) / 256, 256>>>(initMem, xctxA, xcm);
    gemm_mma<1,1,true,false,0,false><<<gridMain, 256, SMEM_DYN>>>(
        imgr, nullptr, nullptr, wIKB, initKB_b, invn, nullptr, nullptr, xloc,
        DFEAT, DFEAT, DFEAT, CTX, 0, 0, 0, 1.f);
    cudaStreamWaitEvent(0, evW, 0);

    // ---- iteration-invariant hoists (main) ----
    gemm_mma<1,0,false,false,0,false><<<gridMain, 256, SMEM_DYN>>>(
        xloc, nullptr, nullptr, wPXL, pxl_b, nullptr, nullptr, nullptr, prjl,
        CTX, CTX, CTX, CTX, 0, 0, 0, 1.f);
    gemm_mma<1,0,false,false,3,false><<<gridMain, 256, SMEM_DYN>>>(
        xloc, nullptr, nullptr, wQRY, nullptr, nullptr, nullptr, ent_num, qL,
        CTX, CTX, 3*CTX, CTX, 0, 0, 0, 1.f);
    gemm_mma<1,0,false,false,3,false><<<gridMain, 256, SMEM_DYN>>>(
        xloc, nullptr, nullptr, wKEY, nullptr, nullptr, nullptr, ent_num, kL,
        CTX, CTX, 3*CTX, CTX, 0, 0, 0, 1.f);
    gemm_mma<1,0,false,false,0,false><<<gridMain, 256, SMEM_DYN>>>(
        xloc, nullptr, nullptr, wVAL, nullptr, nullptr, nullptr, nullptr, vL,
        CTX, CTX, 3*CTX, CTX, 0, 0, 0, 1.f);
    colmean_masked_kernel<<<BB, 512>>>(vL,   ent_num, SvL);
    colmean_masked_kernel<<<BB, 512>>>(prjl, ent_num, Spl);
    cudaEventRecord(ev0, 0);
    cudaStreamWaitEvent(s1, ev0, 0);      // s1 per-iter chain needs Spl/SvL
    cudaStreamWaitEvent(0, evCmd, 0);     // main k/v need pkg/pvg

    float* xc = xctxA;
    float* xn = xctxB;
    for (int t = 0; t < TT; t++) {
        const float* pkg_t = pkg + (size_t)t * BB * CTX;
        const float* pvg_t = pvg + (size_t)t * BB * CTX;

        // ---- s1: analytic masked-v prep (reads xcm from prev ctx_compute) ----
        ppm_kernel<<<dim3(CTX/32, BB), 256, 0, s1>>>(xcm, wPXC, pxc_b, Spl, ent_num, ppm);
        vmask_wide_kernel<<<dim3(CTX/32, BB), 256, 0, s1>>>(xcm, ppm, wVAL, val_b, pvg_t,
                                                            SvL, ent_num, vmask);

        // ---- main: pp (record evPP), then q, k ----
        gemm_mma<1,3,true,false,3,false><<<gridMain, 256, SMEM_DYN>>>(
            xc, nullptr, nullptr, wPXC, pxc_b, prjl, nullptr, ent_num, pp,
            CTX, CTX, CTX, CTX, 0, 0, 0, 1.f);
        cudaEventRecord(evPP, 0);
        gemm_mma<2,0,true,true,3,false><<<gridMain, 256, SMEM_DYN>>>(
            xc, pp, nullptr, wQRY + CTX, qry_b, nullptr, qL, ent_num, q,
            2*CTX, 0, 3*CTX, CTX, 0, 0, 0, 1.f);
        gemm_mma<2,2,true,true,3,false><<<gridMain, 256, SMEM_DYN>>>(
            xc, pp, nullptr, wKEY + CTX, key_b, pkg_t, kL, ent_num, k,
            2*CTX, 0, 3*CTX, CTX, 0, 0, 0, 1.f);

        // ---- s1: v GEMM (after pp) + mean chain, overlapping score/softmax ----
        cudaStreamWaitEvent(s1, evPP, 0);
        gemm_mma<2,2,true,true,3,true><<<gridMain, 256, SMEM_DYN, s1>>>(
            xc, pp, nullptr, wVAL + CTX, val_b, pvg_t, vL, ent_num, vT,
            2*CTX, 0, 3*CTX, CTX, 0, 0, 0, 1.f);
        cudaEventRecord(evV, s1);
        mean_vT_kernel<<<dim3(CTX / 8, BB), 256, 0, s1>>>(vT, ent_num, vmask, msgm);
        ctx_compute_kernel<<<BB, 256, 0, s1>>>(msgm, wMU, mu_b, ent_num, xcm);
        cudaEventRecord(evCtx, s1);

        // ---- main: attention; msg gated on v; mu; gated bcast ----
        gemm_mma<1,0,false,false,1,false><<<gridScore, 256, SMEM_DYN>>>(
            q, nullptr, nullptr, k, nullptr, nullptr, nullptr, ent_num, score,
            CTX, CTX, CTX, NENT,
            (size_t)NENT * CTX, (size_t)NENT * CTX, (size_t)NENT * NENT, scale);
        attn_softmax_kernel<<<MROWS, 256>>>(score, ent_num);
        cudaStreamWaitEvent(0, evV, 0);
        gemm_mma<1,0,true,false,2,false><<<gridMsg, 256, SMEM_DYN>>>(
            score, nullptr, nullptr, vT, nullptr, nullptr, nullptr, ent_num, msg,
            NENT, NENT, NENT, CTX,
            (size_t)NENT * NENT, (size_t)CTX * NENT, (size_t)NENT * CTX, 1.f);
        gemm_mma<2,0,true,false,3,false><<<gridMain, 256, SMEM_DYN>>>(
            xc, msg, nullptr, wMU, mu_b, nullptr, nullptr, ent_num, xn,
            2*CTX, 0, 2*CTX, CTX, 0, 0, 0, 1.f);
        cudaStreamWaitEvent(0, evCtx, 0);
        bcast_rows_kernel<<<dim3(NENT / 128, BB), 256>>>(xcm, ent_num, xn);

        float* tmp = xc; xc = xn; xn = tmp;
    }

    // out = [x_loc | x_ctx] @ ck + b   (main; s1 joined via evCtx)
    gemm_mma<2,0,false,false,0,false><<<gridMain, 256, SMEM_DYN>>>(
        xloc, xc, nullptr, wCK, ck_b, nullptr, nullptr, nullptr, (float*)d_out,
        2*CTX, 0, 2*CTX, CTX, 0, 0, 0, 1.f);
}

// round 17
// speedup vs baseline: 1.4038x; 1.0237x over previous
#include <cuda_runtime.h>
#include <math.h>
#include <stdint.h>

#define BB     32
#define NENT   1024
#define LQL    128
#define DFEAT  2112
#define CTX    512
#define CMD    512
#define TT     4
#define MROWS  (BB*NENT)
#define NEGV   (-1e30f)

// ---- mma.sync GEMM tiling ----
#define BMm 128
#define BNm 128
#define BKm 32
#define STAGES 3
#define SROW 36
#define STAGE_F (2 * BMm * SROW)
#define TILE_F  (BMm * SROW)
#define SMEM_DYN (STAGES * STAGE_F * 4)
#define TSST 132

// ---- scratch ----
__device__ float g_imgr   [(size_t)MROWS*DFEAT];
__device__ float g_invnorm[MROWS];
__device__ float g_xloc   [(size_t)MROWS*CTX];
__device__ float g_xctx0  [(size_t)MROWS*CTX];
__device__ float g_xctx1  [(size_t)MROWS*CTX];
__device__ float g_projloc[(size_t)MROWS*CTX];
__device__ float g_pp     [(size_t)MROWS*CTX];
__device__ float g_qk     [(size_t)MROWS*2*CTX];   // [M][ q(512) | k(512) ]
__device__ float g_qkL    [(size_t)MROWS*2*CTX];   // hoisted xloc partial for q|k
__device__ float g_ckL    [(size_t)MROWS*CTX];     // hoisted xloc half of ck
__device__ float g_vT     [(size_t)MROWS*CTX];     // [B][CTX][NENT]
__device__ float g_msg    [(size_t)MROWS*CTX];
__device__ float g_vL     [(size_t)MROWS*CTX];
__device__ float g_score  [(size_t)BB*NENT*NENT];
__device__ float g_qbase  [BB*CMD];
__device__ float g_qcmd   [BB*CMD];
__device__ float g_cmd    [BB*CMD];
__device__ float g_pkg    [TT*BB*CTX];
__device__ float g_pvg    [TT*BB*CTX];
__device__ float g_msgm   [BB*CTX];
__device__ float g_xcm    [BB*CTX];
__device__ float g_SvL    [BB*CTX];
__device__ float g_Spl    [BB*CTX];
__device__ float g_ppm    [BB*CTX];
__device__ float g_vmask  [BB*CTX];
__device__ float g_qkbias [2*CTX];
__device__ float g_wT_ikb[(size_t)CTX*DFEAT];
__device__ float g_wT_pxl[(size_t)CTX*CTX];
__device__ float g_wT_pxc[(size_t)CTX*CTX];
__device__ float g_wT_qk [(size_t)2*CTX*2*CTX];   // [n:q|k][k=512..1535 of W]
__device__ float g_wT_qkl[(size_t)2*CTX*CTX];     // [n:q|k][k=0..511 of W]
__device__ float g_wT_val[(size_t)CTX*3*CTX];
__device__ float g_wT_mu [(size_t)CTX*2*CTX];
__device__ float g_wT_ck [(size_t)CTX*2*CTX];
__device__ float g_wT_qin [(size_t)CMD*CMD];
__device__ float g_wT_qin2[(size_t)TT*CMD*CMD];
__device__ float g_wT_pk  [(size_t)CMD*CTX];
__device__ float g_wT_pv  [(size_t)CMD*CTX];

__device__ __forceinline__ float rna_tf32(float f) {
    uint32_t r; asm("cvt.rna.tf32.f32 %0, %1;" : "=r"(r) : "f"(f));
    return __uint_as_float(r);
}
__device__ __forceinline__ uint32_t smem_u32(const void* p) {
    uint32_t a;
    asm("{ .reg .u64 t; cvta.to.shared.u64 t, %1; cvt.u32.u64 %0, t; }" : "=r"(a) : "l"(p));
    return a;
}
__device__ __forceinline__ void cp_async16(uint32_t saddr, const void* gptr) {
    asm volatile("cp.async.cg.shared.global [%0], [%1], 16;" :: "r"(saddr), "l"(gptr));
}
#define CP_COMMIT() asm volatile("cp.async.commit_group;" ::: "memory")
#define CP_WAIT1()  asm volatile("cp.async.wait_group 1;" ::: "memory")

__device__ __forceinline__ void ldsm_x4(uint32_t addr, uint32_t& r0, uint32_t& r1,
                                        uint32_t& r2, uint32_t& r3)
{
    asm volatile("ldmatrix.sync.aligned.m8n8.x4.shared.b16 {%0,%1,%2,%3}, [%4];"
                 : "=r"(r0), "=r"(r1), "=r"(r2), "=r"(r3) : "r"(addr));
}

__device__ __forceinline__ void mma_m16n8k8(float* d,
    uint32_t a0, uint32_t a1, uint32_t a2, uint32_t a3,
    uint32_t b0, uint32_t b1)
{
    asm volatile(
        "mma.sync.aligned.m16n8k8.row.col.f32.tf32.tf32.f32 "
        "{%0,%1,%2,%3}, {%4,%5,%6,%7}, {%8,%9}, {%0,%1,%2,%3};"
        : "+f"(d[0]), "+f"(d[1]), "+f"(d[2]), "+f"(d[3])
        : "r"(a0), "r"(a1), "r"(a2), "r"(a3), "r"(b0), "r"(b1));
}

// ---------------- tensor-core GEMM via mma.sync (tf32) ----------------
// MASK 0: none
//      1 (score, z=batch): skip tile if m0>=en || n0>=en
//      2 (message, z=batch): skip tile if m0>=en; truncate K at ceil(en/BKm)
//      3 (row-masked, z=1, batch=m0>>10): skip tile if (m0&1023)>=en
// EPI 0: acc*alpha + bias[n]
//     1: acc*extra[m] + bias[n]
//     2: (acc+bias[n]) * extra[(m>>10)*CTX + n]
//     3: (acc+bias[n]) * extra[m*ldc + n]
//     4 (fused q|k): acc+bias[n]; if n>=CTX multiply extra[(m>>10)*CTX + n-CTX]
// TRANSC: write C transposed per batch: C is [B][CTX][NENT]; batch = m0>>10.
template<int NSRC, int EPI, bool RND, bool ADD, int MASK, bool TRANSC>
__global__ __launch_bounds__(256, 2)
void gemm_mma(const float* __restrict__ A0, const float* __restrict__ A1,
              const float* __restrict__ A2, const float* __restrict__ Bt,
              const float* __restrict__ bias, const float* __restrict__ extra,
              const float* __restrict__ addC, const int* __restrict__ ennum,
              float* __restrict__ C,
              int K, int lda, int ldb, int ldc,
              size_t sA, size_t sB, size_t sC, float alpha)
{
    extern __shared__ float smem[];
    const uint32_t sbase = smem_u32(smem);

    const int tid = threadIdx.x;
    const int z = blockIdx.z;
    const int m0 = blockIdx.y * BMm;
    const int n0 = blockIdx.x * BNm;

    int Keff = K;
    if (MASK == 1 || MASK == 2) {
        const int en = ennum[z];
        if (m0 >= en) return;
        if (MASK == 1 && n0 >= en) return;
        if (MASK == 2) { const int kc = ((en + BKm - 1) / BKm) * BKm; Keff = kc < K ? kc : K; }
    } else if (MASK == 3) {
        const int en = ennum[m0 >> 10];
        if ((m0 & 1023) >= en) return;
    }

    const float* Abase = A0 + (size_t)z * sA;
    const float* Bbase = Bt + (size_t)z * sB;
    float* Cbase = C + (size_t)z * sC;

    const int wid = tid >> 5, lane = tid & 31;
    const int wm = (wid & 3) * 32;
    const int wn = (wid >> 2) * 64;
    const int gr = lane >> 2;
    const int gc = lane & 3;

    const int lr = lane & 7, lg = lane >> 3;
    const int arow  = wm + lr + (lg & 1) * 8;
    const int akoff = (lg >> 1) * 4;
    const int brow  = wn + lr + (lg >> 1) * 8;
    const int bkoff = (lg & 1) * 4;

    const int prow0 = tid >> 3;
    const int pkq   = (tid & 7) * 4;

    float acc[2][8][4] = {};
    const int NCC = Keff / BKm;

    auto loadChunk = [&](int c, int st) {
        const int k0 = c * BKm;
        const float* Ap; int al, ak;
        if (NSRC == 1) { Ap = Abase; al = lda; ak = k0; }
        else {
            const int src = k0 >> 9;
            Ap = (src == 0) ? A0 : ((src == 1) ? A1 : A2);
            al = CTX; ak = k0 & (CTX - 1);
        }
        const uint32_t sa = sbase + (uint32_t)(st * STAGE_F) * 4;
        const uint32_t sb = sa + (uint32_t)TILE_F * 4;
        #pragma unroll
        for (int t = 0; t < 4; ++t) {
            const int row = prow0 + t * 32;
            cp_async16(sa + (uint32_t)(row * SROW + pkq) * 4,
                       Ap + (size_t)(m0 + row) * al + ak + pkq);
            cp_async16(sb + (uint32_t)(row * SROW + pkq) * 4,
                       Bbase + (size_t)(n0 + row) * ldb + k0 + pkq);
        }
        CP_COMMIT();
    };

    auto compute = [&](int st) {
        const uint32_t SAu = sbase + (uint32_t)(st * STAGE_F) * 4;
        const uint32_t SBu = SAu + (uint32_t)TILE_F * 4;
        #pragma unroll
        for (int kk = 0; kk < BKm; kk += 8) {
            uint32_t b[8][2];
            #pragma unroll
            for (int ntp = 0; ntp < 4; ++ntp) {
                const uint32_t addr = SBu +
                    (uint32_t)(((brow + ntp * 16) * SROW) + kk + bkoff) * 4;
                ldsm_x4(addr, b[2*ntp][0], b[2*ntp][1], b[2*ntp+1][0], b[2*ntp+1][1]);
            }
            #pragma unroll
            for (int mt = 0; mt < 2; ++mt) {
                uint32_t a0, a1, a2, a3;
                const uint32_t addr = SAu +
                    (uint32_t)(((arow + mt * 16) * SROW) + kk + akoff) * 4;
                ldsm_x4(addr, a0, a1, a2, a3);
                #pragma unroll
                for (int nt = 0; nt < 8; ++nt)
                    mma_m16n8k8(acc[mt][nt], a0, a1, a2, a3, b[nt][0], b[nt][1]);
            }
        }
    };

    #pragma unroll
    for (int s = 0; s < STAGES - 1; ++s) {
        if (s < NCC) loadChunk(s, s);
        else CP_COMMIT();
    }
    {
        int st = 0;
        for (int c = 0; c < NCC; ++c) {
            CP_WAIT1();
            __syncthreads();
            const int nc = c + STAGES - 1;
            int nst = st + STAGES - 1; if (nst >= STAGES) nst -= STAGES;
            if (nc < NCC) loadChunk(nc, nst);
            else CP_COMMIT();
            compute(st);
            if (++st == STAGES) st = 0;
        }
    }

    if (TRANSC) __syncthreads();

    #pragma unroll
    for (int mt = 0; mt < 2; ++mt) {
        #pragma unroll
        for (int half = 0; half < 2; ++half) {
            const int m = m0 + wm + mt * 16 + gr + half * 8;
            const float rs = (EPI == 1) ? extra[m] : 0.f;
            #pragma unroll
            for (int nt = 0; nt < 8; ++nt) {
                const int n = n0 + wn + nt * 8 + gc * 2;
                float v0 = acc[mt][nt][half * 2 + 0];
                float v1 = acc[mt][nt][half * 2 + 1];
                if (ADD) {
                    const float2 ad = *reinterpret_cast<const float2*>(addC + (size_t)m * ldc + n);
                    v0 += ad.x; v1 += ad.y;
                }
                const float bb0 = bias ? bias[n]     : 0.f;
                const float bb1 = bias ? bias[n + 1] : 0.f;
                if (EPI == 0)      { v0 = v0 * alpha + bb0;  v1 = v1 * alpha + bb1; }
                else if (EPI == 1) { v0 = v0 * rs + bb0;     v1 = v1 * rs + bb1; }
                else if (EPI == 2) {
                    const float* g = extra + (size_t)(m >> 10) * CTX + n;
                    v0 = (v0 + bb0) * g[0];
                    v1 = (v1 + bb1) * g[1];
                } else if (EPI == 3) {
                    const float* g = extra + (size_t)m * ldc + n;
                    v0 = (v0 + bb0) * g[0];
                    v1 = (v1 + bb1) * g[1];
                } else { // EPI == 4: fused q|k
                    v0 += bb0; v1 += bb1;
                    if (n >= CTX) {
                        const float* g = extra + (size_t)(m >> 10) * CTX + (n - CTX);
                        v0 *= g[0];
                        v1 *= g[1];
                    }
                }
                if (RND) { v0 = rna_tf32(v0); v1 = rna_tf32(v1); }
                if (!TRANSC) {
                    *reinterpret_cast<float2*>(Cbase + (size_t)m * ldc + n) = make_float2(v0, v1);
                } else {
                    const int ml = wm + mt * 16 + gr + half * 8;
                    const int nl = wn + nt * 8 + gc * 2;
                    smem[(size_t)nl * TSST + ml] = v0;
                    smem[(size_t)(nl + 1) * TSST + ml] = v1;
                }
            }
        }
    }

    if (TRANSC) {
        __syncthreads();
        float* outT = C + (size_t)(m0 >> 10) * CTX * NENT;
        const int bofs = m0 & 1023;
        #pragma unroll
        for (int r = 0; r < 16; ++r) {
            const int row = wid * 16 + r;
            const float4 val = *reinterpret_cast<const float4*>(&smem[(size_t)row * TSST + lane * 4]);
            *reinterpret_cast<float4*>(outT + (size_t)(n0 + row) * NENT + bofs + lane * 4) = val;
        }
    }
}

// ---- one-time: column mean of src rows [NT, NENT) per batch (4-acc MLP) ----
__global__ __launch_bounds__(512)
void colmean_masked_kernel(const float* __restrict__ src, const int* __restrict__ ennum,
                           float* __restrict__ out)
{
    const int b = blockIdx.x;
    const int en = ennum[b];
    const int NT = ((en + 127) >> 7) << 7;
    if (NT >= NENT) return;
    const int d = threadIdx.x;
    const float* base = src + (size_t)b * NENT * CTX + d;
    float s0 = 0.f, s1 = 0.f, s2 = 0.f, s3 = 0.f;
    for (int m = NT; m < NENT; m += 4) {
        s0 += base[(size_t)(m + 0) * CTX];
        s1 += base[(size_t)(m + 1) * CTX];
        s2 += base[(size_t)(m + 2) * CTX];
        s3 += base[(size_t)(m + 3) * CTX];
    }
    out[b * CTX + d] = ((s0 + s1) + (s2 + s3)) * (1.f / (float)(NENT - NT));
}

// ---- qkbias = [qry_b | key_b] ----
__global__ void concat_bias_kernel(const float* __restrict__ a, const float* __restrict__ b,
                                   float* __restrict__ out)
{
    const int i = blockIdx.x * 512 + threadIdx.x;
    out[i] = (i < CTX) ? a[i] : b[i - CTX];
}

// ---- wide: ppm[b][j] = (xcm[b]@pxc_row_j + pxc_b[j]) * Spl[b][j] ----
__global__ __launch_bounds__(256)
void ppm_kernel(const float* __restrict__ xcm, const float* __restrict__ wPXC,
                const float* __restrict__ pxc_b, const float* __restrict__ Spl,
                const int* __restrict__ ennum, float* __restrict__ ppm)
{
    const int b = blockIdx.y;
    const int en = ennum[b];
    if (((en + 127) >> 7 << 7) >= NENT) return;
    const int jb = blockIdx.x * 32;
    const int tid = threadIdx.x, wid = tid >> 5, lane = tid & 31;
    __shared__ float x[CTX];
    for (int d = tid; d < CTX; d += 256) x[d] = xcm[b * CTX + d];
    __syncthreads();
    #pragma unroll
    for (int jj = 0; jj < 4; ++jj) {
        const int j = jb + wid * 4 + jj;
        const float* w = wPXC + (size_t)j * CTX;
        float acc = 0.f;
        #pragma unroll
        for (int i = 0; i < CTX / 32; ++i)
            acc = fmaf(x[lane + 32 * i], w[lane + 32 * i], acc);
        #pragma unroll
        for (int o = 16; o > 0; o >>= 1) acc += __shfl_down_sync(0xFFFFFFFFu, acc, o);
        if (lane == 0) ppm[b * CTX + j] = (acc + pxc_b[j]) * Spl[b * CTX + j];
    }
}

// ---- wide: vmask[b][d] = ([xcm|ppm]@wVAL_row_d[CTX..3CTX) + val_b + SvL) * pvg ----
__global__ __launch_bounds__(256)
void vmask_wide_kernel(const float* __restrict__ xcm, const float* __restrict__ ppm,
                       const float* __restrict__ wVAL, const float* __restrict__ val_b,
                       const float* __restrict__ pvg, const float* __restrict__ SvL,
                       const int* __restrict__ ennum, float* __restrict__ vmask)
{
    const int b = blockIdx.y;
    const int en = ennum[b];
    if (((en + 127) >> 7 << 7) >= NENT) return;
    const int jb = blockIdx.x * 32;
    const int tid = threadIdx.x, wid = tid >> 5, lane = tid & 31;
    __shared__ float x[2 * CTX];
    for (int d = tid; d < CTX; d += 256) {
        x[d] = xcm[b * CTX + d];
        x[CTX + d] = ppm[b * CTX + d];
    }
    __syncthreads();
    #pragma unroll
    for (int jj = 0; jj < 4; ++jj) {
        const int d = jb + wid * 4 + jj;
        const float* w = wVAL + (size_t)d * (3 * CTX) + CTX;
        float acc = 0.f;
        #pragma unroll
        for (int i = 0; i < (2 * CTX) / 32; ++i)
            acc = fmaf(x[lane + 32 * i], w[lane + 32 * i], acc);
        #pragma unroll
        for (int o = 16; o > 0; o >>= 1) acc += __shfl_down_sync(0xFFFFFFFFu, acc, o);
        if (lane == 0)
            vmask[b * CTX + d] = (acc + val_b[d] + SvL[b * CTX + d]) * pvg[b * CTX + d];
    }
}

// ---- per-batch mean over vT rows: unrolled predicated sum + analytic tail ----
__global__ void mean_vT_kernel(const float* __restrict__ vT, const int* __restrict__ ennum,
                               const float* __restrict__ vmask, float* __restrict__ msgm)
{
    const int b = blockIdx.y;
    const int en = ennum[b];
    if (en >= NENT) return;
    const int NT = ((en + 127) >> 7) << 7;
    const int wid = threadIdx.x >> 5, lane = threadIdx.x & 31;
    const int d = blockIdx.x * 8 + wid;
    const float* row = vT + (size_t)b * CTX * NENT + (size_t)d * NENT;
    float s = 0.f;
    #pragma unroll
    for (int i = 0; i < NENT / 32; ++i) {
        float x = row[lane + 32 * i];
        if (lane + 32 * i >= NT) x = 0.f;
        s += x;
    }
    #pragma unroll
    for (int o = 16; o > 0; o >>= 1) s += __shfl_down_sync(0xFFFFFFFFu, s, o);
    if (lane == 0)
        msgm[b * CTX + d] = rna_tf32((s + (float)(NENT - NT) * vmask[b * CTX + d]) * (1.f / NENT));
}

// ---- masked-row x_ctx compute ----
__global__ __launch_bounds__(256)
void ctx_compute_kernel(const float* __restrict__ msgm, const float* __restrict__ wMU,
                        const float* __restrict__ mu_b, const int* __restrict__ ennum,
                        float* __restrict__ xcm)
{
    const int b = blockIdx.x;
    if (ennum[b] >= NENT) return;
    const int tid = threadIdx.x;
    const int wid = tid >> 5, lane = tid & 31;
    __shared__ float x[2 * CTX];
    __shared__ float y[CTX];
    for (int d = tid; d < CTX; d += 256) {
        x[d] = xcm[b * CTX + d];
        x[CTX + d] = msgm[b * CTX + d];
    }
    __syncthreads();
    for (int j = wid; j < CTX; j += 8) {
        const float* w = wMU + (size_t)j * (2 * CTX);
        float acc = 0.f;
        #pragma unroll
        for (int i = 0; i < (2 * CTX) / 32; ++i)
            acc = fmaf(x[lane + 32 * i], w[lane + 32 * i], acc);
        #pragma unroll
        for (int o = 16; o > 0; o >>= 1)
            acc += __shfl_down_sync(0xFFFFFFFFu, acc, o);
        if (lane == 0) y[j] = rna_tf32(acc + mu_b[j]);
    }
    __syncthreads();
    for (int d = tid; d < CTX; d += 256) xcm[b * CTX + d] = y[d];
}

// ---- broadcast xcm row into xn masked rows ----
__global__ __launch_bounds__(256)
void bcast_rows_kernel(const float* __restrict__ xcm, const int* __restrict__ ennum,
                       float* __restrict__ xn)
{
    const int b = blockIdx.y;
    const int en = ennum[b];
    const int r0 = blockIdx.x * 128;
    int start = r0 > en ? r0 : en;
    const int end = r0 + 128;
    if (start >= end) return;
    __shared__ float y[CTX];
    const int tid = threadIdx.x;
    for (int d = tid; d < CTX; d += 256) y[d] = xcm[b * CTX + d];
    __syncthreads();
    const int c4 = (tid & 127) * 4;
    const float4 val = *reinterpret_cast<const float4*>(&y[c4]);
    float* base = xn + (size_t)b * NENT * CTX;
    for (int m = start + (tid >> 7); m < end; m += 2)
        *reinterpret_cast<float4*>(base + (size_t)m * CTX + c4) = val;
}

// ---- transpose, optional tf32 round ----
template<bool RND>
__global__ void transpose_kernel(const float* __restrict__ in, float* __restrict__ out,
                                 int R, int C, size_t sIn, size_t sOut)
{
    __shared__ float tile[32][33];
    const int z = blockIdx.z;
    in  += (size_t)z * sIn;
    out += (size_t)z * sOut;
    const int r0 = blockIdx.y * 32, c0 = blockIdx.x * 32;
    #pragma unroll
    for (int i = threadIdx.y; i < 32; i += 8) {
        float x = in[(size_t)(r0 + i) * C + c0 + threadIdx.x];
        tile[i][threadIdx.x] = RND ? rna_tf32(x) : x;
    }
    __syncthreads();
    #pragma unroll
    for (int i = threadIdx.y; i < 32; i += 8)
        out[(size_t)(c0 + i) * R + r0 + threadIdx.x] = tile[threadIdx.x][i];
}

// ---- fused row inv-norm + tf32-rounded copy ----
__global__ void rownorm_round_kernel(const float* __restrict__ img, float* __restrict__ invn,
                                     float* __restrict__ imgr)
{
    const int m = blockIdx.x;
    const float4* r4 = reinterpret_cast<const float4*>(img + (size_t)m * DFEAT);
    float4* o4 = reinterpret_cast<float4*>(imgr + (size_t)m * DFEAT);
    const int tid = threadIdx.x;
    float s = 0.f;
    for (int i = tid; i < DFEAT / 4; i += 256) {
        float4 u = r4[i];
        s = fmaf(u.x, u.x, s); s = fmaf(u.y, u.y, s);
        s = fmaf(u.z, u.z, s); s = fmaf(u.w, u.w, s);
        u.x = rna_tf32(u.x); u.y = rna_tf32(u.y);
        u.z = rna_tf32(u.z); u.w = rna_tf32(u.w);
        o4[i] = u;
    }
    __shared__ float red[256];
    red[tid] = s; __syncthreads();
    for (int o = 128; o > 0; o >>= 1) { if (tid < o) red[tid] += red[tid + o]; __syncthreads(); }
    if (tid == 0) invn[m] = 1.f / fmaxf(sqrtf(red[0]), 1e-12f);
}

__global__ void ctx_init_kernel(const float* __restrict__ initMem, float* __restrict__ xctx,
                                float* __restrict__ xcm)
{
    const size_t i = (size_t)blockIdx.x * blockDim.x + threadIdx.x;
    const float val = rna_tf32(initMem[i & (CTX - 1)]);
    xctx[i] = val;
    if (i < BB * CTX) xcm[i] = val;
}

// ---- fast batch-32 linear ----
template<bool ELU>
__global__ void small_linear_fast(const float* __restrict__ in, const float* __restrict__ wT,
                                  const float* __restrict__ bias, float* __restrict__ out)
{
    const int b = blockIdx.y;
    const int jb = blockIdx.x * 32;
    const int tid = threadIdx.x;
    const int wid = tid >> 5, lane = tid & 31;
    __shared__ float x[CMD];
    for (int d = tid; d < CMD; d += 256) x[d] = in[b * CMD + d];
    __syncthreads();
    #pragma unroll
    for (int jj = 0; jj < 4; ++jj) {
        const int j = jb + wid * 4 + jj;
        const float* w = wT + (size_t)j * CMD;
        float acc = 0.f;
        #pragma unroll
        for (int i = 0; i < CMD / 32; ++i)
            acc = fmaf(x[lane + 32 * i], w[lane + 32 * i], acc);
        #pragma unroll
        for (int o = 16; o > 0; o >>= 1)
            acc += __shfl_down_sync(0xFFFFFFFFu, acc, o);
        if (lane == 0) {
            acc += bias[j];
            if (ELU) acc = (acc > 0.f) ? acc : expm1f(acc);
            out[b * CMD + j] = acc;
        }
    }
}

// ---- fast textual command ----
__global__ __launch_bounds__(1024)
void text_cmd_fast(const float* __restrict__ qcmd, const float* __restrict__ lstm,
                   const float* __restrict__ c2l_w, const float* __restrict__ c2l_b,
                   const int* __restrict__ qlen, float* __restrict__ cmd)
{
    const int b = blockIdx.x;
    const int tid = threadIdx.x;
    const int wid = tid >> 5, lane = tid & 31;
    __shared__ float e[CMD];
    __shared__ float att[LQL];
    __shared__ float red[128];
    __shared__ float smx, ssum;

    if (tid < CMD) e[tid] = qcmd[b * CMD + tid] * c2l_w[tid];
    __syncthreads();

    const int en = qlen[b];
    #pragma unroll
    for (int li = 0; li < 4; ++li) {
        const int l = wid + li * 32;
        const float* L = lstm + ((size_t)b * LQL + l) * CMD;
        float acc = 0.f;
        #pragma unroll
        for (int i = 0; i < CMD / 32; ++i)
            acc = fmaf(L[lane + 32 * i], e[lane + 32 * i], acc);
        #pragma unroll
        for (int o = 16; o > 0; o >>= 1)
            acc += __shfl_down_sync(0xFFFFFFFFu, acc, o);
        if (lane == 0) att[l] = (l >= en) ? NEGV : (acc + c2l_b[0]);
    }
    __syncthreads();

    if (tid < 128) red[tid] = att[tid];
    __syncthreads();
    for (int o = 64; o > 0; o >>= 1) {
        if (tid < o) red[tid] = fmaxf(red[tid], red[tid + o]);
        __syncthreads();
    }
    if (tid == 0) smx = red[0];
    __syncthreads();
    float ev = 0.f;
    if (tid < 128) { ev = expf(att[tid] - smx); red[tid] = ev; }
    __syncthreads();
    for (int o = 64; o > 0; o >>= 1) {
        if (tid < o) red[tid] += red[tid + o];
        __syncthreads();
    }
    if (tid == 0) ssum = red[0];
    __syncthreads();
    if (tid < 128) att[tid] = ev / ssum;
    __syncthreads();

    if (tid < CMD) {
        float acc = 0.f;
        const float* L = lstm + (size_t)b * LQL * CMD + tid;
        #pragma unroll 4
        for (int l = 0; l < LQL; ++l)
            acc = fmaf(att[l], L[(size_t)l * CMD], acc);
        cmd[b * CMD + tid] = acc;
    }
}

// masked row softmax (in place)
__global__ void attn_softmax_kernel(float* __restrict__ score, const int* __restrict__ entity_num)
{
    const int row = blockIdx.x;
    const int b = row >> 10;
    const int n = row & 1023;
    const int en = entity_num[b];
    if (n >= en) return;
    float* s = score + (size_t)row * NENT;
    const int tid = threadIdx.x;

    const int kc = ((en + 15) / 16) * 16;
    const int nblk = (kc + 255) >> 8;

    float v[4];
    float mx = -3.4e38f;
    #pragma unroll
    for (int j = 0; j < 4; j++) {
        const int m = tid + j * 256;
        float x = NEGV;
        if (j < nblk && m < en) x = s[m];
        v[j] = x;
        mx = fmaxf(mx, x);
    }
    __shared__ float red[256];
    red[tid] = mx; __syncthreads();
    for (int o = 128; o > 0; o >>= 1) { if (tid < o) red[tid] = fmaxf(red[tid], red[tid + o]); __syncthreads(); }
    mx = red[0];
    __syncthreads();

    float sum = 0.f;
    #pragma unroll
    for (int j = 0; j < 4; j++) { v[j] = expf(v[j] - mx); sum += v[j]; }
    red[tid] = sum; __syncthreads();
    for (int o = 128; o > 0; o >>= 1) { if (tid < o) red[tid] += red[tid + o]; __syncthreads(); }
    const float inv = 1.f / red[0];

    #pragma unroll
    for (int j = 0; j < 4; j++)
        if (j < nblk) s[tid + j * 256] = rna_tf32(v[j] * inv);
}

// ---------------- launch ----------------
template<typename T> static float* symaddr(T& sym) {
    void* p = nullptr;
    cudaGetSymbolAddress(&p, sym);
    return (float*)p;
}

extern "C" void kernel_launch(void* const* d_in, const int* in_sizes, int n_in,
                              void* d_out, int out_size)
{
    const float* images    = (const float*)d_in[0];
    const float* q_enc     = (const float*)d_in[1];
    const float* lstm      = (const float*)d_in[2];
    const int*   q_length  = (const int*)  d_in[3];
    const int*   ent_num   = (const int*)  d_in[4];
    const float* initKB_w  = (const float*)d_in[5];
    const float* initKB_b  = (const float*)d_in[6];
    const float* initMem   = (const float*)d_in[7];
    const float* qInput_w  = (const float*)d_in[8];
    const float* qInput_b  = (const float*)d_in[9];
    const float* qInput2_w = (const float*)d_in[10];
    const float* qInput2_b = (const float*)d_in[11];
    const float* c2l_w     = (const float*)d_in[12];
    const float* c2l_b     = (const float*)d_in[13];
    const float* pxl_w     = (const float*)d_in[14];
    const float* pxl_b     = (const float*)d_in[15];
    const float* pxc_w     = (const float*)d_in[16];
    const float* pxc_b     = (const float*)d_in[17];
    const float* qry_w     = (const float*)d_in[18];
    const float* qry_b     = (const float*)d_in[19];
    const float* key_w     = (const float*)d_in[20];
    const float* key_b     = (const float*)d_in[21];
    const float* val_w     = (const float*)d_in[22];
    const float* val_b     = (const float*)d_in[23];
    const float* pk_w      = (const float*)d_in[24];
    const float* pk_b      = (const float*)d_in[25];
    const float* pv_w      = (const float*)d_in[26];
    const float* pv_b      = (const float*)d_in[27];
    const float* mu_w      = (const float*)d_in[28];
    const float* mu_b      = (const float*)d_in[29];
    const float* ck_w      = (const float*)d_in[30];
    const float* ck_b      = (const float*)d_in[31];

    float* imgr  = symaddr(g_imgr);
    float* invn  = symaddr(g_invnorm);
    float* xloc  = symaddr(g_xloc);
    float* xctxA = symaddr(g_xctx0);
    float* xctxB = symaddr(g_xctx1);
    float* prjl  = symaddr(g_projloc);
    float* pp    = symaddr(g_pp);
    float* qk    = symaddr(g_qk);
    float* qkL   = symaddr(g_qkL);
    float* ckL   = symaddr(g_ckL);
    float* vT    = symaddr(g_vT);
    float* msg   = symaddr(g_msg);
    float* vL    = symaddr(g_vL);
    float* score = symaddr(g_score);
    float* qbase = symaddr(g_qbase);
    float* qcmd  = symaddr(g_qcmd);
    float* cmd   = symaddr(g_cmd);
    float* pkg   = symaddr(g_pkg);
    float* pvg   = symaddr(g_pvg);
    float* msgm  = symaddr(g_msgm);
    float* xcm   = symaddr(g_xcm);
    float* SvL   = symaddr(g_SvL);
    float* Spl   = symaddr(g_Spl);
    float* ppm   = symaddr(g_ppm);
    float* vmask = symaddr(g_vmask);
    float* qkb   = symaddr(g_qkbias);
    float* wIKB  = symaddr(g_wT_ikb);
    float* wPXL  = symaddr(g_wT_pxl);
    float* wPXC  = symaddr(g_wT_pxc);
    float* wQK   = symaddr(g_wT_qk);
    float* wQKl  = symaddr(g_wT_qkl);
    float* wVAL  = symaddr(g_wT_val);
    float* wMU   = symaddr(g_wT_mu);
    float* wCK   = symaddr(g_wT_ck);
    float* wQIN  = symaddr(g_wT_qin);
    float* wQIN2 = symaddr(g_wT_qin2);
    float* wPK   = symaddr(g_wT_pk);
    float* wPV   = symaddr(g_wT_pv);

    cudaFuncSetAttribute(gemm_mma<1,0,false,false,0,false>, cudaFuncAttributeMaxDynamicSharedMemorySize, SMEM_DYN);
    cudaFuncSetAttribute(gemm_mma<1,0,false,true ,0,false>, cudaFuncAttributeMaxDynamicSharedMemorySize, SMEM_DYN);
    cudaFuncSetAttribute(gemm_mma<1,0,false,false,3,false>, cudaFuncAttributeMaxDynamicSharedMemorySize, SMEM_DYN);
    cudaFuncSetAttribute(gemm_mma<1,1,true ,false,0,false>, cudaFuncAttributeMaxDynamicSharedMemorySize, SMEM_DYN);
    cudaFuncSetAttribute(gemm_mma<1,3,true ,false,3,false>, cudaFuncAttributeMaxDynamicSharedMemorySize, SMEM_DYN);
    cudaFuncSetAttribute(gemm_mma<1,0,false,false,1,false>, cudaFuncAttributeMaxDynamicSharedMemorySize, SMEM_DYN);
    cudaFuncSetAttribute(gemm_mma<1,0,true ,false,2,false>, cudaFuncAttributeMaxDynamicSharedMemorySize, SMEM_DYN);
    cudaFuncSetAttribute(gemm_mma<2,4,true ,true ,3,false>, cudaFuncAttributeMaxDynamicSharedMemorySize, SMEM_DYN);
    cudaFuncSetAttribute(gemm_mma<2,2,true ,true ,3,true >, cudaFuncAttributeMaxDynamicSharedMemorySize, SMEM_DYN);
    cudaFuncSetAttribute(gemm_mma<2,0,true ,false,3,false>, cudaFuncAttributeMaxDynamicSharedMemorySize, SMEM_DYN);

    // ---- one-time side stream + events ----
    static bool s_init = false;
    static cudaStream_t s1;
    static cudaEvent_t evStart, evW, evCmd, ev0, evPP, evV, evCtx;
    if (!s_init) {
        cudaStreamCreateWithFlags(&s1, cudaStreamNonBlocking);
        cudaEventCreateWithFlags(&evStart, cudaEventDisableTiming);
        cudaEventCreateWithFlags(&evW,     cudaEventDisableTiming);
        cudaEventCreateWithFlags(&evCmd,   cudaEventDisableTiming);
        cudaEventCreateWithFlags(&ev0,     cudaEventDisableTiming);
        cudaEventCreateWithFlags(&evPP,    cudaEventDisableTiming);
        cudaEventCreateWithFlags(&evV,     cudaEventDisableTiming);
        cudaEventCreateWithFlags(&evCtx,   cudaEventDisableTiming);
        s_init = true;
    }

    const float scale = 0.044194173824159216f;   // 1/sqrt(512)
    const dim3 tdim(32, 8);
    const dim3 gridMain(CTX / BNm, MROWS / BMm, 1);      // (4,256)
    const dim3 gridQK(2 * CTX / BNm, MROWS / BMm, 1);    // (8,256)
    const dim3 gridScore(NENT / BNm, NENT / BMm, BB);
    const dim3 gridMsg(CTX / BNm, NENT / BMm, BB);
    const dim3 gridSL(CMD / 32, BB);

    // ---- fork: s1 does tf32 weight transposes (evW), then cmd chains ----
    cudaEventRecord(evStart, 0);
    cudaStreamWaitEvent(s1, evStart, 0);
    transpose_kernel<true><<<dim3(CTX/32, CTX/32, 1),   tdim, 0, s1>>>(pxl_w, wPXL, CTX,   CTX, 0, 0);
    transpose_kernel<true><<<dim3(CTX/32, CTX/32, 1),   tdim, 0, s1>>>(pxc_w, wPXC, CTX,   CTX, 0, 0);
    // wQKl: K-rows 0..511 of qry/key -> [n(q|k)][k]
    transpose_kernel<true><<<dim3(CTX/32, CTX/32, 1),   tdim, 0, s1>>>(qry_w, wQKl, CTX, CTX, 0, 0);
    transpose_kernel<true><<<dim3(CTX/32, CTX/32, 1),   tdim, 0, s1>>>(key_w, wQKl + (size_t)CTX*CTX, CTX, CTX, 0, 0);
    // wQK: K-rows 512..1535 of qry/key -> [n(q|k)][k 0..1023]
    transpose_kernel<true><<<dim3(CTX/32, 2*CTX/32, 1), tdim, 0, s1>>>(qry_w + (size_t)CTX*CTX, wQK, 2*CTX, CTX, 0, 0);
    transpose_kernel<true><<<dim3(CTX/32, 2*CTX/32, 1), tdim, 0, s1>>>(key_w + (size_t)CTX*CTX, wQK + (size_t)CTX*2*CTX, 2*CTX, CTX, 0, 0);
    transpose_kernel<true><<<dim3(CTX/32, 3*CTX/32, 1), tdim, 0, s1>>>(val_w, wVAL, 3*CTX, CTX, 0, 0);
    transpose_kernel<true><<<dim3(CTX/32, 2*CTX/32, 1), tdim, 0, s1>>>(mu_w,  wMU,  2*CTX, CTX, 0, 0);
    transpose_kernel<true><<<dim3(CTX/32, 2*CTX/32, 1), tdim, 0, s1>>>(ck_w,  wCK,  2*CTX, CTX, 0, 0);
    concat_bias_kernel<<<2, 512, 0, s1>>>(qry_b, key_b, qkb);
    cudaEventRecord(evW, s1);
    // cmd chains for all iterations (inputs are constants)
    transpose_kernel<false><<<dim3(CMD/32, CMD/32, 1), tdim, 0, s1>>>(qInput_w, wQIN, CMD, CMD, 0, 0);
    small_linear_fast<true><<<gridSL, 256, 0, s1>>>(q_enc, wQIN, qInput_b, qbase);
    transpose_kernel<false><<<dim3(CMD/32, CMD/32, TT), tdim, 0, s1>>>(qInput2_w, wQIN2, CMD, CMD,
                                                                       (size_t)CMD*CMD, (size_t)CMD*CMD);
    transpose_kernel<false><<<dim3(CTX/32, CMD/32, 1), tdim, 0, s1>>>(pk_w, wPK, CMD, CTX, 0, 0);
    transpose_kernel<false><<<dim3(CTX/32, CMD/32, 1), tdim, 0, s1>>>(pv_w, wPV, CMD, CTX, 0, 0);
    for (int t = 0; t < TT; t++) {
        small_linear_fast<false><<<gridSL, 256, 0, s1>>>(qbase, wQIN2 + (size_t)t * CMD * CMD,
                                                         qInput2_b + (size_t)t * CMD, qcmd);
        text_cmd_fast<<<BB, 1024, 0, s1>>>(qcmd, lstm, c2l_w, c2l_b, q_length, cmd);
        small_linear_fast<false><<<gridSL, 256, 0, s1>>>(cmd, wPK, pk_b, pkg + (size_t)t * BB * CTX);
        small_linear_fast<false><<<gridSL, 256, 0, s1>>>(cmd, wPV, pv_b, pvg + (size_t)t * BB * CTX);
    }
    cudaEventRecord(evCmd, s1);

    // ---- main: big one-time work overlapping s1 ----
    transpose_kernel<true><<<dim3(CTX/32, DFEAT/32, 1), tdim>>>(initKB_w, wIKB, DFEAT, CTX, 0, 0);
    rownorm_round_kernel<<<MROWS, 256>>>(images, invn, imgr);
    ctx_init_kernel<<<(MROWS * CTX) / 256, 256>>>(initMem, xctxA, xcm);
    gemm_mma<1,1,true,false,0,false><<<gridMain, 256, SMEM_DYN>>>(
        imgr, nullptr, nullptr, wIKB, initKB_b, invn, nullptr, nullptr, xloc,
        DFEAT, DFEAT, DFEAT, CTX, 0, 0, 0, 1.f);
    cudaStreamWaitEvent(0, evW, 0);

    // ---- iteration-invariant hoists (main) ----
    gemm_mma<1,0,false,false,0,false><<<gridMain, 256, SMEM_DYN>>>(
        xloc, nullptr, nullptr, wPXL, pxl_b, nullptr, nullptr, nullptr, prjl,
        CTX, CTX, CTX, CTX, 0, 0, 0, 1.f);
    // qkL = xloc @ [wq|wk][:, :512]  (live rows only), written [M,1024]
    gemm_mma<1,0,false,false,3,false><<<gridQK, 256, SMEM_DYN>>>(
        xloc, nullptr, nullptr, wQKl, nullptr, nullptr, nullptr, ent_num, qkL,
        CTX, CTX, CTX, 2*CTX, 0, 0, 0, 1.f);
    gemm_mma<1,0,false,false,0,false><<<gridMain, 256, SMEM_DYN>>>(
        xloc, nullptr, nullptr, wVAL, nullptr, nullptr, nullptr, nullptr, vL,
        CTX, CTX, 3*CTX, CTX, 0, 0, 0, 1.f);
    colmean_masked_kernel<<<BB, 512>>>(vL,   ent_num, SvL);
    colmean_masked_kernel<<<BB, 512>>>(prjl, ent_num, Spl);
    cudaEventRecord(ev0, 0);
    cudaStreamWaitEvent(s1, ev0, 0);      // s1 per-iter chain needs Spl/SvL (+ xloc,wCK below)
    cudaStreamWaitEvent(0, evCmd, 0);     // main qk needs pkg

    // ---- s1: hoist ckL = xloc @ wCK[:, :512] (runs under iter-0 main work) ----
    gemm_mma<1,0,false,false,0,false><<<gridMain, 256, SMEM_DYN, s1>>>(
        xloc, nullptr, nullptr, wCK, nullptr, nullptr, nullptr, nullptr, ckL,
        CTX, CTX, 2*CTX, CTX, 0, 0, 0, 1.f);

    float* xc = xctxA;
    float* xn = xctxB;
    for (int t = 0; t < TT; t++) {
        const float* pkg_t = pkg + (size_t)t * BB * CTX;
        const float* pvg_t = pvg + (size_t)t * BB * CTX;

        // ---- s1: analytic masked-v prep (reads xcm from prev ctx_compute) ----
        ppm_kernel<<<dim3(CTX/32, BB), 256, 0, s1>>>(xcm, wPXC, pxc_b, Spl, ent_num, ppm);
        vmask_wide_kernel<<<dim3(CTX/32, BB), 256, 0, s1>>>(xcm, ppm, wVAL, val_b, pvg_t,
                                                            SvL, ent_num, vmask);

        // ---- main: pp (record evPP), then fused q|k ----
        gemm_mma<1,3,true,false,3,false><<<gridMain, 256, SMEM_DYN>>>(
            xc, nullptr, nullptr, wPXC, pxc_b, prjl, nullptr, ent_num, pp,
            CTX, CTX, CTX, CTX, 0, 0, 0, 1.f);
        cudaEventRecord(evPP, 0);
        gemm_mma<2,4,true,true,3,false><<<gridQK, 256, SMEM_DYN>>>(
            xc, pp, nullptr, wQK, qkb, pkg_t, qkL, ent_num, qk,
            2*CTX, 0, 2*CTX, 2*CTX, 0, 0, 0, 1.f);

        // ---- s1: v GEMM (after pp) + mean chain, overlapping score/softmax ----
        cudaStreamWaitEvent(s1, evPP, 0);
        gemm_mma<2,2,true,true,3,true><<<gridMain, 256, SMEM_DYN, s1>>>(
            xc, pp, nullptr, wVAL + CTX, val_b, pvg_t, vL, ent_num, vT,
            2*CTX, 0, 3*CTX, CTX, 0, 0, 0, 1.f);
        cudaEventRecord(evV, s1);
        mean_vT_kernel<<<dim3(CTX / 8, BB), 256, 0, s1>>>(vT, ent_num, vmask, msgm);
        ctx_compute_kernel<<<BB, 256, 0, s1>>>(msgm, wMU, mu_b, ent_num, xcm);
        cudaEventRecord(evCtx, s1);

        // ---- main: attention; msg gated on v; mu; gated bcast ----
        gemm_mma<1,0,false,false,1,false><<<gridScore, 256, SMEM_DYN>>>(
            qk, nullptr, nullptr, qk + CTX, nullptr, nullptr, nullptr, ent_num, score,
            CTX, 2*CTX, 2*CTX, NENT,
            (size_t)NENT * 2*CTX, (size_t)NENT * 2*CTX, (size_t)NENT * NENT, scale);
        attn_softmax_kernel<<<MROWS, 256>>>(score, ent_num);
        cudaStreamWaitEvent(0, evV, 0);
        gemm_mma<1,0,true,false,2,false><<<gridMsg, 256, SMEM_DYN>>>(
            score, nullptr, nullptr, vT, nullptr, nullptr, nullptr, ent_num, msg,
            NENT, NENT, NENT, CTX,
            (size_t)NENT * NENT, (size_t)CTX * NENT, (size_t)NENT * CTX, 1.f);
        gemm_mma<2,0,true,false,3,false><<<gridMain, 256, SMEM_DYN>>>(
            xc, msg, nullptr, wMU, mu_b, nullptr, nullptr, ent_num, xn,
            2*CTX, 0, 2*CTX, CTX, 0, 0, 0, 1.f);
        cudaStreamWaitEvent(0, evCtx, 0);
        bcast_rows_kernel<<<dim3(NENT / 128, BB), 256>>>(xcm, ent_num, xn);

        float* tmp = xc; xc = xn; xn = tmp;
    }

    // out = xc @ wCK[:, 512:] + ckL + b   (xloc half hoisted; s1 joined via evCtx)
    gemm_mma<1,0,false,true,0,false><<<gridMain, 256, SMEM_DYN>>>(
        xc, nullptr, nullptr, wCK + CTX, ck_b, nullptr, ckL, nullptr, (float*)d_out,
        CTX, CTX, 2*CTX, CTX, 0, 0, 0, 1.f);
}